// round 7
// baseline (speedup 1.0000x reference)
#include <cuda_runtime.h>
#include <cstdint>

// ---------------------------------------------------------------------------
// NeuralSDEHead: batch=8, d_model=512, hidden=64, n_paths=4096, horizon=128
// out = [paths (8*4096*128), mu (8), sigma (8)]  all fp32
// PRNG: JAX threefry2x32, jax_threefry_partitionable=True semantics.
// ---------------------------------------------------------------------------

#define BATCH    8
#define DMODEL   512
#define HIDDEN   64
#define NPATHS   4096
#define HORIZON  128
#define BN       (BATCH * NPATHS)      /* 32768 */
#define PATHS_ELEMS (BN * HORIZON)     /* 4194304 */

typedef unsigned long long ull;

// Scratch (allocation-free rule: __device__ globals)
__device__ float        g_base_f1[BATCH * HIDDEN];
__device__ float        g_base_g1[BATCH * HIDDEN];
__device__ unsigned int g_keys[2 * HORIZON];

// ---------------------------------------------------------------------------
// Threefry-2x32 (JAX-compatible, 20 rounds)
// ---------------------------------------------------------------------------
__device__ __forceinline__ void threefry2x32(unsigned int k0, unsigned int k1,
                                             unsigned int x0, unsigned int x1,
                                             unsigned int* o0, unsigned int* o1)
{
    unsigned int ks0 = k0, ks1 = k1, ks2 = k0 ^ k1 ^ 0x1BD11BDAu;
    x0 += ks0; x1 += ks1;
#define TF_ROUND(r) { x0 += x1; x1 = __funnelshift_l(x1, x1, (r)); x1 ^= x0; }
    TF_ROUND(13) TF_ROUND(15) TF_ROUND(26) TF_ROUND(6)
    x0 += ks1; x1 += ks2 + 1u;
    TF_ROUND(17) TF_ROUND(29) TF_ROUND(16) TF_ROUND(24)
    x0 += ks2; x1 += ks0 + 2u;
    TF_ROUND(13) TF_ROUND(15) TF_ROUND(26) TF_ROUND(6)
    x0 += ks0; x1 += ks1 + 3u;
    TF_ROUND(17) TF_ROUND(29) TF_ROUND(16) TF_ROUND(24)
    x0 += ks1; x1 += ks2 + 4u;
    TF_ROUND(13) TF_ROUND(15) TF_ROUND(26) TF_ROUND(6)
    x0 += ks2; x1 += ks0 + 5u;
#undef TF_ROUND
    *o0 = x0; *o1 = x1;
}

// XLA ErfInv32 (Giles polynomial)
__device__ __forceinline__ float erfinv_xla(float x)
{
    float w = -log1pf(-x * x);
    float p;
    if (w < 5.0f) {
        w = w - 2.5f;
        p = 2.81022636e-08f;
        p = fmaf(p, w, 3.43273939e-07f);
        p = fmaf(p, w, -3.5233877e-06f);
        p = fmaf(p, w, -4.39150654e-06f);
        p = fmaf(p, w, 0.00021858087f);
        p = fmaf(p, w, -0.00125372503f);
        p = fmaf(p, w, -0.00417768164f);
        p = fmaf(p, w, 0.246640727f);
        p = fmaf(p, w, 1.50140941f);
    } else {
        w = sqrtf(w) - 3.0f;
        p = -0.000200214257f;
        p = fmaf(p, w, 0.000100950558f);
        p = fmaf(p, w, 0.00134934322f);
        p = fmaf(p, w, -0.00367342844f);
        p = fmaf(p, w, 0.00573950773f);
        p = fmaf(p, w, -0.0076224613f);
        p = fmaf(p, w, 0.00943887047f);
        p = fmaf(p, w, 1.00167406f);
        p = fmaf(p, w, 2.83297682f);
    }
    return p * x;
}

__device__ __forceinline__ float silu_f(float x)
{
    return __fdividef(x, 1.0f + __expf(-x));
}

__device__ __forceinline__ float softplus_acc(float x)
{
    return fmaxf(x, 0.0f) + log1pf(__expf(-fabsf(x)));
}

// packed f32x2 helpers -------------------------------------------------------
__device__ __forceinline__ ull pack_dup(float x)
{
    unsigned int b = __float_as_uint(x);
    ull r;
    asm("mov.b64 %0, {%1, %2};" : "=l"(r) : "r"(b), "r"(b));
    return r;
}
__device__ __forceinline__ ull pack2(float lo, float hi)
{
    unsigned int a = __float_as_uint(lo), b = __float_as_uint(hi);
    ull r;
    asm("mov.b64 %0, {%1, %2};" : "=l"(r) : "r"(a), "r"(b));
    return r;
}
__device__ __forceinline__ float2 unpack2(ull v)
{
    unsigned int lo, hi;
    asm("mov.b64 {%0, %1}, %2;" : "=r"(lo), "=r"(hi) : "l"(v));
    return make_float2(__uint_as_float(lo), __uint_as_float(hi));
}
#define FMA2(acc, a, b) asm("fma.rn.f32x2 %0, %1, %2, %0;" : "+l"(acc) : "l"(a), "l"(b))

// ---------------------------------------------------------------------------
// Setup kernel 1: partitionable (fold-like) split:
//   key[j] = threefry2x32(key=(0,42), counts=(hi=0, lo=j))  ->  (o0, o1)
// ---------------------------------------------------------------------------
__global__ void keys_kernel()
{
    unsigned int j = threadIdx.x;   // 0..127
    unsigned int o0, o1;
    threefry2x32(0u, 42u, 0u, j, &o0, &o1);
    g_keys[2 * j]     = o0;
    g_keys[2 * j + 1] = o1;
}

// ---------------------------------------------------------------------------
// Setup kernel 2 (grid=8, block=160): per-batch bases + mu/sigma
// ---------------------------------------------------------------------------
__global__ void precompute_kernel(const float* __restrict__ h_t,
                                  const float* __restrict__ W_f1, const float* __restrict__ b_f1,
                                  const float* __restrict__ W_g1, const float* __restrict__ b_g1,
                                  const float* __restrict__ W_mu, const float* __restrict__ b_mu,
                                  const float* __restrict__ W_sig, const float* __restrict__ b_sig,
                                  float* __restrict__ out_mu, float* __restrict__ out_sigma)
{
    int b = blockIdx.x;
    int tid = threadIdx.x;
    const float* h = h_t + b * DMODEL;
    if (tid < HIDDEN) {
        float s = b_f1[tid];
        for (int i = 0; i < DMODEL; ++i)
            s = fmaf(h[i], W_f1[i * HIDDEN + tid], s);
        g_base_f1[b * HIDDEN + tid] = s;
    } else if (tid < 2 * HIDDEN) {
        int j = tid - HIDDEN;
        float s = b_g1[j];
        for (int i = 0; i < DMODEL; ++i)
            s = fmaf(h[i], W_g1[i * HIDDEN + j], s);
        g_base_g1[b * HIDDEN + j] = s;
    } else if (tid == 2 * HIDDEN) {
        float s = b_mu[0];
        for (int i = 0; i < DMODEL; ++i) s = fmaf(h[i], W_mu[i], s);
        out_mu[b] = s;
    } else if (tid == 2 * HIDDEN + 1) {
        float s = b_sig[0];
        for (int i = 0; i < DMODEL; ++i) s = fmaf(h[i], W_sig[i], s);
        out_sigma[b] = fmaxf(s, 0.0f) + log1pf(expf(-fabsf(s))) + 1e-6f;
    }
}

// ---------------------------------------------------------------------------
// Main kernel: 256 blocks x 128 threads (occ 2 -> 8 warps/SM on most SMs).
// One thread per (batch,path) row, 128 sequential Euler steps.
// ---------------------------------------------------------------------------
__global__ __launch_bounds__(128)
void sde_main_kernel(const float* __restrict__ W_f1,
                     const float* __restrict__ W_f2, const float* __restrict__ b_f2,
                     const float* __restrict__ W_f3, const float* __restrict__ b_f3,
                     const float* __restrict__ W_g1,
                     const float* __restrict__ W_g2, const float* __restrict__ b_g2,
                     const float* __restrict__ initial_price,
                     float* __restrict__ out_paths)
{
    __shared__ __align__(16) float sWf2[HIDDEN * HIDDEN];   // 16 KB
    __shared__ __align__(16) float sbf2[HIDDEN];
    __shared__ __align__(16) float4 sF[HIDDEN];   // {base_f1, wy_f1, wt_f1, wg2}
    __shared__ __align__(16) float4 sG[HIDDEN];   // {base_g1, wy_g1, wt_g1, 0}
    __shared__ float sWf3[HIDDEN];
    __shared__ unsigned int skeys[2 * HORIZON];

    const int tid = threadIdx.x;                  // 0..127
    const int row = blockIdx.x * 128 + tid;       // 0..32767
    const int b   = row >> 12;                    // uniform per block (128 | 4096)

    for (int i = tid; i < HIDDEN * HIDDEN; i += 128) sWf2[i] = W_f2[i];
    for (int i = tid; i < 2 * HORIZON; i += 128)     skeys[i] = g_keys[i];

    if (tid < HIDDEN) {
        sbf2[tid] = b_f2[tid];
        sWf3[tid] = W_f3[tid];
        sF[tid] = make_float4(g_base_f1[b * HIDDEN + tid],
                              W_f1[512 * HIDDEN + tid],
                              W_f1[513 * HIDDEN + tid],
                              W_g2[tid]);
    } else {
        int j = tid - HIDDEN;                     // 0..63
        sG[j] = make_float4(g_base_g1[b * HIDDEN + j],
                            W_g1[512 * HIDDEN + j],
                            W_g1[513 * HIDDEN + j],
                            0.0f);
    }
    __syncthreads();

    const float bf3v = b_f3[0];
    const float bg2v = b_g2[0];

    float y = logf(initial_price[b]);

    const unsigned int cnt_lo = (unsigned int)row;   // iota_2x32: hi=0, lo=flat index
    // out base: row*HORIZON floats = row*512 bytes -> 16B-aligned for float4
    float4* outp4 = reinterpret_cast<float4*>(out_paths + (size_t)row * HORIZON);
    float obuf[4];

    #pragma unroll 1
    for (int step = 0; step < HORIZON; ++step) {
        const float t = (float)step;

        // ---- noise: partitionable random_bits = o0 ^ o1, counts=(0,row) ----
        unsigned int o0, o1;
        threefry2x32(skeys[2 * step], skeys[2 * step + 1], 0u, cnt_lo, &o0, &o1);
        const unsigned int bits = o0 ^ o1;
        const float u01 = __uint_as_float((bits >> 9) | 0x3f800000u) - 1.0f;
        float u = fmaf(u01, 2.0f, -0.99999994039535522f);
        u = fmaxf(-0.99999994039535522f, u);
        const float z = 1.4142135381698608f * erfinv_xla(u);

        // ---- fused: h1 on the fly + h2_pre accumulation + g-branch dot ----
        ull acc[HIDDEN / 2];
        #pragma unroll
        for (int m = 0; m < HIDDEN / 2; ++m) {
            acc[m] = pack2(sbf2[2 * m], sbf2[2 * m + 1]);
        }
        float ga0 = bg2v, ga1 = 0.0f, ga2 = 0.0f, ga3 = 0.0f;

        #pragma unroll 4
        for (int i = 0; i < HIDDEN; ++i) {
            const float4 pf = sF[i];              // one LDS.128 (broadcast)
            const float4 pg = sG[i];              // one LDS.128 (broadcast)
            // f-branch pre-activation + silu
            const float xf = fmaf(y, pf.y, fmaf(t, pf.z, pf.x));
            const float hf = silu_f(xf);
            // g-branch pre-activation + silu + dot (4 partial chains)
            const float xg = fmaf(y, pg.y, fmaf(t, pg.z, pg.x));
            const float hg = silu_f(xg);
            if      ((i & 3) == 0) ga0 = fmaf(hg, pf.w, ga0);
            else if ((i & 3) == 1) ga1 = fmaf(hg, pf.w, ga1);
            else if ((i & 3) == 2) ga2 = fmaf(hg, pf.w, ga2);
            else                   ga3 = fmaf(hg, pf.w, ga3);

            // f-branch matvec row i (packed f32x2, shared-broadcast weights)
            const ull a2 = pack_dup(hf);
            const ulonglong2* wr = reinterpret_cast<const ulonglong2*>(&sWf2[i * HIDDEN]);
            #pragma unroll
            for (int q = 0; q < HIDDEN / 4; ++q) {
                ulonglong2 w = wr[q];
                FMA2(acc[2 * q],     a2, w.x);
                FMA2(acc[2 * q + 1], a2, w.y);
            }
        }

        // ---- f = silu(h2_pre) @ W_f3 + b_f3 (2 partial chains) ----
        float f0 = bf3v, f1 = 0.0f;
        #pragma unroll
        for (int m = 0; m < HIDDEN / 2; ++m) {
            float2 h2 = unpack2(acc[m]);
            f0 = fmaf(silu_f(h2.x), sWf3[2 * m],     f0);
            f1 = fmaf(silu_f(h2.y), sWf3[2 * m + 1], f1);
        }
        const float f = f0 + f1;

        const float ga = (ga0 + ga1) + (ga2 + ga3);
        const float g = softplus_acc(ga) + 1e-6f;

        // ---- Euler-Maruyama (dt = 1, sqrt_dt = 1) ----
        y = (y + f) + g * z;

        const float yc = fminf(fmaxf(y, -20.0f), 20.0f);
        obuf[step & 3] = __expf(yc);
        if ((step & 3) == 3)
            outp4[step >> 2] = make_float4(obuf[0], obuf[1], obuf[2], obuf[3]);
    }
}

// ---------------------------------------------------------------------------
// Launch (graph-capturable: kernels only, no allocs/syncs)
// ---------------------------------------------------------------------------
extern "C" void kernel_launch(void* const* d_in, const int* in_sizes, int n_in,
                              void* d_out, int out_size)
{
    const float* h_t    = (const float*)d_in[0];
    const float* price  = (const float*)d_in[1];
    const float* W_f1   = (const float*)d_in[2];
    const float* b_f1   = (const float*)d_in[3];
    const float* W_f2   = (const float*)d_in[4];
    const float* b_f2   = (const float*)d_in[5];
    const float* W_f3   = (const float*)d_in[6];
    const float* b_f3   = (const float*)d_in[7];
    const float* W_g1   = (const float*)d_in[8];
    const float* b_g1   = (const float*)d_in[9];
    const float* W_g2   = (const float*)d_in[10];
    const float* b_g2   = (const float*)d_in[11];
    const float* W_mu   = (const float*)d_in[12];
    const float* b_mu   = (const float*)d_in[13];
    const float* W_sig  = (const float*)d_in[14];
    const float* b_sig  = (const float*)d_in[15];

    float* out        = (float*)d_out;
    float* out_paths  = out;
    float* out_mu     = out + PATHS_ELEMS;
    float* out_sigma  = out + PATHS_ELEMS + BATCH;

    keys_kernel<<<1, 128>>>();
    precompute_kernel<<<BATCH, 160>>>(h_t, W_f1, b_f1, W_g1, b_g1,
                                      W_mu, b_mu, W_sig, b_sig,
                                      out_mu, out_sigma);
    sde_main_kernel<<<BN / 128, 128>>>(W_f1, W_f2, b_f2, W_f3, b_f3,
                                       W_g1, W_g2, b_g2, price, out_paths);
}

// round 8
// speedup vs baseline: 1.0663x; 1.0663x over previous
#include <cuda_runtime.h>
#include <cstdint>

// ---------------------------------------------------------------------------
// NeuralSDEHead: batch=8, d_model=512, hidden=64, n_paths=4096, horizon=128
// out = [paths (8*4096*128), mu (8), sigma (8)]  all fp32
// PRNG: JAX threefry2x32, jax_threefry_partitionable=True semantics.
//
// Strategy: per (batch, step), f and g are scalar functions of scalar y.
// Tabulate them on a y-grid (build kernel, fully parallel), then run the
// sequential path loop with cubic interpolation (tiny per-step cost).
// ---------------------------------------------------------------------------

#define BATCH    8
#define DMODEL   512
#define HIDDEN   64
#define NPATHS   4096
#define HORIZON  128
#define BN       (BATCH * NPATHS)      /* 32768 */
#define PATHS_ELEMS (BN * HORIZON)     /* 4194304 */

#define TAB_G    1024
#define YMIN     (-40.0f)
#define YSPAN    (80.0f)
#define DELTA    (YSPAN / (float)TAB_G)        /* 0.078125 */
#define INV_DELTA ((float)TAB_G / YSPAN)       /* 12.8 */

typedef unsigned long long ull;

// Scratch (allocation-free rule: __device__ globals)
__device__ float        g_base_f1[BATCH * HIDDEN];
__device__ float        g_base_g1[BATCH * HIDDEN];
__device__ unsigned int g_keys[2 * HORIZON];
__device__ float2       g_tab[BATCH * HORIZON * TAB_G];   // 8 MB: {f, g}

// ---------------------------------------------------------------------------
// Threefry-2x32 (JAX-compatible, 20 rounds)
// ---------------------------------------------------------------------------
__device__ __forceinline__ void threefry2x32(unsigned int k0, unsigned int k1,
                                             unsigned int x0, unsigned int x1,
                                             unsigned int* o0, unsigned int* o1)
{
    unsigned int ks0 = k0, ks1 = k1, ks2 = k0 ^ k1 ^ 0x1BD11BDAu;
    x0 += ks0; x1 += ks1;
#define TF_ROUND(r) { x0 += x1; x1 = __funnelshift_l(x1, x1, (r)); x1 ^= x0; }
    TF_ROUND(13) TF_ROUND(15) TF_ROUND(26) TF_ROUND(6)
    x0 += ks1; x1 += ks2 + 1u;
    TF_ROUND(17) TF_ROUND(29) TF_ROUND(16) TF_ROUND(24)
    x0 += ks2; x1 += ks0 + 2u;
    TF_ROUND(13) TF_ROUND(15) TF_ROUND(26) TF_ROUND(6)
    x0 += ks0; x1 += ks1 + 3u;
    TF_ROUND(17) TF_ROUND(29) TF_ROUND(16) TF_ROUND(24)
    x0 += ks1; x1 += ks2 + 4u;
    TF_ROUND(13) TF_ROUND(15) TF_ROUND(26) TF_ROUND(6)
    x0 += ks2; x1 += ks0 + 5u;
#undef TF_ROUND
    *o0 = x0; *o1 = x1;
}

// XLA ErfInv32 (Giles polynomial)
__device__ __forceinline__ float erfinv_xla(float x)
{
    float w = -log1pf(-x * x);
    float p;
    if (w < 5.0f) {
        w = w - 2.5f;
        p = 2.81022636e-08f;
        p = fmaf(p, w, 3.43273939e-07f);
        p = fmaf(p, w, -3.5233877e-06f);
        p = fmaf(p, w, -4.39150654e-06f);
        p = fmaf(p, w, 0.00021858087f);
        p = fmaf(p, w, -0.00125372503f);
        p = fmaf(p, w, -0.00417768164f);
        p = fmaf(p, w, 0.246640727f);
        p = fmaf(p, w, 1.50140941f);
    } else {
        w = sqrtf(w) - 3.0f;
        p = -0.000200214257f;
        p = fmaf(p, w, 0.000100950558f);
        p = fmaf(p, w, 0.00134934322f);
        p = fmaf(p, w, -0.00367342844f);
        p = fmaf(p, w, 0.00573950773f);
        p = fmaf(p, w, -0.0076224613f);
        p = fmaf(p, w, 0.00943887047f);
        p = fmaf(p, w, 1.00167406f);
        p = fmaf(p, w, 2.83297682f);
    }
    return p * x;
}

__device__ __forceinline__ float silu_f(float x)
{
    return __fdividef(x, 1.0f + __expf(-x));
}

__device__ __forceinline__ float softplus_acc(float x)
{
    return fmaxf(x, 0.0f) + log1pf(__expf(-fabsf(x)));
}

// packed f32x2 helpers -------------------------------------------------------
__device__ __forceinline__ ull pack_dup(float x)
{
    unsigned int b = __float_as_uint(x);
    ull r;
    asm("mov.b64 %0, {%1, %2};" : "=l"(r) : "r"(b), "r"(b));
    return r;
}
__device__ __forceinline__ ull pack2(float lo, float hi)
{
    unsigned int a = __float_as_uint(lo), b = __float_as_uint(hi);
    ull r;
    asm("mov.b64 %0, {%1, %2};" : "=l"(r) : "r"(a), "r"(b));
    return r;
}
__device__ __forceinline__ float2 unpack2(ull v)
{
    unsigned int lo, hi;
    asm("mov.b64 {%0, %1}, %2;" : "=r"(lo), "=r"(hi) : "l"(v));
    return make_float2(__uint_as_float(lo), __uint_as_float(hi));
}
#define FMA2(acc, a, b) asm("fma.rn.f32x2 %0, %1, %2, %0;" : "+l"(acc) : "l"(a), "l"(b))

// ---------------------------------------------------------------------------
// Setup kernel (grid=8, block=160): per-batch bases + mu/sigma + split keys.
// All blocks redundantly write the same g_keys values (benign, deterministic).
// ---------------------------------------------------------------------------
__global__ void precompute_kernel(const float* __restrict__ h_t,
                                  const float* __restrict__ W_f1, const float* __restrict__ b_f1,
                                  const float* __restrict__ W_g1, const float* __restrict__ b_g1,
                                  const float* __restrict__ W_mu, const float* __restrict__ b_mu,
                                  const float* __restrict__ W_sig, const float* __restrict__ b_sig,
                                  float* __restrict__ out_mu, float* __restrict__ out_sigma)
{
    int b = blockIdx.x;
    int tid = threadIdx.x;
    const float* h = h_t + b * DMODEL;

    if (tid < 2 * HORIZON / 2) {  // tid < 128: split keys (fold-like)
        unsigned int o0, o1;
        threefry2x32(0u, 42u, 0u, (unsigned int)tid, &o0, &o1);
        g_keys[2 * tid]     = o0;
        g_keys[2 * tid + 1] = o1;
    }

    if (tid < HIDDEN) {
        float s = b_f1[tid];
        for (int i = 0; i < DMODEL; ++i)
            s = fmaf(h[i], W_f1[i * HIDDEN + tid], s);
        g_base_f1[b * HIDDEN + tid] = s;
    } else if (tid < 2 * HIDDEN) {
        int j = tid - HIDDEN;
        float s = b_g1[j];
        for (int i = 0; i < DMODEL; ++i)
            s = fmaf(h[i], W_g1[i * HIDDEN + j], s);
        g_base_g1[b * HIDDEN + j] = s;
    } else if (tid == 2 * HIDDEN) {
        float s = b_mu[0];
        for (int i = 0; i < DMODEL; ++i) s = fmaf(h[i], W_mu[i], s);
        out_mu[b] = s;
    } else if (tid == 2 * HIDDEN + 1) {
        float s = b_sig[0];
        for (int i = 0; i < DMODEL; ++i) s = fmaf(h[i], W_sig[i], s);
        out_sigma[b] = fmaxf(s, 0.0f) + log1pf(expf(-fabsf(s))) + 1e-6f;
    }
}

// ---------------------------------------------------------------------------
// Table build kernel: 1024 blocks (one per (b, step)) x 128 threads.
// Each thread evaluates 8 grid points: f(y_i), g(y_i) via the exact MLP.
// t is constant per block and folded into the bases.
// ---------------------------------------------------------------------------
__global__ __launch_bounds__(128, 2)
void build_table_kernel(const float* __restrict__ W_f1,
                        const float* __restrict__ W_f2, const float* __restrict__ b_f2,
                        const float* __restrict__ W_f3, const float* __restrict__ b_f3,
                        const float* __restrict__ W_g1,
                        const float* __restrict__ W_g2, const float* __restrict__ b_g2)
{
    __shared__ __align__(16) float sWf2[HIDDEN * HIDDEN];   // 16 KB
    __shared__ __align__(16) float sbf2[HIDDEN];
    __shared__ __align__(16) float4 sP[HIDDEN];  // {tbase_f, wy_f, tbase_g, wy_g}
    __shared__ float sWf3[HIDDEN], sWg2[HIDDEN];

    const int tid  = threadIdx.x;
    const int b    = blockIdx.x >> 7;       // 0..7
    const int step = blockIdx.x & 127;      // 0..127
    const float t  = (float)step;

    for (int i = tid; i < HIDDEN * HIDDEN; i += 128) sWf2[i] = W_f2[i];
    if (tid < HIDDEN) {
        sbf2[tid] = b_f2[tid];
        sWf3[tid] = W_f3[tid];
        sWg2[tid] = W_g2[tid];
        sP[tid] = make_float4(
            fmaf(t, W_f1[513 * HIDDEN + tid], g_base_f1[b * HIDDEN + tid]),
            W_f1[512 * HIDDEN + tid],
            fmaf(t, W_g1[513 * HIDDEN + tid], g_base_g1[b * HIDDEN + tid]),
            W_g1[512 * HIDDEN + tid]);
    }
    __syncthreads();

    const float bf3v = b_f3[0];
    const float bg2v = b_g2[0];
    float2* slice = g_tab + (size_t)(b * HORIZON + step) * TAB_G;

    #pragma unroll 1
    for (int k = 0; k < TAB_G / 128; ++k) {
        const int idx = k * 128 + tid;
        const float y = YMIN + (float)idx * DELTA;

        ull acc[HIDDEN / 2];
        #pragma unroll
        for (int m = 0; m < HIDDEN / 2; ++m)
            acc[m] = pack2(sbf2[2 * m], sbf2[2 * m + 1]);
        float ga0 = bg2v, ga1 = 0.0f, ga2 = 0.0f, ga3 = 0.0f;

        #pragma unroll 4
        for (int i = 0; i < HIDDEN; ++i) {
            const float4 p4 = sP[i];
            const float hf = silu_f(fmaf(y, p4.y, p4.x));
            const float hg = silu_f(fmaf(y, p4.w, p4.z));
            const float gw = sWg2[i];
            if      ((i & 3) == 0) ga0 = fmaf(hg, gw, ga0);
            else if ((i & 3) == 1) ga1 = fmaf(hg, gw, ga1);
            else if ((i & 3) == 2) ga2 = fmaf(hg, gw, ga2);
            else                   ga3 = fmaf(hg, gw, ga3);

            const ull a2 = pack_dup(hf);
            const ulonglong2* wr = reinterpret_cast<const ulonglong2*>(&sWf2[i * HIDDEN]);
            #pragma unroll
            for (int q = 0; q < HIDDEN / 4; ++q) {
                ulonglong2 w = wr[q];
                FMA2(acc[2 * q],     a2, w.x);
                FMA2(acc[2 * q + 1], a2, w.y);
            }
        }

        float f0 = bf3v, f1 = 0.0f;
        #pragma unroll
        for (int m = 0; m < HIDDEN / 2; ++m) {
            float2 h2 = unpack2(acc[m]);
            f0 = fmaf(silu_f(h2.x), sWf3[2 * m],     f0);
            f1 = fmaf(silu_f(h2.y), sWf3[2 * m + 1], f1);
        }
        const float f = f0 + f1;
        const float g = softplus_acc((ga0 + ga1) + (ga2 + ga3)) + 1e-6f;

        slice[idx] = make_float2(f, g);
    }
}

// ---------------------------------------------------------------------------
// Exact fallback for y outside the table range (never expected to execute).
// ---------------------------------------------------------------------------
__device__ __noinline__ float2 exact_fg(float y, float t, int b,
                                        const float* W_f1,
                                        const float* W_f2, const float* b_f2,
                                        const float* W_f3, const float* b_f3,
                                        const float* W_g1,
                                        const float* W_g2, const float* b_g2)
{
    float acc[HIDDEN];
    for (int j = 0; j < HIDDEN; ++j) acc[j] = b_f2[j];
    float ga = b_g2[0];
    for (int i = 0; i < HIDDEN; ++i) {
        float xf = g_base_f1[b * HIDDEN + i]
                 + y * W_f1[512 * HIDDEN + i] + t * W_f1[513 * HIDDEN + i];
        float hf = silu_f(xf);
        float xg = g_base_g1[b * HIDDEN + i]
                 + y * W_g1[512 * HIDDEN + i] + t * W_g1[513 * HIDDEN + i];
        float hg = silu_f(xg);
        ga = fmaf(hg, W_g2[i], ga);
        for (int j = 0; j < HIDDEN; ++j)
            acc[j] = fmaf(hf, W_f2[i * HIDDEN + j], acc[j]);
    }
    float f = b_f3[0];
    for (int j = 0; j < HIDDEN; ++j) f = fmaf(silu_f(acc[j]), W_f3[j], f);
    float g = softplus_acc(ga) + 1e-6f;
    return make_float2(f, g);
}

// ---------------------------------------------------------------------------
// Path kernel: 256 blocks x 128 threads; per step: threefry + erfinv + cubic
// table interpolation. Table slices stay hot in L1/L2.
// ---------------------------------------------------------------------------
__global__ __launch_bounds__(128)
void path_kernel(const float* __restrict__ initial_price,
                 float* __restrict__ out_paths,
                 const float* __restrict__ W_f1,
                 const float* __restrict__ W_f2, const float* __restrict__ b_f2,
                 const float* __restrict__ W_f3, const float* __restrict__ b_f3,
                 const float* __restrict__ W_g1,
                 const float* __restrict__ W_g2, const float* __restrict__ b_g2)
{
    __shared__ unsigned int skeys[2 * HORIZON];

    const int tid = threadIdx.x;
    const int row = blockIdx.x * 128 + tid;
    const int b   = row >> 12;

    skeys[tid]       = g_keys[tid];
    skeys[tid + 128] = g_keys[tid + 128];
    __syncthreads();

    float y = logf(initial_price[b]);
    const unsigned int cnt_lo = (unsigned int)row;
    float4* outp4 = reinterpret_cast<float4*>(out_paths + (size_t)row * HORIZON);
    float obuf[4];

    const float2* tab_b = g_tab + (size_t)b * HORIZON * TAB_G;

    #pragma unroll 1
    for (int step = 0; step < HORIZON; ++step) {
        // ---- noise: partitionable random_bits = o0 ^ o1, counts=(0,row) ----
        unsigned int o0, o1;
        threefry2x32(skeys[2 * step], skeys[2 * step + 1], 0u, cnt_lo, &o0, &o1);
        const unsigned int bits = o0 ^ o1;
        const float u01 = __uint_as_float((bits >> 9) | 0x3f800000u) - 1.0f;
        float u = fmaf(u01, 2.0f, -0.99999994039535522f);
        u = fmaxf(-0.99999994039535522f, u);
        const float z = 1.4142135381698608f * erfinv_xla(u);

        // ---- f, g via Catmull-Rom cubic on the (b, step) table slice ----
        float f, g;
        const float p = (y - YMIN) * INV_DELTA;
        const int i1 = (int)floorf(p);
        if (i1 >= 1 && i1 <= TAB_G - 3) {
            const float uu = p - (float)i1;
            const float2* base = tab_b + (size_t)step * TAB_G + i1;
            const float2 q0 = base[-1];
            const float2 q1 = base[0];
            const float2 q2 = base[1];
            const float2 q3 = base[2];
            const float u2 = uu * uu;
            const float u3 = u2 * uu;
            const float w0 = 0.5f * (-u3 + 2.0f * u2 - uu);
            const float w1 = 0.5f * (3.0f * u3 - 5.0f * u2 + 2.0f);
            const float w2 = 0.5f * (-3.0f * u3 + 4.0f * u2 + uu);
            const float w3 = 0.5f * (u3 - u2);
            f = w0 * q0.x + w1 * q1.x + w2 * q2.x + w3 * q3.x;
            g = w0 * q0.y + w1 * q1.y + w2 * q2.y + w3 * q3.y;
        } else {
            float2 fg = exact_fg(y, (float)step, b, W_f1, W_f2, b_f2,
                                 W_f3, b_f3, W_g1, W_g2, b_g2);
            f = fg.x; g = fg.y;
        }

        // ---- Euler-Maruyama (dt = 1, sqrt_dt = 1) ----
        y = (y + f) + g * z;

        const float yc = fminf(fmaxf(y, -20.0f), 20.0f);
        obuf[step & 3] = __expf(yc);
        if ((step & 3) == 3)
            outp4[step >> 2] = make_float4(obuf[0], obuf[1], obuf[2], obuf[3]);
    }
}

// ---------------------------------------------------------------------------
// Launch (graph-capturable: kernels only, no allocs/syncs) — 3 launches.
// ---------------------------------------------------------------------------
extern "C" void kernel_launch(void* const* d_in, const int* in_sizes, int n_in,
                              void* d_out, int out_size)
{
    const float* h_t    = (const float*)d_in[0];
    const float* price  = (const float*)d_in[1];
    const float* W_f1   = (const float*)d_in[2];
    const float* b_f1   = (const float*)d_in[3];
    const float* W_f2   = (const float*)d_in[4];
    const float* b_f2   = (const float*)d_in[5];
    const float* W_f3   = (const float*)d_in[6];
    const float* b_f3   = (const float*)d_in[7];
    const float* W_g1   = (const float*)d_in[8];
    const float* b_g1   = (const float*)d_in[9];
    const float* W_g2   = (const float*)d_in[10];
    const float* b_g2   = (const float*)d_in[11];
    const float* W_mu   = (const float*)d_in[12];
    const float* b_mu   = (const float*)d_in[13];
    const float* W_sig  = (const float*)d_in[14];
    const float* b_sig  = (const float*)d_in[15];

    float* out        = (float*)d_out;
    float* out_paths  = out;
    float* out_mu     = out + PATHS_ELEMS;
    float* out_sigma  = out + PATHS_ELEMS + BATCH;

    precompute_kernel<<<BATCH, 160>>>(h_t, W_f1, b_f1, W_g1, b_g1,
                                      W_mu, b_mu, W_sig, b_sig,
                                      out_mu, out_sigma);
    build_table_kernel<<<BATCH * HORIZON, 128>>>(W_f1, W_f2, b_f2, W_f3, b_f3,
                                                 W_g1, W_g2, b_g2);
    path_kernel<<<BN / 128, 128>>>(price, out_paths, W_f1, W_f2, b_f2,
                                   W_f3, b_f3, W_g1, W_g2, b_g2);
}

// round 9
// speedup vs baseline: 2.5298x; 2.3724x over previous
#include <cuda_runtime.h>
#include <cstdint>

// ---------------------------------------------------------------------------
// NeuralSDEHead: batch=8, d_model=512, hidden=64, n_paths=4096, horizon=128
// out = [paths (8*4096*128), mu (8), sigma (8)]  all fp32
// PRNG: JAX threefry2x32, jax_threefry_partitionable=True semantics.
//
// Strategy: per (batch, step), f and g are scalar functions of scalar y.
// Two-tier tabulation: fine inner grid [-32,32), coarse outer [-192,192).
// Path loop does threefry + erfinv + Catmull-Rom cubic interpolation.
// ---------------------------------------------------------------------------

#define BATCH    8
#define DMODEL   512
#define HIDDEN   64
#define NPATHS   4096
#define HORIZON  128
#define BN       (BATCH * NPATHS)      /* 32768 */
#define PATHS_ELEMS (BN * HORIZON)     /* 4194304 */

#define GI       512                    /* inner grid points */
#define GO       512                    /* outer grid points */
#define TAB_G    (GI + GO)              /* 1024 per (b,step) slice */
#define YI_MIN   (-32.0f)
#define YI_D     (0.125f)
#define YI_INV   (8.0f)
#define YO_MIN   (-192.0f)
#define YO_D     (0.75f)
#define YO_INV   (1.0f / 0.75f)

typedef unsigned long long ull;

// Scratch (allocation-free rule: __device__ globals)
__device__ float        g_base_f1[BATCH * HIDDEN];
__device__ float        g_base_g1[BATCH * HIDDEN];
__device__ unsigned int g_keys[2 * HORIZON];
__device__ float2       g_tab[BATCH * HORIZON * TAB_G];   // 8 MB: {f, g}

// ---------------------------------------------------------------------------
// Threefry-2x32 (JAX-compatible, 20 rounds)
// ---------------------------------------------------------------------------
__device__ __forceinline__ void threefry2x32(unsigned int k0, unsigned int k1,
                                             unsigned int x0, unsigned int x1,
                                             unsigned int* o0, unsigned int* o1)
{
    unsigned int ks0 = k0, ks1 = k1, ks2 = k0 ^ k1 ^ 0x1BD11BDAu;
    x0 += ks0; x1 += ks1;
#define TF_ROUND(r) { x0 += x1; x1 = __funnelshift_l(x1, x1, (r)); x1 ^= x0; }
    TF_ROUND(13) TF_ROUND(15) TF_ROUND(26) TF_ROUND(6)
    x0 += ks1; x1 += ks2 + 1u;
    TF_ROUND(17) TF_ROUND(29) TF_ROUND(16) TF_ROUND(24)
    x0 += ks2; x1 += ks0 + 2u;
    TF_ROUND(13) TF_ROUND(15) TF_ROUND(26) TF_ROUND(6)
    x0 += ks0; x1 += ks1 + 3u;
    TF_ROUND(17) TF_ROUND(29) TF_ROUND(16) TF_ROUND(24)
    x0 += ks1; x1 += ks2 + 4u;
    TF_ROUND(13) TF_ROUND(15) TF_ROUND(26) TF_ROUND(6)
    x0 += ks2; x1 += ks0 + 5u;
#undef TF_ROUND
    *o0 = x0; *o1 = x1;
}

// XLA ErfInv32 (Giles polynomial)
__device__ __forceinline__ float erfinv_xla(float x)
{
    float w = -log1pf(-x * x);
    float p;
    if (w < 5.0f) {
        w = w - 2.5f;
        p = 2.81022636e-08f;
        p = fmaf(p, w, 3.43273939e-07f);
        p = fmaf(p, w, -3.5233877e-06f);
        p = fmaf(p, w, -4.39150654e-06f);
        p = fmaf(p, w, 0.00021858087f);
        p = fmaf(p, w, -0.00125372503f);
        p = fmaf(p, w, -0.00417768164f);
        p = fmaf(p, w, 0.246640727f);
        p = fmaf(p, w, 1.50140941f);
    } else {
        w = sqrtf(w) - 3.0f;
        p = -0.000200214257f;
        p = fmaf(p, w, 0.000100950558f);
        p = fmaf(p, w, 0.00134934322f);
        p = fmaf(p, w, -0.00367342844f);
        p = fmaf(p, w, 0.00573950773f);
        p = fmaf(p, w, -0.0076224613f);
        p = fmaf(p, w, 0.00943887047f);
        p = fmaf(p, w, 1.00167406f);
        p = fmaf(p, w, 2.83297682f);
    }
    return p * x;
}

__device__ __forceinline__ float silu_f(float x)
{
    return __fdividef(x, 1.0f + __expf(-x));
}

__device__ __forceinline__ float softplus_acc(float x)
{
    return fmaxf(x, 0.0f) + log1pf(__expf(-fabsf(x)));
}

// packed f32x2 helpers -------------------------------------------------------
__device__ __forceinline__ ull pack_dup(float x)
{
    unsigned int b = __float_as_uint(x);
    ull r;
    asm("mov.b64 %0, {%1, %2};" : "=l"(r) : "r"(b), "r"(b));
    return r;
}
__device__ __forceinline__ ull pack2(float lo, float hi)
{
    unsigned int a = __float_as_uint(lo), b = __float_as_uint(hi);
    ull r;
    asm("mov.b64 %0, {%1, %2};" : "=l"(r) : "r"(a), "r"(b));
    return r;
}
__device__ __forceinline__ float2 unpack2(ull v)
{
    unsigned int lo, hi;
    asm("mov.b64 {%0, %1}, %2;" : "=r"(lo), "=r"(hi) : "l"(v));
    return make_float2(__uint_as_float(lo), __uint_as_float(hi));
}
#define FMA2(acc, a, b) asm("fma.rn.f32x2 %0, %1, %2, %0;" : "+l"(acc) : "l"(a), "l"(b))

// ---------------------------------------------------------------------------
// Setup kernel (grid=8, block=576): per-batch bases (4 threads/column,
// shuffle-combined) + warp-reduced mu/sigma + split keys.
// ---------------------------------------------------------------------------
__global__ __launch_bounds__(576)
void precompute_kernel(const float* __restrict__ h_t,
                       const float* __restrict__ W_f1, const float* __restrict__ b_f1,
                       const float* __restrict__ W_g1, const float* __restrict__ b_g1,
                       const float* __restrict__ W_mu, const float* __restrict__ b_mu,
                       const float* __restrict__ W_sig, const float* __restrict__ b_sig,
                       float* __restrict__ out_mu, float* __restrict__ out_sigma)
{
    const int b   = blockIdx.x;
    const int tid = threadIdx.x;
    const float* h = h_t + b * DMODEL;

    if (tid < 128) {   // split keys (benign redundant writes across blocks)
        unsigned int o0, o1;
        threefry2x32(0u, 42u, 0u, (unsigned int)tid, &o0, &o1);
        g_keys[2 * tid]     = o0;
        g_keys[2 * tid + 1] = o1;
    }

    if (tid < 256) {
        // f-branch base: 4 threads per column, 128 dims each
        const int col = tid >> 2;
        const int q   = tid & 3;
        float s = 0.0f;
        const int i0 = q * 128;
        #pragma unroll 8
        for (int i = i0; i < i0 + 128; ++i)
            s = fmaf(h[i], W_f1[i * HIDDEN + col], s);
        s += __shfl_xor_sync(0xffffffffu, s, 1);
        s += __shfl_xor_sync(0xffffffffu, s, 2);
        if (q == 0) g_base_f1[b * HIDDEN + col] = s + b_f1[col];
    } else if (tid < 512) {
        const int tt  = tid - 256;
        const int col = tt >> 2;
        const int q   = tt & 3;
        float s = 0.0f;
        const int i0 = q * 128;
        #pragma unroll 8
        for (int i = i0; i < i0 + 128; ++i)
            s = fmaf(h[i], W_g1[i * HIDDEN + col], s);
        s += __shfl_xor_sync(0xffffffffu, s, 1);
        s += __shfl_xor_sync(0xffffffffu, s, 2);
        if (q == 0) g_base_g1[b * HIDDEN + col] = s + b_g1[col];
    } else if (tid < 544) {
        const int lane = tid - 512;     // full warp 16
        float s = 0.0f;
        #pragma unroll 4
        for (int i = lane; i < DMODEL; i += 32)
            s = fmaf(h[i], W_mu[i], s);
        #pragma unroll
        for (int off = 16; off > 0; off >>= 1)
            s += __shfl_xor_sync(0xffffffffu, s, off);
        if (lane == 0) out_mu[b] = s + b_mu[0];
    } else {
        const int lane = tid - 544;     // full warp 17
        float s = 0.0f;
        #pragma unroll 4
        for (int i = lane; i < DMODEL; i += 32)
            s = fmaf(h[i], W_sig[i], s);
        #pragma unroll
        for (int off = 16; off > 0; off >>= 1)
            s += __shfl_xor_sync(0xffffffffu, s, off);
        if (lane == 0) {
            float v = s + b_sig[0];
            out_sigma[b] = fmaxf(v, 0.0f) + log1pf(expf(-fabsf(v))) + 1e-6f;
        }
    }
}

// ---------------------------------------------------------------------------
// Table build kernel: 1024 blocks (one per (b, step)) x 128 threads.
// Each thread evaluates an inner point and an outer point TOGETHER:
// W_f2 rows are loaded once and feed both evals (half LDS, double ILP).
// ---------------------------------------------------------------------------
__global__ __launch_bounds__(128, 2)
void build_table_kernel(const float* __restrict__ W_f1,
                        const float* __restrict__ W_f2, const float* __restrict__ b_f2,
                        const float* __restrict__ W_f3, const float* __restrict__ b_f3,
                        const float* __restrict__ W_g1,
                        const float* __restrict__ W_g2, const float* __restrict__ b_g2)
{
    __shared__ __align__(16) float sWf2[HIDDEN * HIDDEN];   // 16 KB
    __shared__ __align__(16) float sbf2[HIDDEN];
    __shared__ __align__(16) float4 sP[HIDDEN];  // {tbase_f, wy_f, tbase_g, wy_g}
    __shared__ float sWf3[HIDDEN], sWg2[HIDDEN];

    const int tid  = threadIdx.x;
    const int b    = blockIdx.x >> 7;       // 0..7
    const int step = blockIdx.x & 127;      // 0..127
    const float t  = (float)step;

    for (int i = tid; i < HIDDEN * HIDDEN; i += 128) sWf2[i] = W_f2[i];
    if (tid < HIDDEN) {
        sbf2[tid] = b_f2[tid];
        sWf3[tid] = W_f3[tid];
        sWg2[tid] = W_g2[tid];
        sP[tid] = make_float4(
            fmaf(t, W_f1[513 * HIDDEN + tid], g_base_f1[b * HIDDEN + tid]),
            W_f1[512 * HIDDEN + tid],
            fmaf(t, W_g1[513 * HIDDEN + tid], g_base_g1[b * HIDDEN + tid]),
            W_g1[512 * HIDDEN + tid]);
    }
    __syncthreads();

    const float bf3v = b_f3[0];
    const float bg2v = b_g2[0];
    float2* slice = g_tab + (size_t)(b * HORIZON + step) * TAB_G;

    #pragma unroll 1
    for (int k = 0; k < GI / 128; ++k) {
        const int idx = k * 128 + tid;               // 0..511
        const float yA = YI_MIN + (float)idx * YI_D; // inner point
        const float yB = YO_MIN + (float)idx * YO_D; // outer point

        ull accA[HIDDEN / 2], accB[HIDDEN / 2];
        #pragma unroll
        for (int m = 0; m < HIDDEN / 2; ++m) {
            ull bb = pack2(sbf2[2 * m], sbf2[2 * m + 1]);
            accA[m] = bb;
            accB[m] = bb;
        }
        float gaA0 = bg2v, gaA1 = 0.0f, gaB0 = bg2v, gaB1 = 0.0f;

        #pragma unroll 2
        for (int i = 0; i < HIDDEN; ++i) {
            const float4 p4 = sP[i];
            const float hfA = silu_f(fmaf(yA, p4.y, p4.x));
            const float hgA = silu_f(fmaf(yA, p4.w, p4.z));
            const float hfB = silu_f(fmaf(yB, p4.y, p4.x));
            const float hgB = silu_f(fmaf(yB, p4.w, p4.z));
            const float gw = sWg2[i];
            if ((i & 1) == 0) { gaA0 = fmaf(hgA, gw, gaA0); gaB0 = fmaf(hgB, gw, gaB0); }
            else              { gaA1 = fmaf(hgA, gw, gaA1); gaB1 = fmaf(hgB, gw, gaB1); }

            const ull a2A = pack_dup(hfA);
            const ull a2B = pack_dup(hfB);
            const ulonglong2* wr = reinterpret_cast<const ulonglong2*>(&sWf2[i * HIDDEN]);
            #pragma unroll
            for (int q = 0; q < HIDDEN / 4; ++q) {
                ulonglong2 w = wr[q];                 // loaded once, used twice
                FMA2(accA[2 * q],     a2A, w.x);
                FMA2(accB[2 * q],     a2B, w.x);
                FMA2(accA[2 * q + 1], a2A, w.y);
                FMA2(accB[2 * q + 1], a2B, w.y);
            }
        }

        float fA0 = bf3v, fA1 = 0.0f, fB0 = bf3v, fB1 = 0.0f;
        #pragma unroll
        for (int m = 0; m < HIDDEN / 2; ++m) {
            float2 hA = unpack2(accA[m]);
            float2 hB = unpack2(accB[m]);
            const float w0 = sWf3[2 * m], w1 = sWf3[2 * m + 1];
            fA0 = fmaf(silu_f(hA.x), w0, fA0);
            fA1 = fmaf(silu_f(hA.y), w1, fA1);
            fB0 = fmaf(silu_f(hB.x), w0, fB0);
            fB1 = fmaf(silu_f(hB.y), w1, fB1);
        }
        slice[idx]      = make_float2(fA0 + fA1, softplus_acc(gaA0 + gaA1) + 1e-6f);
        slice[idx + GI] = make_float2(fB0 + fB1, softplus_acc(gaB0 + gaB1) + 1e-6f);
    }
}

// ---------------------------------------------------------------------------
// Exact fallback for y outside [-192, 192) (never expected to execute).
// ---------------------------------------------------------------------------
__device__ __noinline__ float2 exact_fg(float y, float t, int b,
                                        const float* W_f1,
                                        const float* W_f2, const float* b_f2,
                                        const float* W_f3, const float* b_f3,
                                        const float* W_g1,
                                        const float* W_g2, const float* b_g2)
{
    float acc[HIDDEN];
    for (int j = 0; j < HIDDEN; ++j) acc[j] = b_f2[j];
    float ga = b_g2[0];
    for (int i = 0; i < HIDDEN; ++i) {
        float xf = g_base_f1[b * HIDDEN + i]
                 + y * W_f1[512 * HIDDEN + i] + t * W_f1[513 * HIDDEN + i];
        float hf = silu_f(xf);
        float xg = g_base_g1[b * HIDDEN + i]
                 + y * W_g1[512 * HIDDEN + i] + t * W_g1[513 * HIDDEN + i];
        float hg = silu_f(xg);
        ga = fmaf(hg, W_g2[i], ga);
        for (int j = 0; j < HIDDEN; ++j)
            acc[j] = fmaf(hf, W_f2[i * HIDDEN + j], acc[j]);
    }
    float f = b_f3[0];
    for (int j = 0; j < HIDDEN; ++j) f = fmaf(silu_f(acc[j]), W_f3[j], f);
    float g = softplus_acc(ga) + 1e-6f;
    return make_float2(f, g);
}

// ---------------------------------------------------------------------------
// Path kernel: 256 blocks x 128 threads; per step: threefry + erfinv + cubic
// two-tier table interpolation.
// ---------------------------------------------------------------------------
__global__ __launch_bounds__(128)
void path_kernel(const float* __restrict__ initial_price,
                 float* __restrict__ out_paths,
                 const float* __restrict__ W_f1,
                 const float* __restrict__ W_f2, const float* __restrict__ b_f2,
                 const float* __restrict__ W_f3, const float* __restrict__ b_f3,
                 const float* __restrict__ W_g1,
                 const float* __restrict__ W_g2, const float* __restrict__ b_g2)
{
    __shared__ unsigned int skeys[2 * HORIZON];

    const int tid = threadIdx.x;
    const int row = blockIdx.x * 128 + tid;
    const int b   = row >> 12;

    skeys[tid]       = g_keys[tid];
    skeys[tid + 128] = g_keys[tid + 128];
    __syncthreads();

    float y = logf(initial_price[b]);
    const unsigned int cnt_lo = (unsigned int)row;
    float4* outp4 = reinterpret_cast<float4*>(out_paths + (size_t)row * HORIZON);

    const float2* tab_b = g_tab + (size_t)b * HORIZON * TAB_G;

    #pragma unroll 1
    for (int s4 = 0; s4 < HORIZON / 4; ++s4) {
        float o[4];
        #pragma unroll
        for (int kk = 0; kk < 4; ++kk) {
            const int step = s4 * 4 + kk;

            // ---- noise (independent of y -> overlaps the table loads) ----
            unsigned int o0, o1;
            threefry2x32(skeys[2 * step], skeys[2 * step + 1], 0u, cnt_lo, &o0, &o1);
            const unsigned int bits = o0 ^ o1;
            const float u01 = __uint_as_float((bits >> 9) | 0x3f800000u) - 1.0f;
            float u = fmaf(u01, 2.0f, -0.99999994039535522f);
            u = fmaxf(-0.99999994039535522f, u);
            const float z = 1.4142135381698608f * erfinv_xla(u);

            // ---- two-tier Catmull-Rom lookup ----
            const float2* slice = tab_b + (size_t)step * TAB_G;
            float f, g;
            bool hit = false;
            float p = (y - YI_MIN) * YI_INV;
            int i1 = (int)floorf(p);
            const float2* base = slice;
            float uu = 0.0f;
            if (i1 >= 1 && i1 <= GI - 3) {
                uu = p - (float)i1;
                base = slice + i1;
                hit = true;
            } else {
                p = (y - YO_MIN) * YO_INV;
                i1 = (int)floorf(p);
                if (i1 >= 1 && i1 <= GO - 3) {
                    uu = p - (float)i1;
                    base = slice + (GI + i1);
                    hit = true;
                }
            }
            if (hit) {
                const float2 q0 = base[-1];
                const float2 q1 = base[0];
                const float2 q2 = base[1];
                const float2 q3 = base[2];
                const float u2 = uu * uu;
                const float u3 = u2 * uu;
                const float w0 = 0.5f * (-u3 + 2.0f * u2 - uu);
                const float w1 = 0.5f * (3.0f * u3 - 5.0f * u2 + 2.0f);
                const float w2 = 0.5f * (-3.0f * u3 + 4.0f * u2 + uu);
                const float w3 = 0.5f * (u3 - u2);
                f = w0 * q0.x + w1 * q1.x + w2 * q2.x + w3 * q3.x;
                g = w0 * q0.y + w1 * q1.y + w2 * q2.y + w3 * q3.y;
            } else {
                float2 fg = exact_fg(y, (float)step, b, W_f1, W_f2, b_f2,
                                     W_f3, b_f3, W_g1, W_g2, b_g2);
                f = fg.x; g = fg.y;
            }

            // ---- Euler-Maruyama (dt = 1, sqrt_dt = 1) ----
            y = (y + f) + g * z;

            const float yc = fminf(fmaxf(y, -20.0f), 20.0f);
            o[kk] = __expf(yc);
        }
        outp4[s4] = make_float4(o[0], o[1], o[2], o[3]);
    }
}

// ---------------------------------------------------------------------------
// Launch (graph-capturable: kernels only, no allocs/syncs) — 3 launches.
// ---------------------------------------------------------------------------
extern "C" void kernel_launch(void* const* d_in, const int* in_sizes, int n_in,
                              void* d_out, int out_size)
{
    const float* h_t    = (const float*)d_in[0];
    const float* price  = (const float*)d_in[1];
    const float* W_f1   = (const float*)d_in[2];
    const float* b_f1   = (const float*)d_in[3];
    const float* W_f2   = (const float*)d_in[4];
    const float* b_f2   = (const float*)d_in[5];
    const float* W_f3   = (const float*)d_in[6];
    const float* b_f3   = (const float*)d_in[7];
    const float* W_g1   = (const float*)d_in[8];
    const float* b_g1   = (const float*)d_in[9];
    const float* W_g2   = (const float*)d_in[10];
    const float* b_g2   = (const float*)d_in[11];
    const float* W_mu   = (const float*)d_in[12];
    const float* b_mu   = (const float*)d_in[13];
    const float* W_sig  = (const float*)d_in[14];
    const float* b_sig  = (const float*)d_in[15];

    float* out        = (float*)d_out;
    float* out_paths  = out;
    float* out_mu     = out + PATHS_ELEMS;
    float* out_sigma  = out + PATHS_ELEMS + BATCH;

    precompute_kernel<<<BATCH, 576>>>(h_t, W_f1, b_f1, W_g1, b_g1,
                                      W_mu, b_mu, W_sig, b_sig,
                                      out_mu, out_sigma);
    build_table_kernel<<<BATCH * HORIZON, 128>>>(W_f1, W_f2, b_f2, W_f3, b_f3,
                                                 W_g1, W_g2, b_g2);
    path_kernel<<<BN / 128, 128>>>(price, out_paths, W_f1, W_f2, b_f2,
                                   W_f3, b_f3, W_g1, W_g2, b_g2);
}

// round 10
// speedup vs baseline: 3.6479x; 1.4420x over previous
#include <cuda_runtime.h>
#include <cstdint>

// ---------------------------------------------------------------------------
// NeuralSDEHead: batch=8, d_model=512, hidden=64, n_paths=4096, horizon=128
// out = [paths (8*4096*128), mu (8), sigma (8)]  all fp32
// PRNG: JAX threefry2x32, jax_threefry_partitionable=True semantics.
//
// Strategy: per (batch, step), f and g are scalar functions of scalar y.
// Two-tier tabulation: fine inner grid [-32,32), coarse outer [-192,192).
// Path loop: threefry + erfinv + Catmull-Rom cubic, 2 paths per thread (ILP).
// ---------------------------------------------------------------------------

#define BATCH    8
#define DMODEL   512
#define HIDDEN   64
#define NPATHS   4096
#define HORIZON  128
#define BN       (BATCH * NPATHS)      /* 32768 */
#define PATHS_ELEMS (BN * HORIZON)     /* 4194304 */

#define GI       256                    /* inner grid points */
#define GO       256                    /* outer grid points */
#define TAB_G    (GI + GO)              /* 512 per (b,step) slice */
#define YI_MIN   (-32.0f)
#define YI_D     (0.25f)
#define YI_INV   (4.0f)
#define YO_MIN   (-192.0f)
#define YO_D     (1.5f)
#define YO_INV   (1.0f / 1.5f)

typedef unsigned long long ull;

// Scratch (allocation-free rule: __device__ globals)
__device__ float        g_base_f1[BATCH * HIDDEN];
__device__ float        g_base_g1[BATCH * HIDDEN];
__device__ unsigned int g_keys[2 * HORIZON];
__device__ float2       g_tab[BATCH * HORIZON * TAB_G];   // 4 MB: {f, g}

// ---------------------------------------------------------------------------
// Threefry-2x32 (JAX-compatible, 20 rounds)
// ---------------------------------------------------------------------------
__device__ __forceinline__ void threefry2x32(unsigned int k0, unsigned int k1,
                                             unsigned int x0, unsigned int x1,
                                             unsigned int* o0, unsigned int* o1)
{
    unsigned int ks0 = k0, ks1 = k1, ks2 = k0 ^ k1 ^ 0x1BD11BDAu;
    x0 += ks0; x1 += ks1;
#define TF_ROUND(r) { x0 += x1; x1 = __funnelshift_l(x1, x1, (r)); x1 ^= x0; }
    TF_ROUND(13) TF_ROUND(15) TF_ROUND(26) TF_ROUND(6)
    x0 += ks1; x1 += ks2 + 1u;
    TF_ROUND(17) TF_ROUND(29) TF_ROUND(16) TF_ROUND(24)
    x0 += ks2; x1 += ks0 + 2u;
    TF_ROUND(13) TF_ROUND(15) TF_ROUND(26) TF_ROUND(6)
    x0 += ks0; x1 += ks1 + 3u;
    TF_ROUND(17) TF_ROUND(29) TF_ROUND(16) TF_ROUND(24)
    x0 += ks1; x1 += ks2 + 4u;
    TF_ROUND(13) TF_ROUND(15) TF_ROUND(26) TF_ROUND(6)
    x0 += ks2; x1 += ks0 + 5u;
#undef TF_ROUND
    *o0 = x0; *o1 = x1;
}

// XLA ErfInv32 (Giles polynomial)
__device__ __forceinline__ float erfinv_xla(float x)
{
    float w = -log1pf(-x * x);
    float p;
    if (w < 5.0f) {
        w = w - 2.5f;
        p = 2.81022636e-08f;
        p = fmaf(p, w, 3.43273939e-07f);
        p = fmaf(p, w, -3.5233877e-06f);
        p = fmaf(p, w, -4.39150654e-06f);
        p = fmaf(p, w, 0.00021858087f);
        p = fmaf(p, w, -0.00125372503f);
        p = fmaf(p, w, -0.00417768164f);
        p = fmaf(p, w, 0.246640727f);
        p = fmaf(p, w, 1.50140941f);
    } else {
        w = sqrtf(w) - 3.0f;
        p = -0.000200214257f;
        p = fmaf(p, w, 0.000100950558f);
        p = fmaf(p, w, 0.00134934322f);
        p = fmaf(p, w, -0.00367342844f);
        p = fmaf(p, w, 0.00573950773f);
        p = fmaf(p, w, -0.0076224613f);
        p = fmaf(p, w, 0.00943887047f);
        p = fmaf(p, w, 1.00167406f);
        p = fmaf(p, w, 2.83297682f);
    }
    return p * x;
}

__device__ __forceinline__ float silu_f(float x)
{
    return __fdividef(x, 1.0f + __expf(-x));
}

__device__ __forceinline__ float softplus_acc(float x)
{
    return fmaxf(x, 0.0f) + log1pf(__expf(-fabsf(x)));
}

// packed f32x2 helpers -------------------------------------------------------
__device__ __forceinline__ ull pack_dup(float x)
{
    unsigned int b = __float_as_uint(x);
    ull r;
    asm("mov.b64 %0, {%1, %2};" : "=l"(r) : "r"(b), "r"(b));
    return r;
}
__device__ __forceinline__ ull pack2(float lo, float hi)
{
    unsigned int a = __float_as_uint(lo), b = __float_as_uint(hi);
    ull r;
    asm("mov.b64 %0, {%1, %2};" : "=l"(r) : "r"(a), "r"(b));
    return r;
}
__device__ __forceinline__ float2 unpack2(ull v)
{
    unsigned int lo, hi;
    asm("mov.b64 {%0, %1}, %2;" : "=r"(lo), "=r"(hi) : "l"(v));
    return make_float2(__uint_as_float(lo), __uint_as_float(hi));
}
#define FMA2(acc, a, b) asm("fma.rn.f32x2 %0, %1, %2, %0;" : "+l"(acc) : "l"(a), "l"(b))

// ---------------------------------------------------------------------------
// Setup kernel (grid=8, block=576): per-batch bases (4 threads/column,
// shuffle-combined) + warp-reduced mu/sigma + split keys.
// ---------------------------------------------------------------------------
__global__ __launch_bounds__(576)
void precompute_kernel(const float* __restrict__ h_t,
                       const float* __restrict__ W_f1, const float* __restrict__ b_f1,
                       const float* __restrict__ W_g1, const float* __restrict__ b_g1,
                       const float* __restrict__ W_mu, const float* __restrict__ b_mu,
                       const float* __restrict__ W_sig, const float* __restrict__ b_sig,
                       float* __restrict__ out_mu, float* __restrict__ out_sigma)
{
    const int b   = blockIdx.x;
    const int tid = threadIdx.x;
    const float* h = h_t + b * DMODEL;

    if (tid < 128) {   // split keys (benign redundant writes across blocks)
        unsigned int o0, o1;
        threefry2x32(0u, 42u, 0u, (unsigned int)tid, &o0, &o1);
        g_keys[2 * tid]     = o0;
        g_keys[2 * tid + 1] = o1;
    }

    if (tid < 256) {
        const int col = tid >> 2;
        const int q   = tid & 3;
        float s = 0.0f;
        const int i0 = q * 128;
        #pragma unroll 8
        for (int i = i0; i < i0 + 128; ++i)
            s = fmaf(h[i], W_f1[i * HIDDEN + col], s);
        s += __shfl_xor_sync(0xffffffffu, s, 1);
        s += __shfl_xor_sync(0xffffffffu, s, 2);
        if (q == 0) g_base_f1[b * HIDDEN + col] = s + b_f1[col];
    } else if (tid < 512) {
        const int tt  = tid - 256;
        const int col = tt >> 2;
        const int q   = tt & 3;
        float s = 0.0f;
        const int i0 = q * 128;
        #pragma unroll 8
        for (int i = i0; i < i0 + 128; ++i)
            s = fmaf(h[i], W_g1[i * HIDDEN + col], s);
        s += __shfl_xor_sync(0xffffffffu, s, 1);
        s += __shfl_xor_sync(0xffffffffu, s, 2);
        if (q == 0) g_base_g1[b * HIDDEN + col] = s + b_g1[col];
    } else if (tid < 544) {
        const int lane = tid - 512;
        float s = 0.0f;
        #pragma unroll 4
        for (int i = lane; i < DMODEL; i += 32)
            s = fmaf(h[i], W_mu[i], s);
        #pragma unroll
        for (int off = 16; off > 0; off >>= 1)
            s += __shfl_xor_sync(0xffffffffu, s, off);
        if (lane == 0) out_mu[b] = s + b_mu[0];
    } else {
        const int lane = tid - 544;
        float s = 0.0f;
        #pragma unroll 4
        for (int i = lane; i < DMODEL; i += 32)
            s = fmaf(h[i], W_sig[i], s);
        #pragma unroll
        for (int off = 16; off > 0; off >>= 1)
            s += __shfl_xor_sync(0xffffffffu, s, off);
        if (lane == 0) {
            float v = s + b_sig[0];
            out_sigma[b] = fmaxf(v, 0.0f) + log1pf(expf(-fabsf(v))) + 1e-6f;
        }
    }
}

// ---------------------------------------------------------------------------
// Table build kernel: 1024 blocks (one per (b, step)) x 128 threads.
// Each thread evaluates an inner point and an outer point TOGETHER:
// W_f2 rows are loaded once and feed both evals (half LDS, double ILP).
// ---------------------------------------------------------------------------
__global__ __launch_bounds__(128, 2)
void build_table_kernel(const float* __restrict__ W_f1,
                        const float* __restrict__ W_f2, const float* __restrict__ b_f2,
                        const float* __restrict__ W_f3, const float* __restrict__ b_f3,
                        const float* __restrict__ W_g1,
                        const float* __restrict__ W_g2, const float* __restrict__ b_g2)
{
    __shared__ __align__(16) float sWf2[HIDDEN * HIDDEN];   // 16 KB
    __shared__ __align__(16) float sbf2[HIDDEN];
    __shared__ __align__(16) float4 sP[HIDDEN];  // {tbase_f, wy_f, tbase_g, wy_g}
    __shared__ float sWf3[HIDDEN], sWg2[HIDDEN];

    const int tid  = threadIdx.x;
    const int b    = blockIdx.x >> 7;       // 0..7
    const int step = blockIdx.x & 127;      // 0..127
    const float t  = (float)step;

    for (int i = tid; i < HIDDEN * HIDDEN; i += 128) sWf2[i] = W_f2[i];
    if (tid < HIDDEN) {
        sbf2[tid] = b_f2[tid];
        sWf3[tid] = W_f3[tid];
        sWg2[tid] = W_g2[tid];
        sP[tid] = make_float4(
            fmaf(t, W_f1[513 * HIDDEN + tid], g_base_f1[b * HIDDEN + tid]),
            W_f1[512 * HIDDEN + tid],
            fmaf(t, W_g1[513 * HIDDEN + tid], g_base_g1[b * HIDDEN + tid]),
            W_g1[512 * HIDDEN + tid]);
    }
    __syncthreads();

    const float bf3v = b_f3[0];
    const float bg2v = b_g2[0];
    float2* slice = g_tab + (size_t)(b * HORIZON + step) * TAB_G;

    #pragma unroll 1
    for (int k = 0; k < GI / 128; ++k) {
        const int idx = k * 128 + tid;               // 0..255
        const float yA = YI_MIN + (float)idx * YI_D; // inner point
        const float yB = YO_MIN + (float)idx * YO_D; // outer point

        ull accA[HIDDEN / 2], accB[HIDDEN / 2];
        #pragma unroll
        for (int m = 0; m < HIDDEN / 2; ++m) {
            ull bb = pack2(sbf2[2 * m], sbf2[2 * m + 1]);
            accA[m] = bb;
            accB[m] = bb;
        }
        float gaA0 = bg2v, gaA1 = 0.0f, gaB0 = bg2v, gaB1 = 0.0f;

        #pragma unroll 2
        for (int i = 0; i < HIDDEN; ++i) {
            const float4 p4 = sP[i];
            const float hfA = silu_f(fmaf(yA, p4.y, p4.x));
            const float hgA = silu_f(fmaf(yA, p4.w, p4.z));
            const float hfB = silu_f(fmaf(yB, p4.y, p4.x));
            const float hgB = silu_f(fmaf(yB, p4.w, p4.z));
            const float gw = sWg2[i];
            if ((i & 1) == 0) { gaA0 = fmaf(hgA, gw, gaA0); gaB0 = fmaf(hgB, gw, gaB0); }
            else              { gaA1 = fmaf(hgA, gw, gaA1); gaB1 = fmaf(hgB, gw, gaB1); }

            const ull a2A = pack_dup(hfA);
            const ull a2B = pack_dup(hfB);
            const ulonglong2* wr = reinterpret_cast<const ulonglong2*>(&sWf2[i * HIDDEN]);
            #pragma unroll
            for (int q = 0; q < HIDDEN / 4; ++q) {
                ulonglong2 w = wr[q];                 // loaded once, used twice
                FMA2(accA[2 * q],     a2A, w.x);
                FMA2(accB[2 * q],     a2B, w.x);
                FMA2(accA[2 * q + 1], a2A, w.y);
                FMA2(accB[2 * q + 1], a2B, w.y);
            }
        }

        float fA0 = bf3v, fA1 = 0.0f, fB0 = bf3v, fB1 = 0.0f;
        #pragma unroll
        for (int m = 0; m < HIDDEN / 2; ++m) {
            float2 hA = unpack2(accA[m]);
            float2 hB = unpack2(accB[m]);
            const float w0 = sWf3[2 * m], w1 = sWf3[2 * m + 1];
            fA0 = fmaf(silu_f(hA.x), w0, fA0);
            fA1 = fmaf(silu_f(hA.y), w1, fA1);
            fB0 = fmaf(silu_f(hB.x), w0, fB0);
            fB1 = fmaf(silu_f(hB.y), w1, fB1);
        }
        slice[idx]      = make_float2(fA0 + fA1, softplus_acc(gaA0 + gaA1) + 1e-6f);
        slice[idx + GI] = make_float2(fB0 + fB1, softplus_acc(gaB0 + gaB1) + 1e-6f);
    }
}

// ---------------------------------------------------------------------------
// Exact fallback for y outside [-192, 192) (never expected to execute).
// ---------------------------------------------------------------------------
__device__ __noinline__ float2 exact_fg(float y, float t, int b,
                                        const float* W_f1,
                                        const float* W_f2, const float* b_f2,
                                        const float* W_f3, const float* b_f3,
                                        const float* W_g1,
                                        const float* W_g2, const float* b_g2)
{
    float acc[HIDDEN];
    for (int j = 0; j < HIDDEN; ++j) acc[j] = b_f2[j];
    float ga = b_g2[0];
    for (int i = 0; i < HIDDEN; ++i) {
        float xf = g_base_f1[b * HIDDEN + i]
                 + y * W_f1[512 * HIDDEN + i] + t * W_f1[513 * HIDDEN + i];
        float hf = silu_f(xf);
        float xg = g_base_g1[b * HIDDEN + i]
                 + y * W_g1[512 * HIDDEN + i] + t * W_g1[513 * HIDDEN + i];
        float hg = silu_f(xg);
        ga = fmaf(hg, W_g2[i], ga);
        for (int j = 0; j < HIDDEN; ++j)
            acc[j] = fmaf(hf, W_f2[i * HIDDEN + j], acc[j]);
    }
    float f = b_f3[0];
    for (int j = 0; j < HIDDEN; ++j) f = fmaf(silu_f(acc[j]), W_f3[j], f);
    float g = softplus_acc(ga) + 1e-6f;
    return make_float2(f, g);
}

// ---------------------------------------------------------------------------
// Table lookup (two-tier Catmull-Rom); returns {f, g}.
// ---------------------------------------------------------------------------
__device__ __forceinline__ float2 lookup_fg(const float2* __restrict__ slice,
                                            float y, float t, int b,
                                            const float* W_f1,
                                            const float* W_f2, const float* b_f2,
                                            const float* W_f3, const float* b_f3,
                                            const float* W_g1,
                                            const float* W_g2, const float* b_g2)
{
    float p = (y - YI_MIN) * YI_INV;
    int i1 = (int)floorf(p);
    const float2* base;
    float uu;
    bool hit;
    if (i1 >= 1 && i1 <= GI - 3) {
        uu = p - (float)i1;
        base = slice + i1;
        hit = true;
    } else {
        p = (y - YO_MIN) * YO_INV;
        i1 = (int)floorf(p);
        hit = (i1 >= 1 && i1 <= GO - 3);
        uu = p - (float)i1;
        base = slice + (GI + i1);
    }
    if (hit) {
        const float2 q0 = base[-1];
        const float2 q1 = base[0];
        const float2 q2 = base[1];
        const float2 q3 = base[2];
        const float u2 = uu * uu;
        const float u3 = u2 * uu;
        const float w0 = 0.5f * (-u3 + 2.0f * u2 - uu);
        const float w1 = 0.5f * (3.0f * u3 - 5.0f * u2 + 2.0f);
        const float w2 = 0.5f * (-3.0f * u3 + 4.0f * u2 + uu);
        const float w3 = 0.5f * (u3 - u2);
        return make_float2(w0 * q0.x + w1 * q1.x + w2 * q2.x + w3 * q3.x,
                           w0 * q0.y + w1 * q1.y + w2 * q2.y + w3 * q3.y);
    }
    return exact_fg(y, t, b, W_f1, W_f2, b_f2, W_f3, b_f3, W_g1, W_g2, b_g2);
}

// ---------------------------------------------------------------------------
// Path kernel: 256 blocks x 64 threads, TWO paths per thread (rows r and
// r+16384) — interleaved chains double the memory-level parallelism.
// ---------------------------------------------------------------------------
__global__ __launch_bounds__(64)
void path_kernel(const float* __restrict__ initial_price,
                 float* __restrict__ out_paths,
                 const float* __restrict__ W_f1,
                 const float* __restrict__ W_f2, const float* __restrict__ b_f2,
                 const float* __restrict__ W_f3, const float* __restrict__ b_f3,
                 const float* __restrict__ W_g1,
                 const float* __restrict__ W_g2, const float* __restrict__ b_g2)
{
    __shared__ unsigned int skeys[2 * HORIZON];

    const int tid  = threadIdx.x;                 // 0..63
    const int rowA = blockIdx.x * 64 + tid;       // 0..16383
    const int rowB = rowA + BN / 2;               // 16384..32767
    const int bA   = rowA >> 12;                  // 0..3
    const int bB   = rowB >> 12;                  // 4..7

    for (int i = tid; i < 2 * HORIZON; i += 64) skeys[i] = g_keys[i];
    __syncthreads();

    float yA = logf(initial_price[bA]);
    float yB = logf(initial_price[bB]);
    const unsigned int cntA = (unsigned int)rowA;
    const unsigned int cntB = (unsigned int)rowB;
    float4* outA4 = reinterpret_cast<float4*>(out_paths + (size_t)rowA * HORIZON);
    float4* outB4 = reinterpret_cast<float4*>(out_paths + (size_t)rowB * HORIZON);

    const float2* tabA = g_tab + (size_t)bA * HORIZON * TAB_G;
    const float2* tabB = g_tab + (size_t)bB * HORIZON * TAB_G;

    #pragma unroll 1
    for (int s4 = 0; s4 < HORIZON / 4; ++s4) {
        float oA[4], oB[4];
        #pragma unroll
        for (int kk = 0; kk < 4; ++kk) {
            const int step = s4 * 4 + kk;
            const unsigned int k0 = skeys[2 * step], k1 = skeys[2 * step + 1];

            // ---- noise for both chains (independent ALU work) ----
            unsigned int a0, a1, b0, b1;
            threefry2x32(k0, k1, 0u, cntA, &a0, &a1);
            threefry2x32(k0, k1, 0u, cntB, &b0, &b1);
            const unsigned int bitsA = a0 ^ a1;
            const unsigned int bitsB = b0 ^ b1;
            float uA = fmaf(__uint_as_float((bitsA >> 9) | 0x3f800000u) - 1.0f,
                            2.0f, -0.99999994039535522f);
            float uB = fmaf(__uint_as_float((bitsB >> 9) | 0x3f800000u) - 1.0f,
                            2.0f, -0.99999994039535522f);
            uA = fmaxf(-0.99999994039535522f, uA);
            uB = fmaxf(-0.99999994039535522f, uB);
            const float zA = 1.4142135381698608f * erfinv_xla(uA);
            const float zB = 1.4142135381698608f * erfinv_xla(uB);

            // ---- table lookups (two independent load chains) ----
            const float2 fgA = lookup_fg(tabA + (size_t)step * TAB_G, yA, (float)step,
                                         bA, W_f1, W_f2, b_f2, W_f3, b_f3,
                                         W_g1, W_g2, b_g2);
            const float2 fgB = lookup_fg(tabB + (size_t)step * TAB_G, yB, (float)step,
                                         bB, W_f1, W_f2, b_f2, W_f3, b_f3,
                                         W_g1, W_g2, b_g2);

            // ---- Euler-Maruyama (dt = 1, sqrt_dt = 1) ----
            yA = (yA + fgA.x) + fgA.y * zA;
            yB = (yB + fgB.x) + fgB.y * zB;

            oA[kk] = __expf(fminf(fmaxf(yA, -20.0f), 20.0f));
            oB[kk] = __expf(fminf(fmaxf(yB, -20.0f), 20.0f));
        }
        outA4[s4] = make_float4(oA[0], oA[1], oA[2], oA[3]);
        outB4[s4] = make_float4(oB[0], oB[1], oB[2], oB[3]);
    }
}

// ---------------------------------------------------------------------------
// Launch (graph-capturable: kernels only, no allocs/syncs) — 3 launches.
// ---------------------------------------------------------------------------
extern "C" void kernel_launch(void* const* d_in, const int* in_sizes, int n_in,
                              void* d_out, int out_size)
{
    const float* h_t    = (const float*)d_in[0];
    const float* price  = (const float*)d_in[1];
    const float* W_f1   = (const float*)d_in[2];
    const float* b_f1   = (const float*)d_in[3];
    const float* W_f2   = (const float*)d_in[4];
    const float* b_f2   = (const float*)d_in[5];
    const float* W_f3   = (const float*)d_in[6];
    const float* b_f3   = (const float*)d_in[7];
    const float* W_g1   = (const float*)d_in[8];
    const float* b_g1   = (const float*)d_in[9];
    const float* W_g2   = (const float*)d_in[10];
    const float* b_g2   = (const float*)d_in[11];
    const float* W_mu   = (const float*)d_in[12];
    const float* b_mu   = (const float*)d_in[13];
    const float* W_sig  = (const float*)d_in[14];
    const float* b_sig  = (const float*)d_in[15];

    float* out        = (float*)d_out;
    float* out_paths  = out;
    float* out_mu     = out + PATHS_ELEMS;
    float* out_sigma  = out + PATHS_ELEMS + BATCH;

    precompute_kernel<<<BATCH, 576>>>(h_t, W_f1, b_f1, W_g1, b_g1,
                                      W_mu, b_mu, W_sig, b_sig,
                                      out_mu, out_sigma);
    build_table_kernel<<<BATCH * HORIZON, 128>>>(W_f1, W_f2, b_f2, W_f3, b_f3,
                                                 W_g1, W_g2, b_g2);
    path_kernel<<<BN / 128, 64>>>(price, out_paths, W_f1, W_f2, b_f2,
                                  W_f3, b_f3, W_g1, W_g2, b_g2);
}

// round 11
// speedup vs baseline: 5.9442x; 1.6295x over previous
#include <cuda_runtime.h>
#include <cstdint>

// ---------------------------------------------------------------------------
// NeuralSDEHead: batch=8, d_model=512, hidden=64, n_paths=4096, horizon=128
// out = [paths (8*4096*128), mu (8), sigma (8)]  all fp32
// PRNG: JAX threefry2x32, jax_threefry_partitionable=True semantics.
//
// Strategy: per (batch, step), f and g are scalar functions of scalar y.
// Two-tier tabulation: fine inner grid [-32,32) Δ=0.5, coarse outer
// [-384,384) Δ=3.0. Path loop: threefry + erfinv + Catmull-Rom cubic,
// 2 paths per thread (ILP) + L1 prefetch of next step's table slice.
// ---------------------------------------------------------------------------

#define BATCH    8
#define DMODEL   512
#define HIDDEN   64
#define NPATHS   4096
#define HORIZON  128
#define BN       (BATCH * NPATHS)      /* 32768 */
#define PATHS_ELEMS (BN * HORIZON)     /* 4194304 */

#define GI       128                    /* inner grid points */
#define GO       256                    /* outer grid points */
#define TAB_G    (GI + GO)              /* 384 per (b,step) slice */
#define YI_MIN   (-32.0f)
#define YI_D     (0.5f)
#define YI_INV   (2.0f)
#define YO_MIN   (-384.0f)
#define YO_D     (3.0f)
#define YO_INV   (1.0f / 3.0f)

typedef unsigned long long ull;

// Scratch (allocation-free rule: __device__ globals)
__device__ float        g_base_f1[BATCH * HIDDEN];
__device__ float        g_base_g1[BATCH * HIDDEN];
__device__ unsigned int g_keys[2 * HORIZON];
__device__ float2       g_tab[BATCH * HORIZON * TAB_G];   // 3 MB: {f, g}

// ---------------------------------------------------------------------------
// Threefry-2x32 (JAX-compatible, 20 rounds)
// ---------------------------------------------------------------------------
__device__ __forceinline__ void threefry2x32(unsigned int k0, unsigned int k1,
                                             unsigned int x0, unsigned int x1,
                                             unsigned int* o0, unsigned int* o1)
{
    unsigned int ks0 = k0, ks1 = k1, ks2 = k0 ^ k1 ^ 0x1BD11BDAu;
    x0 += ks0; x1 += ks1;
#define TF_ROUND(r) { x0 += x1; x1 = __funnelshift_l(x1, x1, (r)); x1 ^= x0; }
    TF_ROUND(13) TF_ROUND(15) TF_ROUND(26) TF_ROUND(6)
    x0 += ks1; x1 += ks2 + 1u;
    TF_ROUND(17) TF_ROUND(29) TF_ROUND(16) TF_ROUND(24)
    x0 += ks2; x1 += ks0 + 2u;
    TF_ROUND(13) TF_ROUND(15) TF_ROUND(26) TF_ROUND(6)
    x0 += ks0; x1 += ks1 + 3u;
    TF_ROUND(17) TF_ROUND(29) TF_ROUND(16) TF_ROUND(24)
    x0 += ks1; x1 += ks2 + 4u;
    TF_ROUND(13) TF_ROUND(15) TF_ROUND(26) TF_ROUND(6)
    x0 += ks2; x1 += ks0 + 5u;
#undef TF_ROUND
    *o0 = x0; *o1 = x1;
}

// XLA ErfInv32 (Giles polynomial)
__device__ __forceinline__ float erfinv_xla(float x)
{
    float w = -log1pf(-x * x);
    float p;
    if (w < 5.0f) {
        w = w - 2.5f;
        p = 2.81022636e-08f;
        p = fmaf(p, w, 3.43273939e-07f);
        p = fmaf(p, w, -3.5233877e-06f);
        p = fmaf(p, w, -4.39150654e-06f);
        p = fmaf(p, w, 0.00021858087f);
        p = fmaf(p, w, -0.00125372503f);
        p = fmaf(p, w, -0.00417768164f);
        p = fmaf(p, w, 0.246640727f);
        p = fmaf(p, w, 1.50140941f);
    } else {
        w = sqrtf(w) - 3.0f;
        p = -0.000200214257f;
        p = fmaf(p, w, 0.000100950558f);
        p = fmaf(p, w, 0.00134934322f);
        p = fmaf(p, w, -0.00367342844f);
        p = fmaf(p, w, 0.00573950773f);
        p = fmaf(p, w, -0.0076224613f);
        p = fmaf(p, w, 0.00943887047f);
        p = fmaf(p, w, 1.00167406f);
        p = fmaf(p, w, 2.83297682f);
    }
    return p * x;
}

__device__ __forceinline__ float silu_f(float x)
{
    return __fdividef(x, 1.0f + __expf(-x));
}

__device__ __forceinline__ float softplus_acc(float x)
{
    return fmaxf(x, 0.0f) + log1pf(__expf(-fabsf(x)));
}

// packed f32x2 helpers -------------------------------------------------------
__device__ __forceinline__ ull pack_dup(float x)
{
    unsigned int b = __float_as_uint(x);
    ull r;
    asm("mov.b64 %0, {%1, %2};" : "=l"(r) : "r"(b), "r"(b));
    return r;
}
__device__ __forceinline__ ull pack2(float lo, float hi)
{
    unsigned int a = __float_as_uint(lo), b = __float_as_uint(hi);
    ull r;
    asm("mov.b64 %0, {%1, %2};" : "=l"(r) : "r"(a), "r"(b));
    return r;
}
__device__ __forceinline__ float2 unpack2(ull v)
{
    unsigned int lo, hi;
    asm("mov.b64 {%0, %1}, %2;" : "=r"(lo), "=r"(hi) : "l"(v));
    return make_float2(__uint_as_float(lo), __uint_as_float(hi));
}
#define FMA2(acc, a, b) asm("fma.rn.f32x2 %0, %1, %2, %0;" : "+l"(acc) : "l"(a), "l"(b))

// ---------------------------------------------------------------------------
// Setup kernel (grid=8, block=576): per-batch bases (4 threads/column,
// shuffle-combined) + warp-reduced mu/sigma + split keys.
// ---------------------------------------------------------------------------
__global__ __launch_bounds__(576)
void precompute_kernel(const float* __restrict__ h_t,
                       const float* __restrict__ W_f1, const float* __restrict__ b_f1,
                       const float* __restrict__ W_g1, const float* __restrict__ b_g1,
                       const float* __restrict__ W_mu, const float* __restrict__ b_mu,
                       const float* __restrict__ W_sig, const float* __restrict__ b_sig,
                       float* __restrict__ out_mu, float* __restrict__ out_sigma)
{
    const int b   = blockIdx.x;
    const int tid = threadIdx.x;
    const float* h = h_t + b * DMODEL;

    if (tid < 128) {   // split keys (benign redundant writes across blocks)
        unsigned int o0, o1;
        threefry2x32(0u, 42u, 0u, (unsigned int)tid, &o0, &o1);
        g_keys[2 * tid]     = o0;
        g_keys[2 * tid + 1] = o1;
    }

    if (tid < 256) {
        const int col = tid >> 2;
        const int q   = tid & 3;
        float s = 0.0f;
        const int i0 = q * 128;
        #pragma unroll 8
        for (int i = i0; i < i0 + 128; ++i)
            s = fmaf(h[i], W_f1[i * HIDDEN + col], s);
        s += __shfl_xor_sync(0xffffffffu, s, 1);
        s += __shfl_xor_sync(0xffffffffu, s, 2);
        if (q == 0) g_base_f1[b * HIDDEN + col] = s + b_f1[col];
    } else if (tid < 512) {
        const int tt  = tid - 256;
        const int col = tt >> 2;
        const int q   = tt & 3;
        float s = 0.0f;
        const int i0 = q * 128;
        #pragma unroll 8
        for (int i = i0; i < i0 + 128; ++i)
            s = fmaf(h[i], W_g1[i * HIDDEN + col], s);
        s += __shfl_xor_sync(0xffffffffu, s, 1);
        s += __shfl_xor_sync(0xffffffffu, s, 2);
        if (q == 0) g_base_g1[b * HIDDEN + col] = s + b_g1[col];
    } else if (tid < 544) {
        const int lane = tid - 512;
        float s = 0.0f;
        #pragma unroll 4
        for (int i = lane; i < DMODEL; i += 32)
            s = fmaf(h[i], W_mu[i], s);
        #pragma unroll
        for (int off = 16; off > 0; off >>= 1)
            s += __shfl_xor_sync(0xffffffffu, s, off);
        if (lane == 0) out_mu[b] = s + b_mu[0];
    } else {
        const int lane = tid - 544;
        float s = 0.0f;
        #pragma unroll 4
        for (int i = lane; i < DMODEL; i += 32)
            s = fmaf(h[i], W_sig[i], s);
        #pragma unroll
        for (int off = 16; off > 0; off >>= 1)
            s += __shfl_xor_sync(0xffffffffu, s, off);
        if (lane == 0) {
            float v = s + b_sig[0];
            out_sigma[b] = fmaxf(v, 0.0f) + log1pf(expf(-fabsf(v))) + 1e-6f;
        }
    }
}

// ---------------------------------------------------------------------------
// Table build kernel: 1024 blocks (one per (b, step)) x 128 threads.
// Pass 1: dual eval (inner tid + outer tid) sharing W_f2 row loads.
// Pass 2: single eval (outer 128+tid).
// ---------------------------------------------------------------------------
__global__ __launch_bounds__(128, 2)
void build_table_kernel(const float* __restrict__ W_f1,
                        const float* __restrict__ W_f2, const float* __restrict__ b_f2,
                        const float* __restrict__ W_f3, const float* __restrict__ b_f3,
                        const float* __restrict__ W_g1,
                        const float* __restrict__ W_g2, const float* __restrict__ b_g2)
{
    __shared__ __align__(16) float sWf2[HIDDEN * HIDDEN];   // 16 KB
    __shared__ __align__(16) float sbf2[HIDDEN];
    __shared__ __align__(16) float4 sP[HIDDEN];  // {tbase_f, wy_f, tbase_g, wy_g}
    __shared__ float sWf3[HIDDEN], sWg2[HIDDEN];

    const int tid  = threadIdx.x;
    const int b    = blockIdx.x >> 7;       // 0..7
    const int step = blockIdx.x & 127;      // 0..127
    const float t  = (float)step;

    for (int i = tid; i < HIDDEN * HIDDEN; i += 128) sWf2[i] = W_f2[i];
    if (tid < HIDDEN) {
        sbf2[tid] = b_f2[tid];
        sWf3[tid] = W_f3[tid];
        sWg2[tid] = W_g2[tid];
        sP[tid] = make_float4(
            fmaf(t, W_f1[513 * HIDDEN + tid], g_base_f1[b * HIDDEN + tid]),
            W_f1[512 * HIDDEN + tid],
            fmaf(t, W_g1[513 * HIDDEN + tid], g_base_g1[b * HIDDEN + tid]),
            W_g1[512 * HIDDEN + tid]);
    }
    __syncthreads();

    const float bf3v = b_f3[0];
    const float bg2v = b_g2[0];
    float2* slice = g_tab + (size_t)(b * HORIZON + step) * TAB_G;

    // ---- pass 1: dual eval (inner yA, outer yB) ----
    {
        const float yA = YI_MIN + (float)tid * YI_D;
        const float yB = YO_MIN + (float)tid * YO_D;

        ull accA[HIDDEN / 2], accB[HIDDEN / 2];
        #pragma unroll
        for (int m = 0; m < HIDDEN / 2; ++m) {
            ull bb = pack2(sbf2[2 * m], sbf2[2 * m + 1]);
            accA[m] = bb;
            accB[m] = bb;
        }
        float gaA0 = bg2v, gaA1 = 0.0f, gaB0 = bg2v, gaB1 = 0.0f;

        #pragma unroll 2
        for (int i = 0; i < HIDDEN; ++i) {
            const float4 p4 = sP[i];
            const float hfA = silu_f(fmaf(yA, p4.y, p4.x));
            const float hgA = silu_f(fmaf(yA, p4.w, p4.z));
            const float hfB = silu_f(fmaf(yB, p4.y, p4.x));
            const float hgB = silu_f(fmaf(yB, p4.w, p4.z));
            const float gw = sWg2[i];
            if ((i & 1) == 0) { gaA0 = fmaf(hgA, gw, gaA0); gaB0 = fmaf(hgB, gw, gaB0); }
            else              { gaA1 = fmaf(hgA, gw, gaA1); gaB1 = fmaf(hgB, gw, gaB1); }

            const ull a2A = pack_dup(hfA);
            const ull a2B = pack_dup(hfB);
            const ulonglong2* wr = reinterpret_cast<const ulonglong2*>(&sWf2[i * HIDDEN]);
            #pragma unroll
            for (int q = 0; q < HIDDEN / 4; ++q) {
                ulonglong2 w = wr[q];                 // loaded once, used twice
                FMA2(accA[2 * q],     a2A, w.x);
                FMA2(accB[2 * q],     a2B, w.x);
                FMA2(accA[2 * q + 1], a2A, w.y);
                FMA2(accB[2 * q + 1], a2B, w.y);
            }
        }

        float fA0 = bf3v, fA1 = 0.0f, fB0 = bf3v, fB1 = 0.0f;
        #pragma unroll
        for (int m = 0; m < HIDDEN / 2; ++m) {
            float2 hA = unpack2(accA[m]);
            float2 hB = unpack2(accB[m]);
            const float w0 = sWf3[2 * m], w1 = sWf3[2 * m + 1];
            fA0 = fmaf(silu_f(hA.x), w0, fA0);
            fA1 = fmaf(silu_f(hA.y), w1, fA1);
            fB0 = fmaf(silu_f(hB.x), w0, fB0);
            fB1 = fmaf(silu_f(hB.y), w1, fB1);
        }
        slice[tid]      = make_float2(fA0 + fA1, softplus_acc(gaA0 + gaA1) + 1e-6f);
        slice[GI + tid] = make_float2(fB0 + fB1, softplus_acc(gaB0 + gaB1) + 1e-6f);
    }

    // ---- pass 2: single outer eval (idx = 128 + tid) ----
    {
        const float yB = YO_MIN + (float)(128 + tid) * YO_D;

        ull accB[HIDDEN / 2];
        #pragma unroll
        for (int m = 0; m < HIDDEN / 2; ++m)
            accB[m] = pack2(sbf2[2 * m], sbf2[2 * m + 1]);
        float gaB0 = bg2v, gaB1 = 0.0f;

        #pragma unroll 4
        for (int i = 0; i < HIDDEN; ++i) {
            const float4 p4 = sP[i];
            const float hfB = silu_f(fmaf(yB, p4.y, p4.x));
            const float hgB = silu_f(fmaf(yB, p4.w, p4.z));
            const float gw = sWg2[i];
            if ((i & 1) == 0) gaB0 = fmaf(hgB, gw, gaB0);
            else              gaB1 = fmaf(hgB, gw, gaB1);

            const ull a2B = pack_dup(hfB);
            const ulonglong2* wr = reinterpret_cast<const ulonglong2*>(&sWf2[i * HIDDEN]);
            #pragma unroll
            for (int q = 0; q < HIDDEN / 4; ++q) {
                ulonglong2 w = wr[q];
                FMA2(accB[2 * q],     a2B, w.x);
                FMA2(accB[2 * q + 1], a2B, w.y);
            }
        }

        float fB0 = bf3v, fB1 = 0.0f;
        #pragma unroll
        for (int m = 0; m < HIDDEN / 2; ++m) {
            float2 hB = unpack2(accB[m]);
            fB0 = fmaf(silu_f(hB.x), sWf3[2 * m],     fB0);
            fB1 = fmaf(silu_f(hB.y), sWf3[2 * m + 1], fB1);
        }
        slice[GI + 128 + tid] = make_float2(fB0 + fB1,
                                            softplus_acc(gaB0 + gaB1) + 1e-6f);
    }
}

// ---------------------------------------------------------------------------
// Exact fallback for y outside [-384, 384) (never expected to execute).
// ---------------------------------------------------------------------------
__device__ __noinline__ float2 exact_fg(float y, float t, int b,
                                        const float* W_f1,
                                        const float* W_f2, const float* b_f2,
                                        const float* W_f3, const float* b_f3,
                                        const float* W_g1,
                                        const float* W_g2, const float* b_g2)
{
    float acc[HIDDEN];
    for (int j = 0; j < HIDDEN; ++j) acc[j] = b_f2[j];
    float ga = b_g2[0];
    for (int i = 0; i < HIDDEN; ++i) {
        float xf = g_base_f1[b * HIDDEN + i]
                 + y * W_f1[512 * HIDDEN + i] + t * W_f1[513 * HIDDEN + i];
        float hf = silu_f(xf);
        float xg = g_base_g1[b * HIDDEN + i]
                 + y * W_g1[512 * HIDDEN + i] + t * W_g1[513 * HIDDEN + i];
        float hg = silu_f(xg);
        ga = fmaf(hg, W_g2[i], ga);
        for (int j = 0; j < HIDDEN; ++j)
            acc[j] = fmaf(hf, W_f2[i * HIDDEN + j], acc[j]);
    }
    float f = b_f3[0];
    for (int j = 0; j < HIDDEN; ++j) f = fmaf(silu_f(acc[j]), W_f3[j], f);
    float g = softplus_acc(ga) + 1e-6f;
    return make_float2(f, g);
}

// ---------------------------------------------------------------------------
// Table lookup (two-tier Catmull-Rom); returns {f, g}.
// ---------------------------------------------------------------------------
__device__ __forceinline__ float2 lookup_fg(const float2* __restrict__ slice,
                                            float y, float t, int b,
                                            const float* W_f1,
                                            const float* W_f2, const float* b_f2,
                                            const float* W_f3, const float* b_f3,
                                            const float* W_g1,
                                            const float* W_g2, const float* b_g2)
{
    float p = (y - YI_MIN) * YI_INV;
    int i1 = (int)floorf(p);
    const float2* base;
    float uu;
    bool hit;
    if (i1 >= 1 && i1 <= GI - 3) {
        uu = p - (float)i1;
        base = slice + i1;
        hit = true;
    } else {
        p = (y - YO_MIN) * YO_INV;
        i1 = (int)floorf(p);
        hit = (i1 >= 1 && i1 <= GO - 3);
        uu = p - (float)i1;
        base = slice + (GI + i1);
    }
    if (hit) {
        const float2 q0 = base[-1];
        const float2 q1 = base[0];
        const float2 q2 = base[1];
        const float2 q3 = base[2];
        const float u2 = uu * uu;
        const float u3 = u2 * uu;
        const float w0 = 0.5f * (-u3 + 2.0f * u2 - uu);
        const float w1 = 0.5f * (3.0f * u3 - 5.0f * u2 + 2.0f);
        const float w2 = 0.5f * (-3.0f * u3 + 4.0f * u2 + uu);
        const float w3 = 0.5f * (u3 - u2);
        return make_float2(w0 * q0.x + w1 * q1.x + w2 * q2.x + w3 * q3.x,
                           w0 * q0.y + w1 * q1.y + w2 * q2.y + w3 * q3.y);
    }
    return exact_fg(y, t, b, W_f1, W_f2, b_f2, W_f3, b_f3, W_g1, W_g2, b_g2);
}

// ---------------------------------------------------------------------------
// Path kernel: 256 blocks x 64 threads, TWO paths per thread (rows r and
// r+16384). L1-prefetch of next step's slices hides the L2 latency.
// ---------------------------------------------------------------------------
__global__ __launch_bounds__(64)
void path_kernel(const float* __restrict__ initial_price,
                 float* __restrict__ out_paths,
                 const float* __restrict__ W_f1,
                 const float* __restrict__ W_f2, const float* __restrict__ b_f2,
                 const float* __restrict__ W_f3, const float* __restrict__ b_f3,
                 const float* __restrict__ W_g1,
                 const float* __restrict__ W_g2, const float* __restrict__ b_g2)
{
    __shared__ unsigned int skeys[2 * HORIZON];

    const int tid  = threadIdx.x;                 // 0..63
    const int rowA = blockIdx.x * 64 + tid;       // 0..16383
    const int rowB = rowA + BN / 2;               // 16384..32767
    const int bA   = rowA >> 12;                  // 0..3
    const int bB   = rowB >> 12;                  // 4..7

    for (int i = tid; i < 2 * HORIZON; i += 64) skeys[i] = g_keys[i];
    __syncthreads();

    float yA = logf(initial_price[bA]);
    float yB = logf(initial_price[bB]);
    const unsigned int cntA = (unsigned int)rowA;
    const unsigned int cntB = (unsigned int)rowB;
    float4* outA4 = reinterpret_cast<float4*>(out_paths + (size_t)rowA * HORIZON);
    float4* outB4 = reinterpret_cast<float4*>(out_paths + (size_t)rowB * HORIZON);

    const float2* tabA = g_tab + (size_t)bA * HORIZON * TAB_G;
    const float2* tabB = g_tab + (size_t)bB * HORIZON * TAB_G;

    // Per-thread prefetch assignment: warp 0 covers chain A's slice lines,
    // warp 1 covers chain B's. Slice = 384*8B = 3 KB = 24 x 128B lines.
    const int pf_line = tid & 31;
    const char* pf_base0 = (const char*)((tid < 32) ? tabA : tabB);

    // prefetch step 0
    if (pf_line < 24)
        asm volatile("prefetch.global.L1 [%0];"
                     :: "l"(pf_base0 + (size_t)pf_line * 128));

    #pragma unroll 1
    for (int s4 = 0; s4 < HORIZON / 4; ++s4) {
        float oA[4], oB[4];
        #pragma unroll
        for (int kk = 0; kk < 4; ++kk) {
            const int step = s4 * 4 + kk;

            // ---- prefetch next step's slices into L1 ----
            if (step + 1 < HORIZON && pf_line < 24)
                asm volatile("prefetch.global.L1 [%0];"
                             :: "l"(pf_base0 + (size_t)(step + 1) * (TAB_G * 8)
                                             + (size_t)pf_line * 128));

            const unsigned int k0 = skeys[2 * step], k1 = skeys[2 * step + 1];

            // ---- noise for both chains (independent ALU work) ----
            unsigned int a0, a1, b0, b1;
            threefry2x32(k0, k1, 0u, cntA, &a0, &a1);
            threefry2x32(k0, k1, 0u, cntB, &b0, &b1);
            const unsigned int bitsA = a0 ^ a1;
            const unsigned int bitsB = b0 ^ b1;
            float uA = fmaf(__uint_as_float((bitsA >> 9) | 0x3f800000u) - 1.0f,
                            2.0f, -0.99999994039535522f);
            float uB = fmaf(__uint_as_float((bitsB >> 9) | 0x3f800000u) - 1.0f,
                            2.0f, -0.99999994039535522f);
            uA = fmaxf(-0.99999994039535522f, uA);
            uB = fmaxf(-0.99999994039535522f, uB);
            const float zA = 1.4142135381698608f * erfinv_xla(uA);
            const float zB = 1.4142135381698608f * erfinv_xla(uB);

            // ---- table lookups (two independent load chains) ----
            const float2 fgA = lookup_fg(tabA + (size_t)step * TAB_G, yA, (float)step,
                                         bA, W_f1, W_f2, b_f2, W_f3, b_f3,
                                         W_g1, W_g2, b_g2);
            const float2 fgB = lookup_fg(tabB + (size_t)step * TAB_G, yB, (float)step,
                                         bB, W_f1, W_f2, b_f2, W_f3, b_f3,
                                         W_g1, W_g2, b_g2);

            // ---- Euler-Maruyama (dt = 1, sqrt_dt = 1) ----
            yA = (yA + fgA.x) + fgA.y * zA;
            yB = (yB + fgB.x) + fgB.y * zB;

            oA[kk] = __expf(fminf(fmaxf(yA, -20.0f), 20.0f));
            oB[kk] = __expf(fminf(fmaxf(yB, -20.0f), 20.0f));
        }
        outA4[s4] = make_float4(oA[0], oA[1], oA[2], oA[3]);
        outB4[s4] = make_float4(oB[0], oB[1], oB[2], oB[3]);
    }
}

// ---------------------------------------------------------------------------
// Launch (graph-capturable: kernels only, no allocs/syncs) — 3 launches.
// ---------------------------------------------------------------------------
extern "C" void kernel_launch(void* const* d_in, const int* in_sizes, int n_in,
                              void* d_out, int out_size)
{
    const float* h_t    = (const float*)d_in[0];
    const float* price  = (const float*)d_in[1];
    const float* W_f1   = (const float*)d_in[2];
    const float* b_f1   = (const float*)d_in[3];
    const float* W_f2   = (const float*)d_in[4];
    const float* b_f2   = (const float*)d_in[5];
    const float* W_f3   = (const float*)d_in[6];
    const float* b_f3   = (const float*)d_in[7];
    const float* W_g1   = (const float*)d_in[8];
    const float* b_g1   = (const float*)d_in[9];
    const float* W_g2   = (const float*)d_in[10];
    const float* b_g2   = (const float*)d_in[11];
    const float* W_mu   = (const float*)d_in[12];
    const float* b_mu   = (const float*)d_in[13];
    const float* W_sig  = (const float*)d_in[14];
    const float* b_sig  = (const float*)d_in[15];

    float* out        = (float*)d_out;
    float* out_paths  = out;
    float* out_mu     = out + PATHS_ELEMS;
    float* out_sigma  = out + PATHS_ELEMS + BATCH;

    precompute_kernel<<<BATCH, 576>>>(h_t, W_f1, b_f1, W_g1, b_g1,
                                      W_mu, b_mu, W_sig, b_sig,
                                      out_mu, out_sigma);
    build_table_kernel<<<BATCH * HORIZON, 128>>>(W_f1, W_f2, b_f2, W_f3, b_f3,
                                                 W_g1, W_g2, b_g2);
    path_kernel<<<BN / 128, 64>>>(price, out_paths, W_f1, W_f2, b_f2,
                                  W_f3, b_f3, W_g1, W_g2, b_g2);
}

// round 12
// speedup vs baseline: 6.3530x; 1.0688x over previous
#include <cuda_runtime.h>
#include <cstdint>

// ---------------------------------------------------------------------------
// NeuralSDEHead: batch=8, d_model=512, hidden=64, n_paths=4096, horizon=128
// out = [paths (8*4096*128), mu (8), sigma (8)]  all fp32
// PRNG: JAX threefry2x32, jax_threefry_partitionable=True semantics.
//
// Pipeline: (1) precompute per-batch bases; (2) noise_kernel: all 4.2M
// normals in parallel -> g_z; (3) build f/g tables over a two-tier y-grid;
// (4) path kernel: sequential Euler steps = z load + cubic table lookup.
// ---------------------------------------------------------------------------

#define BATCH    8
#define DMODEL   512
#define HIDDEN   64
#define NPATHS   4096
#define HORIZON  128
#define BN       (BATCH * NPATHS)      /* 32768 */
#define PATHS_ELEMS (BN * HORIZON)     /* 4194304 */

#define GI       128                    /* inner grid points */
#define GO       256                    /* outer grid points */
#define TAB_G    (GI + GO)              /* 384 per (b,step) slice */
#define YI_MIN   (-32.0f)
#define YI_D     (0.5f)
#define YI_INV   (2.0f)
#define YO_MIN   (-384.0f)
#define YO_D     (3.0f)
#define YO_INV   (1.0f / 3.0f)

typedef unsigned long long ull;

// Scratch (allocation-free rule: __device__ globals)
__device__ float        g_base_f1[BATCH * HIDDEN];
__device__ float        g_base_g1[BATCH * HIDDEN];
__device__ float2       g_tab[BATCH * HORIZON * TAB_G];   // 3 MB: {f, g}
__device__ float        g_z[HORIZON * BN];                // 16.7 MB normals

// ---------------------------------------------------------------------------
// Threefry-2x32 (JAX-compatible, 20 rounds)
// ---------------------------------------------------------------------------
__device__ __forceinline__ void threefry2x32(unsigned int k0, unsigned int k1,
                                             unsigned int x0, unsigned int x1,
                                             unsigned int* o0, unsigned int* o1)
{
    unsigned int ks0 = k0, ks1 = k1, ks2 = k0 ^ k1 ^ 0x1BD11BDAu;
    x0 += ks0; x1 += ks1;
#define TF_ROUND(r) { x0 += x1; x1 = __funnelshift_l(x1, x1, (r)); x1 ^= x0; }
    TF_ROUND(13) TF_ROUND(15) TF_ROUND(26) TF_ROUND(6)
    x0 += ks1; x1 += ks2 + 1u;
    TF_ROUND(17) TF_ROUND(29) TF_ROUND(16) TF_ROUND(24)
    x0 += ks2; x1 += ks0 + 2u;
    TF_ROUND(13) TF_ROUND(15) TF_ROUND(26) TF_ROUND(6)
    x0 += ks0; x1 += ks1 + 3u;
    TF_ROUND(17) TF_ROUND(29) TF_ROUND(16) TF_ROUND(24)
    x0 += ks1; x1 += ks2 + 4u;
    TF_ROUND(13) TF_ROUND(15) TF_ROUND(26) TF_ROUND(6)
    x0 += ks2; x1 += ks0 + 5u;
#undef TF_ROUND
    *o0 = x0; *o1 = x1;
}

// XLA ErfInv32 (Giles polynomial)
__device__ __forceinline__ float erfinv_xla(float x)
{
    float w = -log1pf(-x * x);
    float p;
    if (w < 5.0f) {
        w = w - 2.5f;
        p = 2.81022636e-08f;
        p = fmaf(p, w, 3.43273939e-07f);
        p = fmaf(p, w, -3.5233877e-06f);
        p = fmaf(p, w, -4.39150654e-06f);
        p = fmaf(p, w, 0.00021858087f);
        p = fmaf(p, w, -0.00125372503f);
        p = fmaf(p, w, -0.00417768164f);
        p = fmaf(p, w, 0.246640727f);
        p = fmaf(p, w, 1.50140941f);
    } else {
        w = sqrtf(w) - 3.0f;
        p = -0.000200214257f;
        p = fmaf(p, w, 0.000100950558f);
        p = fmaf(p, w, 0.00134934322f);
        p = fmaf(p, w, -0.00367342844f);
        p = fmaf(p, w, 0.00573950773f);
        p = fmaf(p, w, -0.0076224613f);
        p = fmaf(p, w, 0.00943887047f);
        p = fmaf(p, w, 1.00167406f);
        p = fmaf(p, w, 2.83297682f);
    }
    return p * x;
}

__device__ __forceinline__ float silu_f(float x)
{
    return __fdividef(x, 1.0f + __expf(-x));
}

__device__ __forceinline__ float softplus_acc(float x)
{
    return fmaxf(x, 0.0f) + log1pf(__expf(-fabsf(x)));
}

// packed f32x2 helpers -------------------------------------------------------
__device__ __forceinline__ ull pack_dup(float x)
{
    unsigned int b = __float_as_uint(x);
    ull r;
    asm("mov.b64 %0, {%1, %2};" : "=l"(r) : "r"(b), "r"(b));
    return r;
}
__device__ __forceinline__ ull pack2(float lo, float hi)
{
    unsigned int a = __float_as_uint(lo), b = __float_as_uint(hi);
    ull r;
    asm("mov.b64 %0, {%1, %2};" : "=l"(r) : "r"(a), "r"(b));
    return r;
}
__device__ __forceinline__ float2 unpack2(ull v)
{
    unsigned int lo, hi;
    asm("mov.b64 {%0, %1}, %2;" : "=r"(lo), "=r"(hi) : "l"(v));
    return make_float2(__uint_as_float(lo), __uint_as_float(hi));
}
#define FMA2(acc, a, b) asm("fma.rn.f32x2 %0, %1, %2, %0;" : "+l"(acc) : "l"(a), "l"(b))

// ---------------------------------------------------------------------------
// Noise kernel: grid (BN/256, HORIZON) x 256. One normal per thread.
// Self-contained: computes the per-step split key in smem, then the
// partitionable random_bits = o0 ^ o1 with counts (0, row).
// ---------------------------------------------------------------------------
__global__ __launch_bounds__(256)
void noise_kernel()
{
    __shared__ unsigned int sk0, sk1;
    const int step = blockIdx.y;
    const int row  = blockIdx.x * 256 + threadIdx.x;

    if (threadIdx.x == 0) {
        unsigned int o0, o1;
        threefry2x32(0u, 42u, 0u, (unsigned int)step, &o0, &o1);
        sk0 = o0; sk1 = o1;
    }
    __syncthreads();

    unsigned int o0, o1;
    threefry2x32(sk0, sk1, 0u, (unsigned int)row, &o0, &o1);
    const unsigned int bits = o0 ^ o1;
    const float u01 = __uint_as_float((bits >> 9) | 0x3f800000u) - 1.0f;
    float u = fmaf(u01, 2.0f, -0.99999994039535522f);
    u = fmaxf(-0.99999994039535522f, u);
    g_z[step * BN + row] = 1.4142135381698608f * erfinv_xla(u);
}

// ---------------------------------------------------------------------------
// Setup kernel (grid=8, block=576): per-batch bases (4 threads/column,
// shuffle-combined) + warp-reduced mu/sigma.
// ---------------------------------------------------------------------------
__global__ __launch_bounds__(576)
void precompute_kernel(const float* __restrict__ h_t,
                       const float* __restrict__ W_f1, const float* __restrict__ b_f1,
                       const float* __restrict__ W_g1, const float* __restrict__ b_g1,
                       const float* __restrict__ W_mu, const float* __restrict__ b_mu,
                       const float* __restrict__ W_sig, const float* __restrict__ b_sig,
                       float* __restrict__ out_mu, float* __restrict__ out_sigma)
{
    const int b   = blockIdx.x;
    const int tid = threadIdx.x;
    const float* h = h_t + b * DMODEL;

    if (tid < 256) {
        const int col = tid >> 2;
        const int q   = tid & 3;
        float s = 0.0f;
        const int i0 = q * 128;
        #pragma unroll 8
        for (int i = i0; i < i0 + 128; ++i)
            s = fmaf(h[i], W_f1[i * HIDDEN + col], s);
        s += __shfl_xor_sync(0xffffffffu, s, 1);
        s += __shfl_xor_sync(0xffffffffu, s, 2);
        if (q == 0) g_base_f1[b * HIDDEN + col] = s + b_f1[col];
    } else if (tid < 512) {
        const int tt  = tid - 256;
        const int col = tt >> 2;
        const int q   = tt & 3;
        float s = 0.0f;
        const int i0 = q * 128;
        #pragma unroll 8
        for (int i = i0; i < i0 + 128; ++i)
            s = fmaf(h[i], W_g1[i * HIDDEN + col], s);
        s += __shfl_xor_sync(0xffffffffu, s, 1);
        s += __shfl_xor_sync(0xffffffffu, s, 2);
        if (q == 0) g_base_g1[b * HIDDEN + col] = s + b_g1[col];
    } else if (tid < 544) {
        const int lane = tid - 512;
        float s = 0.0f;
        #pragma unroll 4
        for (int i = lane; i < DMODEL; i += 32)
            s = fmaf(h[i], W_mu[i], s);
        #pragma unroll
        for (int off = 16; off > 0; off >>= 1)
            s += __shfl_xor_sync(0xffffffffu, s, off);
        if (lane == 0) out_mu[b] = s + b_mu[0];
    } else {
        const int lane = tid - 544;
        float s = 0.0f;
        #pragma unroll 4
        for (int i = lane; i < DMODEL; i += 32)
            s = fmaf(h[i], W_sig[i], s);
        #pragma unroll
        for (int off = 16; off > 0; off >>= 1)
            s += __shfl_xor_sync(0xffffffffu, s, off);
        if (lane == 0) {
            float v = s + b_sig[0];
            out_sigma[b] = fmaxf(v, 0.0f) + log1pf(expf(-fabsf(v))) + 1e-6f;
        }
    }
}

// ---------------------------------------------------------------------------
// Table build kernel: 1024 blocks (one per (b, step)) x 128 threads.
// Pass 1: dual eval (inner tid + outer tid) sharing W_f2 row loads.
// Pass 2: single eval (outer 128+tid).
// ---------------------------------------------------------------------------
__global__ __launch_bounds__(128, 2)
void build_table_kernel(const float* __restrict__ W_f1,
                        const float* __restrict__ W_f2, const float* __restrict__ b_f2,
                        const float* __restrict__ W_f3, const float* __restrict__ b_f3,
                        const float* __restrict__ W_g1,
                        const float* __restrict__ W_g2, const float* __restrict__ b_g2)
{
    __shared__ __align__(16) float sWf2[HIDDEN * HIDDEN];   // 16 KB
    __shared__ __align__(16) float sbf2[HIDDEN];
    __shared__ __align__(16) float4 sP[HIDDEN];  // {tbase_f, wy_f, tbase_g, wy_g}
    __shared__ float sWf3[HIDDEN], sWg2[HIDDEN];

    const int tid  = threadIdx.x;
    const int b    = blockIdx.x >> 7;       // 0..7
    const int step = blockIdx.x & 127;      // 0..127
    const float t  = (float)step;

    for (int i = tid; i < HIDDEN * HIDDEN; i += 128) sWf2[i] = W_f2[i];
    if (tid < HIDDEN) {
        sbf2[tid] = b_f2[tid];
        sWf3[tid] = W_f3[tid];
        sWg2[tid] = W_g2[tid];
        sP[tid] = make_float4(
            fmaf(t, W_f1[513 * HIDDEN + tid], g_base_f1[b * HIDDEN + tid]),
            W_f1[512 * HIDDEN + tid],
            fmaf(t, W_g1[513 * HIDDEN + tid], g_base_g1[b * HIDDEN + tid]),
            W_g1[512 * HIDDEN + tid]);
    }
    __syncthreads();

    const float bf3v = b_f3[0];
    const float bg2v = b_g2[0];
    float2* slice = g_tab + (size_t)(b * HORIZON + step) * TAB_G;

    // ---- pass 1: dual eval (inner yA, outer yB) ----
    {
        const float yA = YI_MIN + (float)tid * YI_D;
        const float yB = YO_MIN + (float)tid * YO_D;

        ull accA[HIDDEN / 2], accB[HIDDEN / 2];
        #pragma unroll
        for (int m = 0; m < HIDDEN / 2; ++m) {
            ull bb = pack2(sbf2[2 * m], sbf2[2 * m + 1]);
            accA[m] = bb;
            accB[m] = bb;
        }
        float gaA0 = bg2v, gaA1 = 0.0f, gaB0 = bg2v, gaB1 = 0.0f;

        #pragma unroll 2
        for (int i = 0; i < HIDDEN; ++i) {
            const float4 p4 = sP[i];
            const float hfA = silu_f(fmaf(yA, p4.y, p4.x));
            const float hgA = silu_f(fmaf(yA, p4.w, p4.z));
            const float hfB = silu_f(fmaf(yB, p4.y, p4.x));
            const float hgB = silu_f(fmaf(yB, p4.w, p4.z));
            const float gw = sWg2[i];
            if ((i & 1) == 0) { gaA0 = fmaf(hgA, gw, gaA0); gaB0 = fmaf(hgB, gw, gaB0); }
            else              { gaA1 = fmaf(hgA, gw, gaA1); gaB1 = fmaf(hgB, gw, gaB1); }

            const ull a2A = pack_dup(hfA);
            const ull a2B = pack_dup(hfB);
            const ulonglong2* wr = reinterpret_cast<const ulonglong2*>(&sWf2[i * HIDDEN]);
            #pragma unroll
            for (int q = 0; q < HIDDEN / 4; ++q) {
                ulonglong2 w = wr[q];                 // loaded once, used twice
                FMA2(accA[2 * q],     a2A, w.x);
                FMA2(accB[2 * q],     a2B, w.x);
                FMA2(accA[2 * q + 1], a2A, w.y);
                FMA2(accB[2 * q + 1], a2B, w.y);
            }
        }

        float fA0 = bf3v, fA1 = 0.0f, fB0 = bf3v, fB1 = 0.0f;
        #pragma unroll
        for (int m = 0; m < HIDDEN / 2; ++m) {
            float2 hA = unpack2(accA[m]);
            float2 hB = unpack2(accB[m]);
            const float w0 = sWf3[2 * m], w1 = sWf3[2 * m + 1];
            fA0 = fmaf(silu_f(hA.x), w0, fA0);
            fA1 = fmaf(silu_f(hA.y), w1, fA1);
            fB0 = fmaf(silu_f(hB.x), w0, fB0);
            fB1 = fmaf(silu_f(hB.y), w1, fB1);
        }
        slice[tid]      = make_float2(fA0 + fA1, softplus_acc(gaA0 + gaA1) + 1e-6f);
        slice[GI + tid] = make_float2(fB0 + fB1, softplus_acc(gaB0 + gaB1) + 1e-6f);
    }

    // ---- pass 2: single outer eval (idx = 128 + tid) ----
    {
        const float yB = YO_MIN + (float)(128 + tid) * YO_D;

        ull accB[HIDDEN / 2];
        #pragma unroll
        for (int m = 0; m < HIDDEN / 2; ++m)
            accB[m] = pack2(sbf2[2 * m], sbf2[2 * m + 1]);
        float gaB0 = bg2v, gaB1 = 0.0f;

        #pragma unroll 4
        for (int i = 0; i < HIDDEN; ++i) {
            const float4 p4 = sP[i];
            const float hfB = silu_f(fmaf(yB, p4.y, p4.x));
            const float hgB = silu_f(fmaf(yB, p4.w, p4.z));
            const float gw = sWg2[i];
            if ((i & 1) == 0) gaB0 = fmaf(hgB, gw, gaB0);
            else              gaB1 = fmaf(hgB, gw, gaB1);

            const ull a2B = pack_dup(hfB);
            const ulonglong2* wr = reinterpret_cast<const ulonglong2*>(&sWf2[i * HIDDEN]);
            #pragma unroll
            for (int q = 0; q < HIDDEN / 4; ++q) {
                ulonglong2 w = wr[q];
                FMA2(accB[2 * q],     a2B, w.x);
                FMA2(accB[2 * q + 1], a2B, w.y);
            }
        }

        float fB0 = bf3v, fB1 = 0.0f;
        #pragma unroll
        for (int m = 0; m < HIDDEN / 2; ++m) {
            float2 hB = unpack2(accB[m]);
            fB0 = fmaf(silu_f(hB.x), sWf3[2 * m],     fB0);
            fB1 = fmaf(silu_f(hB.y), sWf3[2 * m + 1], fB1);
        }
        slice[GI + 128 + tid] = make_float2(fB0 + fB1,
                                            softplus_acc(gaB0 + gaB1) + 1e-6f);
    }
}

// ---------------------------------------------------------------------------
// Exact fallback for y outside [-384, 384) (never expected to execute).
// ---------------------------------------------------------------------------
__device__ __noinline__ float2 exact_fg(float y, float t, int b,
                                        const float* W_f1,
                                        const float* W_f2, const float* b_f2,
                                        const float* W_f3, const float* b_f3,
                                        const float* W_g1,
                                        const float* W_g2, const float* b_g2)
{
    float acc[HIDDEN];
    for (int j = 0; j < HIDDEN; ++j) acc[j] = b_f2[j];
    float ga = b_g2[0];
    for (int i = 0; i < HIDDEN; ++i) {
        float xf = g_base_f1[b * HIDDEN + i]
                 + y * W_f1[512 * HIDDEN + i] + t * W_f1[513 * HIDDEN + i];
        float hf = silu_f(xf);
        float xg = g_base_g1[b * HIDDEN + i]
                 + y * W_g1[512 * HIDDEN + i] + t * W_g1[513 * HIDDEN + i];
        float hg = silu_f(xg);
        ga = fmaf(hg, W_g2[i], ga);
        for (int j = 0; j < HIDDEN; ++j)
            acc[j] = fmaf(hf, W_f2[i * HIDDEN + j], acc[j]);
    }
    float f = b_f3[0];
    for (int j = 0; j < HIDDEN; ++j) f = fmaf(silu_f(acc[j]), W_f3[j], f);
    float g = softplus_acc(ga) + 1e-6f;
    return make_float2(f, g);
}

// ---------------------------------------------------------------------------
// Table lookup (two-tier Catmull-Rom); returns {f, g}.
// ---------------------------------------------------------------------------
__device__ __forceinline__ float2 lookup_fg(const float2* __restrict__ slice,
                                            float y, float t, int b,
                                            const float* W_f1,
                                            const float* W_f2, const float* b_f2,
                                            const float* W_f3, const float* b_f3,
                                            const float* W_g1,
                                            const float* W_g2, const float* b_g2)
{
    float p = (y - YI_MIN) * YI_INV;
    int i1 = (int)floorf(p);
    const float2* base;
    float uu;
    bool hit;
    if (i1 >= 1 && i1 <= GI - 3) {
        uu = p - (float)i1;
        base = slice + i1;
        hit = true;
    } else {
        p = (y - YO_MIN) * YO_INV;
        i1 = (int)floorf(p);
        hit = (i1 >= 1 && i1 <= GO - 3);
        uu = p - (float)i1;
        base = slice + (GI + i1);
    }
    if (hit) {
        const float2 q0 = base[-1];
        const float2 q1 = base[0];
        const float2 q2 = base[1];
        const float2 q3 = base[2];
        const float u2 = uu * uu;
        const float u3 = u2 * uu;
        const float w0 = 0.5f * (-u3 + 2.0f * u2 - uu);
        const float w1 = 0.5f * (3.0f * u3 - 5.0f * u2 + 2.0f);
        const float w2 = 0.5f * (-3.0f * u3 + 4.0f * u2 + uu);
        const float w3 = 0.5f * (u3 - u2);
        return make_float2(w0 * q0.x + w1 * q1.x + w2 * q2.x + w3 * q3.x,
                           w0 * q0.y + w1 * q1.y + w2 * q2.y + w3 * q3.y);
    }
    return exact_fg(y, t, b, W_f1, W_f2, b_f2, W_f3, b_f3, W_g1, W_g2, b_g2);
}

// ---------------------------------------------------------------------------
// Path kernel: 256 blocks x 64 threads, TWO paths per thread (rows r and
// r+16384). Noise is pre-generated (g_z); per 4-step group the 8 z values
// load up-front (independent -> batched). Table slices L1-prefetched.
// ---------------------------------------------------------------------------
__global__ __launch_bounds__(64)
void path_kernel(const float* __restrict__ initial_price,
                 float* __restrict__ out_paths,
                 const float* __restrict__ W_f1,
                 const float* __restrict__ W_f2, const float* __restrict__ b_f2,
                 const float* __restrict__ W_f3, const float* __restrict__ b_f3,
                 const float* __restrict__ W_g1,
                 const float* __restrict__ W_g2, const float* __restrict__ b_g2)
{
    const int tid  = threadIdx.x;                 // 0..63
    const int rowA = blockIdx.x * 64 + tid;       // 0..16383
    const int rowB = rowA + BN / 2;               // 16384..32767
    const int bA   = rowA >> 12;                  // 0..3
    const int bB   = rowB >> 12;                  // 4..7

    float yA = logf(initial_price[bA]);
    float yB = logf(initial_price[bB]);
    float4* outA4 = reinterpret_cast<float4*>(out_paths + (size_t)rowA * HORIZON);
    float4* outB4 = reinterpret_cast<float4*>(out_paths + (size_t)rowB * HORIZON);

    const float2* tabA = g_tab + (size_t)bA * HORIZON * TAB_G;
    const float2* tabB = g_tab + (size_t)bB * HORIZON * TAB_G;
    const float* zA_p = g_z + rowA;
    const float* zB_p = g_z + rowB;

    // Per-thread prefetch assignment: warp 0 covers chain A's slice lines,
    // warp 1 covers chain B's. Slice = 384*8B = 3 KB = 24 x 128B lines.
    const int pf_line = tid & 31;
    const char* pf_base0 = (const char*)((tid < 32) ? tabA : tabB);

    if (pf_line < 24)
        asm volatile("prefetch.global.L1 [%0];"
                     :: "l"(pf_base0 + (size_t)pf_line * 128));

    #pragma unroll 1
    for (int s4 = 0; s4 < HORIZON / 4; ++s4) {
        // ---- batched z loads for 4 steps x 2 chains (independent) ----
        float zA[4], zB[4];
        #pragma unroll
        for (int kk = 0; kk < 4; ++kk) {
            zA[kk] = zA_p[(size_t)(s4 * 4 + kk) * BN];
            zB[kk] = zB_p[(size_t)(s4 * 4 + kk) * BN];
        }

        float oA[4], oB[4];
        #pragma unroll
        for (int kk = 0; kk < 4; ++kk) {
            const int step = s4 * 4 + kk;

            // ---- prefetch next step's table slices into L1 ----
            if (step + 1 < HORIZON && pf_line < 24)
                asm volatile("prefetch.global.L1 [%0];"
                             :: "l"(pf_base0 + (size_t)(step + 1) * (TAB_G * 8)
                                             + (size_t)pf_line * 128));

            // ---- table lookups (two independent load chains) ----
            const float2 fgA = lookup_fg(tabA + (size_t)step * TAB_G, yA, (float)step,
                                         bA, W_f1, W_f2, b_f2, W_f3, b_f3,
                                         W_g1, W_g2, b_g2);
            const float2 fgB = lookup_fg(tabB + (size_t)step * TAB_G, yB, (float)step,
                                         bB, W_f1, W_f2, b_f2, W_f3, b_f3,
                                         W_g1, W_g2, b_g2);

            // ---- Euler-Maruyama (dt = 1, sqrt_dt = 1) ----
            yA = (yA + fgA.x) + fgA.y * zA[kk];
            yB = (yB + fgB.x) + fgB.y * zB[kk];

            oA[kk] = __expf(fminf(fmaxf(yA, -20.0f), 20.0f));
            oB[kk] = __expf(fminf(fmaxf(yB, -20.0f), 20.0f));
        }
        outA4[s4] = make_float4(oA[0], oA[1], oA[2], oA[3]);
        outB4[s4] = make_float4(oB[0], oB[1], oB[2], oB[3]);
    }
}

// ---------------------------------------------------------------------------
// Launch (graph-capturable: kernels only, no allocs/syncs) — 4 launches.
// ---------------------------------------------------------------------------
extern "C" void kernel_launch(void* const* d_in, const int* in_sizes, int n_in,
                              void* d_out, int out_size)
{
    const float* h_t    = (const float*)d_in[0];
    const float* price  = (const float*)d_in[1];
    const float* W_f1   = (const float*)d_in[2];
    const float* b_f1   = (const float*)d_in[3];
    const float* W_f2   = (const float*)d_in[4];
    const float* b_f2   = (const float*)d_in[5];
    const float* W_f3   = (const float*)d_in[6];
    const float* b_f3   = (const float*)d_in[7];
    const float* W_g1   = (const float*)d_in[8];
    const float* b_g1   = (const float*)d_in[9];
    const float* W_g2   = (const float*)d_in[10];
    const float* b_g2   = (const float*)d_in[11];
    const float* W_mu   = (const float*)d_in[12];
    const float* b_mu   = (const float*)d_in[13];
    const float* W_sig  = (const float*)d_in[14];
    const float* b_sig  = (const float*)d_in[15];

    float* out        = (float*)d_out;
    float* out_paths  = out;
    float* out_mu     = out + PATHS_ELEMS;
    float* out_sigma  = out + PATHS_ELEMS + BATCH;

    precompute_kernel<<<BATCH, 576>>>(h_t, W_f1, b_f1, W_g1, b_g1,
                                      W_mu, b_mu, W_sig, b_sig,
                                      out_mu, out_sigma);
    {
        dim3 ngrid(BN / 256, HORIZON);
        noise_kernel<<<ngrid, 256>>>();
    }
    build_table_kernel<<<BATCH * HORIZON, 128>>>(W_f1, W_f2, b_f2, W_f3, b_f3,
                                                 W_g1, W_g2, b_g2);
    path_kernel<<<BN / 128, 64>>>(price, out_paths, W_f1, W_f2, b_f2,
                                  W_f3, b_f3, W_g1, W_g2, b_g2);
}

// round 13
// speedup vs baseline: 10.0735x; 1.5856x over previous
#include <cuda_runtime.h>
#include <cstdint>

// ---------------------------------------------------------------------------
// NeuralSDEHead: batch=8, d_model=512, hidden=64, n_paths=4096, horizon=128
// out = [paths (8*4096*128), mu (8), sigma (8)]  all fp32
// PRNG: JAX threefry2x32, jax_threefry_partitionable=True semantics.
//
// Pipeline: (1) precompute bases; (2) noise kernel -> g_z; (3) build f/g
// tables (two-tier y-grid, 192 pts); (4) path kernel: per-block smem-staged
// slices via cp.async ring, LDS cubic lookups.
// ---------------------------------------------------------------------------

#define BATCH    8
#define DMODEL   512
#define HIDDEN   64
#define NPATHS   4096
#define HORIZON  128
#define BN       (BATCH * NPATHS)      /* 32768 */
#define PATHS_ELEMS (BN * HORIZON)     /* 4194304 */

#define GI       64                     /* inner grid points */
#define GO       128                    /* outer grid points */
#define TAB_G    (GI + GO)              /* 192 per (b,step) slice */
#define SLICE_B  (TAB_G * 8)            /* 1536 bytes */
#define YI_MIN   (-32.0f)
#define YI_D     (1.0f)
#define YI_INV   (1.0f)
#define YO_MIN   (-384.0f)
#define YO_D     (6.0f)
#define YO_INV   (1.0f / 6.0f)

typedef unsigned long long ull;

// Scratch (allocation-free rule: __device__ globals)
__device__ float        g_base_f1[BATCH * HIDDEN];
__device__ float        g_base_g1[BATCH * HIDDEN];
__device__ __align__(16) float2 g_tab[BATCH * HORIZON * TAB_G];  // 1.5 MB
__device__ float        g_z[HORIZON * BN];                       // 16.7 MB

// ---------------------------------------------------------------------------
// Threefry-2x32 (JAX-compatible, 20 rounds)
// ---------------------------------------------------------------------------
__device__ __forceinline__ void threefry2x32(unsigned int k0, unsigned int k1,
                                             unsigned int x0, unsigned int x1,
                                             unsigned int* o0, unsigned int* o1)
{
    unsigned int ks0 = k0, ks1 = k1, ks2 = k0 ^ k1 ^ 0x1BD11BDAu;
    x0 += ks0; x1 += ks1;
#define TF_ROUND(r) { x0 += x1; x1 = __funnelshift_l(x1, x1, (r)); x1 ^= x0; }
    TF_ROUND(13) TF_ROUND(15) TF_ROUND(26) TF_ROUND(6)
    x0 += ks1; x1 += ks2 + 1u;
    TF_ROUND(17) TF_ROUND(29) TF_ROUND(16) TF_ROUND(24)
    x0 += ks2; x1 += ks0 + 2u;
    TF_ROUND(13) TF_ROUND(15) TF_ROUND(26) TF_ROUND(6)
    x0 += ks0; x1 += ks1 + 3u;
    TF_ROUND(17) TF_ROUND(29) TF_ROUND(16) TF_ROUND(24)
    x0 += ks1; x1 += ks2 + 4u;
    TF_ROUND(13) TF_ROUND(15) TF_ROUND(26) TF_ROUND(6)
    x0 += ks2; x1 += ks0 + 5u;
#undef TF_ROUND
    *o0 = x0; *o1 = x1;
}

// XLA ErfInv32 (Giles polynomial)
__device__ __forceinline__ float erfinv_xla(float x)
{
    float w = -log1pf(-x * x);
    float p;
    if (w < 5.0f) {
        w = w - 2.5f;
        p = 2.81022636e-08f;
        p = fmaf(p, w, 3.43273939e-07f);
        p = fmaf(p, w, -3.5233877e-06f);
        p = fmaf(p, w, -4.39150654e-06f);
        p = fmaf(p, w, 0.00021858087f);
        p = fmaf(p, w, -0.00125372503f);
        p = fmaf(p, w, -0.00417768164f);
        p = fmaf(p, w, 0.246640727f);
        p = fmaf(p, w, 1.50140941f);
    } else {
        w = sqrtf(w) - 3.0f;
        p = -0.000200214257f;
        p = fmaf(p, w, 0.000100950558f);
        p = fmaf(p, w, 0.00134934322f);
        p = fmaf(p, w, -0.00367342844f);
        p = fmaf(p, w, 0.00573950773f);
        p = fmaf(p, w, -0.0076224613f);
        p = fmaf(p, w, 0.00943887047f);
        p = fmaf(p, w, 1.00167406f);
        p = fmaf(p, w, 2.83297682f);
    }
    return p * x;
}

__device__ __forceinline__ float silu_f(float x)
{
    return __fdividef(x, 1.0f + __expf(-x));
}

__device__ __forceinline__ float softplus_acc(float x)
{
    return fmaxf(x, 0.0f) + log1pf(__expf(-fabsf(x)));
}

// packed f32x2 helpers -------------------------------------------------------
__device__ __forceinline__ ull pack_dup(float x)
{
    unsigned int b = __float_as_uint(x);
    ull r;
    asm("mov.b64 %0, {%1, %2};" : "=l"(r) : "r"(b), "r"(b));
    return r;
}
__device__ __forceinline__ ull pack2(float lo, float hi)
{
    unsigned int a = __float_as_uint(lo), b = __float_as_uint(hi);
    ull r;
    asm("mov.b64 %0, {%1, %2};" : "=l"(r) : "r"(a), "r"(b));
    return r;
}
__device__ __forceinline__ float2 unpack2(ull v)
{
    unsigned int lo, hi;
    asm("mov.b64 {%0, %1}, %2;" : "=r"(lo), "=r"(hi) : "l"(v));
    return make_float2(__uint_as_float(lo), __uint_as_float(hi));
}
#define FMA2(acc, a, b) asm("fma.rn.f32x2 %0, %1, %2, %0;" : "+l"(acc) : "l"(a), "l"(b))

__device__ __forceinline__ unsigned int smem_u32(const void* p)
{
    unsigned int a;
    asm("{ .reg .u64 t; cvta.to.shared.u64 t, %1; cvt.u32.u64 %0, t; }"
        : "=r"(a) : "l"(p));
    return a;
}

// grid point for table index 0..191: inner 0..63, outer 64..191
__device__ __forceinline__ float y_of_idx(int idx)
{
    return (idx < GI) ? (YI_MIN + (float)idx * YI_D)
                      : (YO_MIN + (float)(idx - GI) * YO_D);
}

// ---------------------------------------------------------------------------
// Noise kernel: grid (BN/256, HORIZON) x 256. One normal per thread.
// ---------------------------------------------------------------------------
__global__ __launch_bounds__(256)
void noise_kernel()
{
    __shared__ unsigned int sk0, sk1;
    const int step = blockIdx.y;
    const int row  = blockIdx.x * 256 + threadIdx.x;

    if (threadIdx.x == 0) {
        unsigned int o0, o1;
        threefry2x32(0u, 42u, 0u, (unsigned int)step, &o0, &o1);
        sk0 = o0; sk1 = o1;
    }
    __syncthreads();

    unsigned int o0, o1;
    threefry2x32(sk0, sk1, 0u, (unsigned int)row, &o0, &o1);
    const unsigned int bits = o0 ^ o1;
    const float u01 = __uint_as_float((bits >> 9) | 0x3f800000u) - 1.0f;
    float u = fmaf(u01, 2.0f, -0.99999994039535522f);
    u = fmaxf(-0.99999994039535522f, u);
    g_z[step * BN + row] = 1.4142135381698608f * erfinv_xla(u);
}

// ---------------------------------------------------------------------------
// Setup kernel (grid=8, block=576): bases + mu/sigma (unchanged from R12).
// ---------------------------------------------------------------------------
__global__ __launch_bounds__(576)
void precompute_kernel(const float* __restrict__ h_t,
                       const float* __restrict__ W_f1, const float* __restrict__ b_f1,
                       const float* __restrict__ W_g1, const float* __restrict__ b_g1,
                       const float* __restrict__ W_mu, const float* __restrict__ b_mu,
                       const float* __restrict__ W_sig, const float* __restrict__ b_sig,
                       float* __restrict__ out_mu, float* __restrict__ out_sigma)
{
    const int b   = blockIdx.x;
    const int tid = threadIdx.x;
    const float* h = h_t + b * DMODEL;

    if (tid < 256) {
        const int col = tid >> 2;
        const int q   = tid & 3;
        float s = 0.0f;
        const int i0 = q * 128;
        #pragma unroll 8
        for (int i = i0; i < i0 + 128; ++i)
            s = fmaf(h[i], W_f1[i * HIDDEN + col], s);
        s += __shfl_xor_sync(0xffffffffu, s, 1);
        s += __shfl_xor_sync(0xffffffffu, s, 2);
        if (q == 0) g_base_f1[b * HIDDEN + col] = s + b_f1[col];
    } else if (tid < 512) {
        const int tt  = tid - 256;
        const int col = tt >> 2;
        const int q   = tt & 3;
        float s = 0.0f;
        const int i0 = q * 128;
        #pragma unroll 8
        for (int i = i0; i < i0 + 128; ++i)
            s = fmaf(h[i], W_g1[i * HIDDEN + col], s);
        s += __shfl_xor_sync(0xffffffffu, s, 1);
        s += __shfl_xor_sync(0xffffffffu, s, 2);
        if (q == 0) g_base_g1[b * HIDDEN + col] = s + b_g1[col];
    } else if (tid < 544) {
        const int lane = tid - 512;
        float s = 0.0f;
        #pragma unroll 4
        for (int i = lane; i < DMODEL; i += 32)
            s = fmaf(h[i], W_mu[i], s);
        #pragma unroll
        for (int off = 16; off > 0; off >>= 1)
            s += __shfl_xor_sync(0xffffffffu, s, off);
        if (lane == 0) out_mu[b] = s + b_mu[0];
    } else {
        const int lane = tid - 544;
        float s = 0.0f;
        #pragma unroll 4
        for (int i = lane; i < DMODEL; i += 32)
            s = fmaf(h[i], W_sig[i], s);
        #pragma unroll
        for (int off = 16; off > 0; off >>= 1)
            s += __shfl_xor_sync(0xffffffffu, s, off);
        if (lane == 0) {
            float v = s + b_sig[0];
            out_sigma[b] = fmaxf(v, 0.0f) + log1pf(expf(-fabsf(v))) + 1e-6f;
        }
    }
}

// ---------------------------------------------------------------------------
// Table build kernel: 1024 blocks (one per (b, step)) x 96 threads.
// Dual eval per thread: point tid and point 96+tid (covers all 192 points),
// sharing W_f2 row loads (half LDS, double ILP).
// ---------------------------------------------------------------------------
__global__ __launch_bounds__(96, 2)
void build_table_kernel(const float* __restrict__ W_f1,
                        const float* __restrict__ W_f2, const float* __restrict__ b_f2,
                        const float* __restrict__ W_f3, const float* __restrict__ b_f3,
                        const float* __restrict__ W_g1,
                        const float* __restrict__ W_g2, const float* __restrict__ b_g2)
{
    __shared__ __align__(16) float sWf2[HIDDEN * HIDDEN];   // 16 KB
    __shared__ __align__(16) float sbf2[HIDDEN];
    __shared__ __align__(16) float4 sP[HIDDEN];  // {tbase_f, wy_f, tbase_g, wy_g}
    __shared__ float sWf3[HIDDEN], sWg2[HIDDEN];

    const int tid  = threadIdx.x;           // 0..95
    const int b    = blockIdx.x >> 7;       // 0..7
    const int step = blockIdx.x & 127;      // 0..127
    const float t  = (float)step;

    for (int i = tid; i < HIDDEN * HIDDEN; i += 96) sWf2[i] = W_f2[i];
    if (tid < HIDDEN) {
        sbf2[tid] = b_f2[tid];
        sWf3[tid] = W_f3[tid];
        sWg2[tid] = W_g2[tid];
        sP[tid] = make_float4(
            fmaf(t, W_f1[513 * HIDDEN + tid], g_base_f1[b * HIDDEN + tid]),
            W_f1[512 * HIDDEN + tid],
            fmaf(t, W_g1[513 * HIDDEN + tid], g_base_g1[b * HIDDEN + tid]),
            W_g1[512 * HIDDEN + tid]);
    }
    __syncthreads();

    const float bf3v = b_f3[0];
    const float bg2v = b_g2[0];
    float2* slice = g_tab + (size_t)(b * HORIZON + step) * TAB_G;

    const float yA = y_of_idx(tid);
    const float yB = y_of_idx(96 + tid);

    ull accA[HIDDEN / 2], accB[HIDDEN / 2];
    #pragma unroll
    for (int m = 0; m < HIDDEN / 2; ++m) {
        ull bb = pack2(sbf2[2 * m], sbf2[2 * m + 1]);
        accA[m] = bb;
        accB[m] = bb;
    }
    float gaA0 = bg2v, gaA1 = 0.0f, gaB0 = bg2v, gaB1 = 0.0f;

    #pragma unroll 2
    for (int i = 0; i < HIDDEN; ++i) {
        const float4 p4 = sP[i];
        const float hfA = silu_f(fmaf(yA, p4.y, p4.x));
        const float hgA = silu_f(fmaf(yA, p4.w, p4.z));
        const float hfB = silu_f(fmaf(yB, p4.y, p4.x));
        const float hgB = silu_f(fmaf(yB, p4.w, p4.z));
        const float gw = sWg2[i];
        if ((i & 1) == 0) { gaA0 = fmaf(hgA, gw, gaA0); gaB0 = fmaf(hgB, gw, gaB0); }
        else              { gaA1 = fmaf(hgA, gw, gaA1); gaB1 = fmaf(hgB, gw, gaB1); }

        const ull a2A = pack_dup(hfA);
        const ull a2B = pack_dup(hfB);
        const ulonglong2* wr = reinterpret_cast<const ulonglong2*>(&sWf2[i * HIDDEN]);
        #pragma unroll
        for (int q = 0; q < HIDDEN / 4; ++q) {
            ulonglong2 w = wr[q];                 // loaded once, used twice
            FMA2(accA[2 * q],     a2A, w.x);
            FMA2(accB[2 * q],     a2B, w.x);
            FMA2(accA[2 * q + 1], a2A, w.y);
            FMA2(accB[2 * q + 1], a2B, w.y);
        }
    }

    float fA0 = bf3v, fA1 = 0.0f, fB0 = bf3v, fB1 = 0.0f;
    #pragma unroll
    for (int m = 0; m < HIDDEN / 2; ++m) {
        float2 hA = unpack2(accA[m]);
        float2 hB = unpack2(accB[m]);
        const float w0 = sWf3[2 * m], w1 = sWf3[2 * m + 1];
        fA0 = fmaf(silu_f(hA.x), w0, fA0);
        fA1 = fmaf(silu_f(hA.y), w1, fA1);
        fB0 = fmaf(silu_f(hB.x), w0, fB0);
        fB1 = fmaf(silu_f(hB.y), w1, fB1);
    }
    slice[tid]      = make_float2(fA0 + fA1, softplus_acc(gaA0 + gaA1) + 1e-6f);
    slice[96 + tid] = make_float2(fB0 + fB1, softplus_acc(gaB0 + gaB1) + 1e-6f);
}

// ---------------------------------------------------------------------------
// Exact fallback for y outside [-384, 384) (never expected to execute).
// ---------------------------------------------------------------------------
__device__ __noinline__ float2 exact_fg(float y, float t, int b,
                                        const float* W_f1,
                                        const float* W_f2, const float* b_f2,
                                        const float* W_f3, const float* b_f3,
                                        const float* W_g1,
                                        const float* W_g2, const float* b_g2)
{
    float acc[HIDDEN];
    for (int j = 0; j < HIDDEN; ++j) acc[j] = b_f2[j];
    float ga = b_g2[0];
    for (int i = 0; i < HIDDEN; ++i) {
        float xf = g_base_f1[b * HIDDEN + i]
                 + y * W_f1[512 * HIDDEN + i] + t * W_f1[513 * HIDDEN + i];
        float hf = silu_f(xf);
        float xg = g_base_g1[b * HIDDEN + i]
                 + y * W_g1[512 * HIDDEN + i] + t * W_g1[513 * HIDDEN + i];
        float hg = silu_f(xg);
        ga = fmaf(hg, W_g2[i], ga);
        for (int j = 0; j < HIDDEN; ++j)
            acc[j] = fmaf(hf, W_f2[i * HIDDEN + j], acc[j]);
    }
    float f = b_f3[0];
    for (int j = 0; j < HIDDEN; ++j) f = fmaf(silu_f(acc[j]), W_f3[j], f);
    float g = softplus_acc(ga) + 1e-6f;
    return make_float2(f, g);
}

// ---------------------------------------------------------------------------
// Path kernel: 128 blocks x 128 threads, one batch per block, 2 chains per
// thread (rows base+tid, base+128+tid). Table slices staged into a 3-buffer
// smem ring with cp.async (distance 2); lookups are LDS cubic taps.
// ---------------------------------------------------------------------------
__global__ __launch_bounds__(128)
void path_kernel(const float* __restrict__ initial_price,
                 float* __restrict__ out_paths,
                 const float* __restrict__ W_f1,
                 const float* __restrict__ W_f2, const float* __restrict__ b_f2,
                 const float* __restrict__ W_f3, const float* __restrict__ b_f3,
                 const float* __restrict__ W_g1,
                 const float* __restrict__ W_g2, const float* __restrict__ b_g2)
{
    __shared__ __align__(16) float2 sbuf[3][TAB_G];   // 4.5 KB ring

    const int tid = threadIdx.x;                  // 0..127
    const int bid = blockIdx.x;                   // 0..127
    const int b   = bid >> 4;                     // 16 blocks per batch
    const int base = b * NPATHS + (bid & 15) * 256;
    const int rA = base + tid;
    const int rB = base + 128 + tid;

    float yA = logf(initial_price[b]);
    float yB = yA;
    float4* outA4 = reinterpret_cast<float4*>(out_paths + (size_t)rA * HORIZON);
    float4* outB4 = reinterpret_cast<float4*>(out_paths + (size_t)rB * HORIZON);
    const float* zA_p = g_z + rA;
    const float* zB_p = g_z + rB;

    const char* tb = (const char*)(g_tab + (size_t)b * HORIZON * TAB_G);
    const unsigned int sb = smem_u32(sbuf);

    // prologue: stage steps 0 and 1
    #pragma unroll
    for (int s = 0; s < 2; ++s) {
        if (tid < 96)
            asm volatile("cp.async.cg.shared.global [%0], [%1], 16;"
                         :: "r"(sb + s * SLICE_B + tid * 16),
                            "l"(tb + (size_t)s * SLICE_B + tid * 16));
        asm volatile("cp.async.commit_group;");
    }

    // z double-buffer (4-step groups)
    float zAc[4], zBc[4], zAn[4], zBn[4];
    #pragma unroll
    for (int k = 0; k < 4; ++k) {
        zAn[k] = zA_p[(size_t)k * BN];
        zBn[k] = zB_p[(size_t)k * BN];
    }

    #pragma unroll 1
    for (int g = 0; g < HORIZON / 4; ++g) {
        #pragma unroll
        for (int k = 0; k < 4; ++k) { zAc[k] = zAn[k]; zBc[k] = zBn[k]; }
        if (g + 1 < HORIZON / 4) {
            #pragma unroll
            for (int k = 0; k < 4; ++k) {
                zAn[k] = zA_p[(size_t)((g + 1) * 4 + k) * BN];
                zBn[k] = zB_p[(size_t)((g + 1) * 4 + k) * BN];
            }
        }

        float oA[4], oB[4];
        #pragma unroll
        for (int k = 0; k < 4; ++k) {
            const int s = g * 4 + k;

            // wait for slice s (<=1 newer group pending), make visible
            asm volatile("cp.async.wait_group 1;");
            __syncthreads();

            // stage slice s+2 into ring buffer (s+2)%3 (safe: consumers of
            // (s-1)%3 all passed the barrier above)
            if (s + 2 < HORIZON && tid < 96)
                asm volatile("cp.async.cg.shared.global [%0], [%1], 16;"
                             :: "r"(sb + ((s + 2) % 3) * SLICE_B + tid * 16),
                                "l"(tb + (size_t)(s + 2) * SLICE_B + tid * 16));
            asm volatile("cp.async.commit_group;");

            const float2* cur = sbuf[s % 3];

            // ---- chain A lookup (LDS cubic) ----
            float fA, gA2;
            {
                float p = (yA - YI_MIN) * YI_INV;
                int i1 = (int)floorf(p);
                int off; bool hit = true;
                if (i1 >= 1 && i1 <= GI - 3) { off = i1; }
                else {
                    p = (yA - YO_MIN) * YO_INV;
                    i1 = (int)floorf(p);
                    if (i1 >= 1 && i1 <= GO - 3) off = GI + i1;
                    else hit = false;
                }
                if (hit) {
                    const float uu = p - floorf(p);
                    const float2 q0 = cur[off - 1];
                    const float2 q1 = cur[off];
                    const float2 q2 = cur[off + 1];
                    const float2 q3 = cur[off + 2];
                    const float u2 = uu * uu;
                    const float u3 = u2 * uu;
                    const float w0 = 0.5f * (-u3 + 2.0f * u2 - uu);
                    const float w1 = 0.5f * (3.0f * u3 - 5.0f * u2 + 2.0f);
                    const float w2 = 0.5f * (-3.0f * u3 + 4.0f * u2 + uu);
                    const float w3 = 0.5f * (u3 - u2);
                    fA  = w0 * q0.x + w1 * q1.x + w2 * q2.x + w3 * q3.x;
                    gA2 = w0 * q0.y + w1 * q1.y + w2 * q2.y + w3 * q3.y;
                } else {
                    float2 fg = exact_fg(yA, (float)s, b, W_f1, W_f2, b_f2,
                                         W_f3, b_f3, W_g1, W_g2, b_g2);
                    fA = fg.x; gA2 = fg.y;
                }
            }
            // ---- chain B lookup ----
            float fB, gB2;
            {
                float p = (yB - YI_MIN) * YI_INV;
                int i1 = (int)floorf(p);
                int off; bool hit = true;
                if (i1 >= 1 && i1 <= GI - 3) { off = i1; }
                else {
                    p = (yB - YO_MIN) * YO_INV;
                    i1 = (int)floorf(p);
                    if (i1 >= 1 && i1 <= GO - 3) off = GI + i1;
                    else hit = false;
                }
                if (hit) {
                    const float uu = p - floorf(p);
                    const float2 q0 = cur[off - 1];
                    const float2 q1 = cur[off];
                    const float2 q2 = cur[off + 1];
                    const float2 q3 = cur[off + 2];
                    const float u2 = uu * uu;
                    const float u3 = u2 * uu;
                    const float w0 = 0.5f * (-u3 + 2.0f * u2 - uu);
                    const float w1 = 0.5f * (3.0f * u3 - 5.0f * u2 + 2.0f);
                    const float w2 = 0.5f * (-3.0f * u3 + 4.0f * u2 + uu);
                    const float w3 = 0.5f * (u3 - u2);
                    fB  = w0 * q0.x + w1 * q1.x + w2 * q2.x + w3 * q3.x;
                    gB2 = w0 * q0.y + w1 * q1.y + w2 * q2.y + w3 * q3.y;
                } else {
                    float2 fg = exact_fg(yB, (float)s, b, W_f1, W_f2, b_f2,
                                         W_f3, b_f3, W_g1, W_g2, b_g2);
                    fB = fg.x; gB2 = fg.y;
                }
            }

            // ---- Euler-Maruyama (dt = 1, sqrt_dt = 1) ----
            yA = (yA + fA) + gA2 * zAc[k];
            yB = (yB + fB) + gB2 * zBc[k];

            oA[k] = __expf(fminf(fmaxf(yA, -20.0f), 20.0f));
            oB[k] = __expf(fminf(fmaxf(yB, -20.0f), 20.0f));
        }
        outA4[g] = make_float4(oA[0], oA[1], oA[2], oA[3]);
        outB4[g] = make_float4(oB[0], oB[1], oB[2], oB[3]);
    }
}

// ---------------------------------------------------------------------------
// Launch (graph-capturable: kernels only, no allocs/syncs) — 4 launches.
// ---------------------------------------------------------------------------
extern "C" void kernel_launch(void* const* d_in, const int* in_sizes, int n_in,
                              void* d_out, int out_size)
{
    const float* h_t    = (const float*)d_in[0];
    const float* price  = (const float*)d_in[1];
    const float* W_f1   = (const float*)d_in[2];
    const float* b_f1   = (const float*)d_in[3];
    const float* W_f2   = (const float*)d_in[4];
    const float* b_f2   = (const float*)d_in[5];
    const float* W_f3   = (const float*)d_in[6];
    const float* b_f3   = (const float*)d_in[7];
    const float* W_g1   = (const float*)d_in[8];
    const float* b_g1   = (const float*)d_in[9];
    const float* W_g2   = (const float*)d_in[10];
    const float* b_g2   = (const float*)d_in[11];
    const float* W_mu   = (const float*)d_in[12];
    const float* b_mu   = (const float*)d_in[13];
    const float* W_sig  = (const float*)d_in[14];
    const float* b_sig  = (const float*)d_in[15];

    float* out        = (float*)d_out;
    float* out_paths  = out;
    float* out_mu     = out + PATHS_ELEMS;
    float* out_sigma  = out + PATHS_ELEMS + BATCH;

    precompute_kernel<<<BATCH, 576>>>(h_t, W_f1, b_f1, W_g1, b_g1,
                                      W_mu, b_mu, W_sig, b_sig,
                                      out_mu, out_sigma);
    {
        dim3 ngrid(BN / 256, HORIZON);
        noise_kernel<<<ngrid, 256>>>();
    }
    build_table_kernel<<<BATCH * HORIZON, 96>>>(W_f1, W_f2, b_f2, W_f3, b_f3,
                                                W_g1, W_g2, b_g2);
    path_kernel<<<128, 128>>>(price, out_paths, W_f1, W_f2, b_f2,
                              W_f3, b_f3, W_g1, W_g2, b_g2);
}

// round 14
// speedup vs baseline: 11.0737x; 1.0993x over previous
#include <cuda_runtime.h>
#include <cstdint>

// ---------------------------------------------------------------------------
// NeuralSDEHead: batch=8, d_model=512, hidden=64, n_paths=4096, horizon=128
// out = [paths (8*4096*128), mu (8), sigma (8)]  all fp32
// PRNG: JAX threefry2x32, jax_threefry_partitionable=True semantics.
//
// Pipeline:
//  (1) setup_kernel (fused): noise -> g_z  ||  per-batch bases  ||  mu/sigma
//  (2) build_table_kernel: f/g over two-tier y-grid (192 pts per (b,step))
//  (3) path_kernel: whole batch table (192 KB) staged in smem once; 128
//      barrier-free steps of LDS cubic lookups. 1 path per thread.
// ---------------------------------------------------------------------------

#define BATCH    8
#define DMODEL   512
#define HIDDEN   64
#define NPATHS   4096
#define HORIZON  128
#define BN       (BATCH * NPATHS)      /* 32768 */
#define PATHS_ELEMS (BN * HORIZON)     /* 4194304 */

#define GI       64                     /* inner grid points */
#define GO       128                    /* outer grid points */
#define TAB_G    (GI + GO)              /* 192 per (b,step) slice */
#define SLICE_B  (TAB_G * 8)            /* 1536 bytes */
#define TAB_SMEM (HORIZON * SLICE_B)    /* 196608 bytes = 192 KB */
#define YI_MIN   (-32.0f)
#define YI_D     (1.0f)
#define YI_INV   (1.0f)
#define YO_MIN   (-384.0f)
#define YO_D     (6.0f)
#define YO_INV   (1.0f / 6.0f)

#define NZ_BLOCKS 16384                 /* 128 steps x 128 row-blocks */
#define NB_BLOCKS 32                    /* 8 batches x 4 parts */

typedef unsigned long long ull;

// Scratch (allocation-free rule: __device__ globals)
__device__ float        g_base_f1[BATCH * HIDDEN];
__device__ float        g_base_g1[BATCH * HIDDEN];
__device__ __align__(16) float2 g_tab[BATCH * HORIZON * TAB_G];  // 1.5 MB
__device__ float        g_z[HORIZON * BN];                       // 16.7 MB

// ---------------------------------------------------------------------------
// Threefry-2x32 (JAX-compatible, 20 rounds)
// ---------------------------------------------------------------------------
__device__ __forceinline__ void threefry2x32(unsigned int k0, unsigned int k1,
                                             unsigned int x0, unsigned int x1,
                                             unsigned int* o0, unsigned int* o1)
{
    unsigned int ks0 = k0, ks1 = k1, ks2 = k0 ^ k1 ^ 0x1BD11BDAu;
    x0 += ks0; x1 += ks1;
#define TF_ROUND(r) { x0 += x1; x1 = __funnelshift_l(x1, x1, (r)); x1 ^= x0; }
    TF_ROUND(13) TF_ROUND(15) TF_ROUND(26) TF_ROUND(6)
    x0 += ks1; x1 += ks2 + 1u;
    TF_ROUND(17) TF_ROUND(29) TF_ROUND(16) TF_ROUND(24)
    x0 += ks2; x1 += ks0 + 2u;
    TF_ROUND(13) TF_ROUND(15) TF_ROUND(26) TF_ROUND(6)
    x0 += ks0; x1 += ks1 + 3u;
    TF_ROUND(17) TF_ROUND(29) TF_ROUND(16) TF_ROUND(24)
    x0 += ks1; x1 += ks2 + 4u;
    TF_ROUND(13) TF_ROUND(15) TF_ROUND(26) TF_ROUND(6)
    x0 += ks2; x1 += ks0 + 5u;
#undef TF_ROUND
    *o0 = x0; *o1 = x1;
}

// XLA ErfInv32 (Giles polynomial)
__device__ __forceinline__ float erfinv_xla(float x)
{
    float w = -log1pf(-x * x);
    float p;
    if (w < 5.0f) {
        w = w - 2.5f;
        p = 2.81022636e-08f;
        p = fmaf(p, w, 3.43273939e-07f);
        p = fmaf(p, w, -3.5233877e-06f);
        p = fmaf(p, w, -4.39150654e-06f);
        p = fmaf(p, w, 0.00021858087f);
        p = fmaf(p, w, -0.00125372503f);
        p = fmaf(p, w, -0.00417768164f);
        p = fmaf(p, w, 0.246640727f);
        p = fmaf(p, w, 1.50140941f);
    } else {
        w = sqrtf(w) - 3.0f;
        p = -0.000200214257f;
        p = fmaf(p, w, 0.000100950558f);
        p = fmaf(p, w, 0.00134934322f);
        p = fmaf(p, w, -0.00367342844f);
        p = fmaf(p, w, 0.00573950773f);
        p = fmaf(p, w, -0.0076224613f);
        p = fmaf(p, w, 0.00943887047f);
        p = fmaf(p, w, 1.00167406f);
        p = fmaf(p, w, 2.83297682f);
    }
    return p * x;
}

__device__ __forceinline__ float silu_f(float x)
{
    return __fdividef(x, 1.0f + __expf(-x));
}

__device__ __forceinline__ float softplus_acc(float x)
{
    return fmaxf(x, 0.0f) + log1pf(__expf(-fabsf(x)));
}

// packed f32x2 helpers -------------------------------------------------------
__device__ __forceinline__ ull pack_dup(float x)
{
    unsigned int b = __float_as_uint(x);
    ull r;
    asm("mov.b64 %0, {%1, %2};" : "=l"(r) : "r"(b), "r"(b));
    return r;
}
__device__ __forceinline__ ull pack2(float lo, float hi)
{
    unsigned int a = __float_as_uint(lo), b = __float_as_uint(hi);
    ull r;
    asm("mov.b64 %0, {%1, %2};" : "=l"(r) : "r"(a), "r"(b));
    return r;
}
__device__ __forceinline__ float2 unpack2(ull v)
{
    unsigned int lo, hi;
    asm("mov.b64 {%0, %1}, %2;" : "=r"(lo), "=r"(hi) : "l"(v));
    return make_float2(__uint_as_float(lo), __uint_as_float(hi));
}
#define FMA2(acc, a, b) asm("fma.rn.f32x2 %0, %1, %2, %0;" : "+l"(acc) : "l"(a), "l"(b))

__device__ __forceinline__ unsigned int smem_u32(const void* p)
{
    unsigned int a;
    asm("{ .reg .u64 t; cvta.to.shared.u64 t, %1; cvt.u32.u64 %0, t; }"
        : "=r"(a) : "l"(p));
    return a;
}

// grid point for table index 0..191: inner 0..63, outer 64..191
__device__ __forceinline__ float y_of_idx(int idx)
{
    return (idx < GI) ? (YI_MIN + (float)idx * YI_D)
                      : (YO_MIN + (float)(idx - GI) * YO_D);
}

// ---------------------------------------------------------------------------
// Fused setup kernel: 16417 blocks x 256 threads.
//  blocks [0, 16384): noise -> g_z      (step = n>>7, rows = (n&127)*256+tid)
//  blocks [16384, 16416): per-batch bases (8 threads per column)
//  block 16416: mu/sigma (warp w = batch w)
// ---------------------------------------------------------------------------
__global__ __launch_bounds__(256)
void setup_kernel(const float* __restrict__ h_t,
                  const float* __restrict__ W_f1, const float* __restrict__ b_f1,
                  const float* __restrict__ W_g1, const float* __restrict__ b_g1,
                  const float* __restrict__ W_mu, const float* __restrict__ b_mu,
                  const float* __restrict__ W_sig, const float* __restrict__ b_sig,
                  float* __restrict__ out_mu, float* __restrict__ out_sigma)
{
    const int n   = blockIdx.x;
    const int tid = threadIdx.x;

    if (n < NZ_BLOCKS) {
        // ---- noise ----
        __shared__ unsigned int sk0, sk1;
        const int step = n >> 7;
        const int row  = (n & 127) * 256 + tid;
        if (tid == 0) {
            unsigned int o0, o1;
            threefry2x32(0u, 42u, 0u, (unsigned int)step, &o0, &o1);
            sk0 = o0; sk1 = o1;
        }
        __syncthreads();
        unsigned int o0, o1;
        threefry2x32(sk0, sk1, 0u, (unsigned int)row, &o0, &o1);
        const unsigned int bits = o0 ^ o1;
        const float u01 = __uint_as_float((bits >> 9) | 0x3f800000u) - 1.0f;
        float u = fmaf(u01, 2.0f, -0.99999994039535522f);
        u = fmaxf(-0.99999994039535522f, u);
        g_z[step * BN + row] = 1.4142135381698608f * erfinv_xla(u);
    } else if (n < NZ_BLOCKS + NB_BLOCKS) {
        // ---- bases: 8 threads/column, 32 columns per block ----
        const int idx  = n - NZ_BLOCKS;        // 0..31
        const int b    = idx >> 2;             // batch
        const int part = idx & 3;              // 0,1: f cols; 2,3: g cols
        const float* h = h_t + b * DMODEL;
        const int col  = ((part & 1) * 32) + (tid >> 3);   // 0..63
        const int q    = tid & 7;
        const int i0   = q * 64;
        if (part < 2) {
            float s = 0.0f;
            #pragma unroll 8
            for (int i = i0; i < i0 + 64; ++i)
                s = fmaf(h[i], W_f1[i * HIDDEN + col], s);
            s += __shfl_xor_sync(0xffffffffu, s, 1);
            s += __shfl_xor_sync(0xffffffffu, s, 2);
            s += __shfl_xor_sync(0xffffffffu, s, 4);
            if (q == 0) g_base_f1[b * HIDDEN + col] = s + b_f1[col];
        } else {
            float s = 0.0f;
            #pragma unroll 8
            for (int i = i0; i < i0 + 64; ++i)
                s = fmaf(h[i], W_g1[i * HIDDEN + col], s);
            s += __shfl_xor_sync(0xffffffffu, s, 1);
            s += __shfl_xor_sync(0xffffffffu, s, 2);
            s += __shfl_xor_sync(0xffffffffu, s, 4);
            if (q == 0) g_base_g1[b * HIDDEN + col] = s + b_g1[col];
        }
    } else {
        // ---- mu/sigma: warp w = batch w ----
        const int w    = tid >> 5;             // 0..7
        const int lane = tid & 31;
        const float* h = h_t + w * DMODEL;
        float sm = 0.0f, ss = 0.0f;
        #pragma unroll 4
        for (int i = lane; i < DMODEL; i += 32) {
            float hv = h[i];
            sm = fmaf(hv, W_mu[i], sm);
            ss = fmaf(hv, W_sig[i], ss);
        }
        #pragma unroll
        for (int off = 16; off > 0; off >>= 1) {
            sm += __shfl_xor_sync(0xffffffffu, sm, off);
            ss += __shfl_xor_sync(0xffffffffu, ss, off);
        }
        if (lane == 0) {
            out_mu[w] = sm + b_mu[0];
            float v = ss + b_sig[0];
            out_sigma[w] = fmaxf(v, 0.0f) + log1pf(expf(-fabsf(v))) + 1e-6f;
        }
    }
}

// ---------------------------------------------------------------------------
// Table build kernel: 1024 blocks (one per (b, step)) x 96 threads.
// Dual eval per thread: point tid and point 96+tid (covers all 192 points),
// sharing W_f2 row loads (half LDS, double ILP).
// ---------------------------------------------------------------------------
__global__ __launch_bounds__(96, 2)
void build_table_kernel(const float* __restrict__ W_f1,
                        const float* __restrict__ W_f2, const float* __restrict__ b_f2,
                        const float* __restrict__ W_f3, const float* __restrict__ b_f3,
                        const float* __restrict__ W_g1,
                        const float* __restrict__ W_g2, const float* __restrict__ b_g2)
{
    __shared__ __align__(16) float sWf2[HIDDEN * HIDDEN];   // 16 KB
    __shared__ __align__(16) float sbf2[HIDDEN];
    __shared__ __align__(16) float4 sP[HIDDEN];  // {tbase_f, wy_f, tbase_g, wy_g}
    __shared__ float sWf3[HIDDEN], sWg2[HIDDEN];

    const int tid  = threadIdx.x;           // 0..95
    const int b    = blockIdx.x >> 7;       // 0..7
    const int step = blockIdx.x & 127;      // 0..127
    const float t  = (float)step;

    for (int i = tid; i < HIDDEN * HIDDEN; i += 96) sWf2[i] = W_f2[i];
    if (tid < HIDDEN) {
        sbf2[tid] = b_f2[tid];
        sWf3[tid] = W_f3[tid];
        sWg2[tid] = W_g2[tid];
        sP[tid] = make_float4(
            fmaf(t, W_f1[513 * HIDDEN + tid], g_base_f1[b * HIDDEN + tid]),
            W_f1[512 * HIDDEN + tid],
            fmaf(t, W_g1[513 * HIDDEN + tid], g_base_g1[b * HIDDEN + tid]),
            W_g1[512 * HIDDEN + tid]);
    }
    __syncthreads();

    const float bf3v = b_f3[0];
    const float bg2v = b_g2[0];
    float2* slice = g_tab + (size_t)(b * HORIZON + step) * TAB_G;

    const float yA = y_of_idx(tid);
    const float yB = y_of_idx(96 + tid);

    ull accA[HIDDEN / 2], accB[HIDDEN / 2];
    #pragma unroll
    for (int m = 0; m < HIDDEN / 2; ++m) {
        ull bb = pack2(sbf2[2 * m], sbf2[2 * m + 1]);
        accA[m] = bb;
        accB[m] = bb;
    }
    float gaA0 = bg2v, gaA1 = 0.0f, gaB0 = bg2v, gaB1 = 0.0f;

    #pragma unroll 2
    for (int i = 0; i < HIDDEN; ++i) {
        const float4 p4 = sP[i];
        const float hfA = silu_f(fmaf(yA, p4.y, p4.x));
        const float hgA = silu_f(fmaf(yA, p4.w, p4.z));
        const float hfB = silu_f(fmaf(yB, p4.y, p4.x));
        const float hgB = silu_f(fmaf(yB, p4.w, p4.z));
        const float gw = sWg2[i];
        if ((i & 1) == 0) { gaA0 = fmaf(hgA, gw, gaA0); gaB0 = fmaf(hgB, gw, gaB0); }
        else              { gaA1 = fmaf(hgA, gw, gaA1); gaB1 = fmaf(hgB, gw, gaB1); }

        const ull a2A = pack_dup(hfA);
        const ull a2B = pack_dup(hfB);
        const ulonglong2* wr = reinterpret_cast<const ulonglong2*>(&sWf2[i * HIDDEN]);
        #pragma unroll
        for (int q = 0; q < HIDDEN / 4; ++q) {
            ulonglong2 w = wr[q];                 // loaded once, used twice
            FMA2(accA[2 * q],     a2A, w.x);
            FMA2(accB[2 * q],     a2B, w.x);
            FMA2(accA[2 * q + 1], a2A, w.y);
            FMA2(accB[2 * q + 1], a2B, w.y);
        }
    }

    float fA0 = bf3v, fA1 = 0.0f, fB0 = bf3v, fB1 = 0.0f;
    #pragma unroll
    for (int m = 0; m < HIDDEN / 2; ++m) {
        float2 hA = unpack2(accA[m]);
        float2 hB = unpack2(accB[m]);
        const float w0 = sWf3[2 * m], w1 = sWf3[2 * m + 1];
        fA0 = fmaf(silu_f(hA.x), w0, fA0);
        fA1 = fmaf(silu_f(hA.y), w1, fA1);
        fB0 = fmaf(silu_f(hB.x), w0, fB0);
        fB1 = fmaf(silu_f(hB.y), w1, fB1);
    }
    slice[tid]      = make_float2(fA0 + fA1, softplus_acc(gaA0 + gaA1) + 1e-6f);
    slice[96 + tid] = make_float2(fB0 + fB1, softplus_acc(gaB0 + gaB1) + 1e-6f);
}

// ---------------------------------------------------------------------------
// Exact fallback for y outside [-384, 384) (never expected to execute).
// ---------------------------------------------------------------------------
__device__ __noinline__ float2 exact_fg(float y, float t, int b,
                                        const float* W_f1,
                                        const float* W_f2, const float* b_f2,
                                        const float* W_f3, const float* b_f3,
                                        const float* W_g1,
                                        const float* W_g2, const float* b_g2)
{
    float acc[HIDDEN];
    for (int j = 0; j < HIDDEN; ++j) acc[j] = b_f2[j];
    float ga = b_g2[0];
    for (int i = 0; i < HIDDEN; ++i) {
        float xf = g_base_f1[b * HIDDEN + i]
                 + y * W_f1[512 * HIDDEN + i] + t * W_f1[513 * HIDDEN + i];
        float hf = silu_f(xf);
        float xg = g_base_g1[b * HIDDEN + i]
                 + y * W_g1[512 * HIDDEN + i] + t * W_g1[513 * HIDDEN + i];
        float hg = silu_f(xg);
        ga = fmaf(hg, W_g2[i], ga);
        for (int j = 0; j < HIDDEN; ++j)
            acc[j] = fmaf(hf, W_f2[i * HIDDEN + j], acc[j]);
    }
    float f = b_f3[0];
    for (int j = 0; j < HIDDEN; ++j) f = fmaf(silu_f(acc[j]), W_f3[j], f);
    float g = softplus_acc(ga) + 1e-6f;
    return make_float2(f, g);
}

// ---------------------------------------------------------------------------
// Path kernel: 128 blocks x 256 threads, one batch per block, 1 path per
// thread. The ENTIRE 128-step table for the batch (192 KB) is staged into
// dynamic smem once; the step loop is barrier-free LDS cubic lookups.
// ---------------------------------------------------------------------------
extern __shared__ __align__(16) float2 stab[];   // HORIZON * TAB_G entries

__global__ __launch_bounds__(256)
void path_kernel(const float* __restrict__ initial_price,
                 float* __restrict__ out_paths,
                 const float* __restrict__ W_f1,
                 const float* __restrict__ W_f2, const float* __restrict__ b_f2,
                 const float* __restrict__ W_f3, const float* __restrict__ b_f3,
                 const float* __restrict__ W_g1,
                 const float* __restrict__ W_g2, const float* __restrict__ b_g2)
{
    const int tid = threadIdx.x;                  // 0..255
    const int bid = blockIdx.x;                   // 0..127
    const int b   = bid >> 4;                     // 16 blocks per batch
    const int row = b * NPATHS + (bid & 15) * 256 + tid;

    // ---- prologue: stage the whole batch table (192 KB) via cp.async ----
    {
        const char* src = (const char*)(g_tab + (size_t)b * HORIZON * TAB_G);
        const unsigned int dst = smem_u32(stab);
        #pragma unroll
        for (int k = 0; k < TAB_SMEM / (256 * 16); ++k) {   // 48 iters
            const int off = (k * 256 + tid) * 16;
            asm volatile("cp.async.cg.shared.global [%0], [%1], 16;"
                         :: "r"(dst + off), "l"(src + off));
        }
        asm volatile("cp.async.commit_group;");
    }

    float y = logf(initial_price[b]);
    float4* outp4 = reinterpret_cast<float4*>(out_paths + (size_t)row * HORIZON);
    const float* z_p = g_z + row;

    asm volatile("cp.async.wait_group 0;");
    __syncthreads();

    #pragma unroll 1
    for (int g = 0; g < HORIZON / 4; ++g) {
        // batched z loads (independent, coalesced)
        float zc[4];
        #pragma unroll
        for (int k = 0; k < 4; ++k)
            zc[k] = z_p[(size_t)(g * 4 + k) * BN];

        float o[4];
        #pragma unroll
        for (int k = 0; k < 4; ++k) {
            const int s = g * 4 + k;
            const float2* cur = stab + s * TAB_G;

            float f, gg;
            float p = (y - YI_MIN) * YI_INV;
            int i1 = (int)floorf(p);
            int off; bool hit = true;
            if (i1 >= 1 && i1 <= GI - 3) { off = i1; }
            else {
                p = (y - YO_MIN) * YO_INV;
                i1 = (int)floorf(p);
                if (i1 >= 1 && i1 <= GO - 3) off = GI + i1;
                else hit = false;
            }
            if (hit) {
                const float uu = p - floorf(p);
                const float2 q0 = cur[off - 1];
                const float2 q1 = cur[off];
                const float2 q2 = cur[off + 1];
                const float2 q3 = cur[off + 2];
                const float u2 = uu * uu;
                const float u3 = u2 * uu;
                const float w0 = 0.5f * (-u3 + 2.0f * u2 - uu);
                const float w1 = 0.5f * (3.0f * u3 - 5.0f * u2 + 2.0f);
                const float w2 = 0.5f * (-3.0f * u3 + 4.0f * u2 + uu);
                const float w3 = 0.5f * (u3 - u2);
                f  = w0 * q0.x + w1 * q1.x + w2 * q2.x + w3 * q3.x;
                gg = w0 * q0.y + w1 * q1.y + w2 * q2.y + w3 * q3.y;
            } else {
                float2 fg = exact_fg(y, (float)s, b, W_f1, W_f2, b_f2,
                                     W_f3, b_f3, W_g1, W_g2, b_g2);
                f = fg.x; gg = fg.y;
            }

            // Euler-Maruyama (dt = 1, sqrt_dt = 1)
            y = (y + f) + gg * zc[k];
            o[k] = __expf(fminf(fmaxf(y, -20.0f), 20.0f));
        }
        outp4[g] = make_float4(o[0], o[1], o[2], o[3]);
    }
}

// ---------------------------------------------------------------------------
// Launch (graph-capturable: kernels only, no allocs/syncs) — 3 launches.
// ---------------------------------------------------------------------------
extern "C" void kernel_launch(void* const* d_in, const int* in_sizes, int n_in,
                              void* d_out, int out_size)
{
    const float* h_t    = (const float*)d_in[0];
    const float* price  = (const float*)d_in[1];
    const float* W_f1   = (const float*)d_in[2];
    const float* b_f1   = (const float*)d_in[3];
    const float* W_f2   = (const float*)d_in[4];
    const float* b_f2   = (const float*)d_in[5];
    const float* W_f3   = (const float*)d_in[6];
    const float* b_f3   = (const float*)d_in[7];
    const float* W_g1   = (const float*)d_in[8];
    const float* b_g1   = (const float*)d_in[9];
    const float* W_g2   = (const float*)d_in[10];
    const float* b_g2   = (const float*)d_in[11];
    const float* W_mu   = (const float*)d_in[12];
    const float* b_mu   = (const float*)d_in[13];
    const float* W_sig  = (const float*)d_in[14];
    const float* b_sig  = (const float*)d_in[15];

    float* out        = (float*)d_out;
    float* out_paths  = out;
    float* out_mu     = out + PATHS_ELEMS;
    float* out_sigma  = out + PATHS_ELEMS + BATCH;

    // opt-in to 192 KB dynamic smem for the path kernel (idempotent)
    cudaFuncSetAttribute(path_kernel,
                         cudaFuncAttributeMaxDynamicSharedMemorySize, TAB_SMEM);

    setup_kernel<<<NZ_BLOCKS + NB_BLOCKS + 1, 256>>>(h_t, W_f1, b_f1, W_g1, b_g1,
                                                     W_mu, b_mu, W_sig, b_sig,
                                                     out_mu, out_sigma);
    build_table_kernel<<<BATCH * HORIZON, 96>>>(W_f1, W_f2, b_f2, W_f3, b_f3,
                                                W_g1, W_g2, b_g2);
    path_kernel<<<128, 256, TAB_SMEM>>>(price, out_paths, W_f1, W_f2, b_f2,
                                        W_f3, b_f3, W_g1, W_g2, b_g2);
}

// round 15
// speedup vs baseline: 13.8769x; 1.2531x over previous
#include <cuda_runtime.h>
#include <cstdint>

// ---------------------------------------------------------------------------
// NeuralSDEHead: batch=8, d_model=512, hidden=64, n_paths=4096, horizon=128
// out = [paths (8*4096*128), mu (8), sigma (8)]  all fp32
// PRNG: JAX threefry2x32, jax_threefry_partitionable=True semantics.
//
// Pipeline:
//  (1) setup_kernel: per-batch bases + mu/sigma (33 blocks)
//  (2) build_table_kernel: f/g over two-tier y-grid (96 pts per (b,step))
//  (3) path_kernel: whole batch table (96 KB) staged in smem once; inline
//      one-step-ahead threefry noise; barrier-free LDS cubic step loop.
// ---------------------------------------------------------------------------

#define BATCH    8
#define DMODEL   512
#define HIDDEN   64
#define NPATHS   4096
#define HORIZON  128
#define BN       (BATCH * NPATHS)      /* 32768 */
#define PATHS_ELEMS (BN * HORIZON)     /* 4194304 */

#define GI       32                     /* inner grid points (d=2)  */
#define GO       64                     /* outer grid points (d=12) */
#define TAB_G    (GI + GO)              /* 96 per (b,step) slice */
#define SLICE_B  (TAB_G * 8)            /* 768 bytes */
#define TAB_SMEM (HORIZON * SLICE_B)    /* 98304 bytes = 96 KB */
#define YI_MIN   (-32.0f)
#define YI_D     (2.0f)
#define YI_INV   (0.5f)
#define YO_MIN   (-384.0f)
#define YO_D     (12.0f)
#define YO_INV   (1.0f / 12.0f)

typedef unsigned long long ull;

// Scratch (allocation-free rule: __device__ globals)
__device__ float        g_base_f1[BATCH * HIDDEN];
__device__ float        g_base_g1[BATCH * HIDDEN];
__device__ __align__(16) float2 g_tab[BATCH * HORIZON * TAB_G];  // 768 KB

// ---------------------------------------------------------------------------
// Threefry-2x32 (JAX-compatible, 20 rounds)
// ---------------------------------------------------------------------------
__device__ __forceinline__ void threefry2x32(unsigned int k0, unsigned int k1,
                                             unsigned int x0, unsigned int x1,
                                             unsigned int* o0, unsigned int* o1)
{
    unsigned int ks0 = k0, ks1 = k1, ks2 = k0 ^ k1 ^ 0x1BD11BDAu;
    x0 += ks0; x1 += ks1;
#define TF_ROUND(r) { x0 += x1; x1 = __funnelshift_l(x1, x1, (r)); x1 ^= x0; }
    TF_ROUND(13) TF_ROUND(15) TF_ROUND(26) TF_ROUND(6)
    x0 += ks1; x1 += ks2 + 1u;
    TF_ROUND(17) TF_ROUND(29) TF_ROUND(16) TF_ROUND(24)
    x0 += ks2; x1 += ks0 + 2u;
    TF_ROUND(13) TF_ROUND(15) TF_ROUND(26) TF_ROUND(6)
    x0 += ks0; x1 += ks1 + 3u;
    TF_ROUND(17) TF_ROUND(29) TF_ROUND(16) TF_ROUND(24)
    x0 += ks1; x1 += ks2 + 4u;
    TF_ROUND(13) TF_ROUND(15) TF_ROUND(26) TF_ROUND(6)
    x0 += ks2; x1 += ks0 + 5u;
#undef TF_ROUND
    *o0 = x0; *o1 = x1;
}

// XLA ErfInv32 (Giles polynomial)
__device__ __forceinline__ float erfinv_xla(float x)
{
    float w = -log1pf(-x * x);
    float p;
    if (w < 5.0f) {
        w = w - 2.5f;
        p = 2.81022636e-08f;
        p = fmaf(p, w, 3.43273939e-07f);
        p = fmaf(p, w, -3.5233877e-06f);
        p = fmaf(p, w, -4.39150654e-06f);
        p = fmaf(p, w, 0.00021858087f);
        p = fmaf(p, w, -0.00125372503f);
        p = fmaf(p, w, -0.00417768164f);
        p = fmaf(p, w, 0.246640727f);
        p = fmaf(p, w, 1.50140941f);
    } else {
        w = sqrtf(w) - 3.0f;
        p = -0.000200214257f;
        p = fmaf(p, w, 0.000100950558f);
        p = fmaf(p, w, 0.00134934322f);
        p = fmaf(p, w, -0.00367342844f);
        p = fmaf(p, w, 0.00573950773f);
        p = fmaf(p, w, -0.0076224613f);
        p = fmaf(p, w, 0.00943887047f);
        p = fmaf(p, w, 1.00167406f);
        p = fmaf(p, w, 2.83297682f);
    }
    return p * x;
}

__device__ __forceinline__ float silu_f(float x)
{
    return __fdividef(x, 1.0f + __expf(-x));
}

__device__ __forceinline__ float softplus_acc(float x)
{
    return fmaxf(x, 0.0f) + log1pf(__expf(-fabsf(x)));
}

// packed f32x2 helpers -------------------------------------------------------
__device__ __forceinline__ ull pack_dup(float x)
{
    unsigned int b = __float_as_uint(x);
    ull r;
    asm("mov.b64 %0, {%1, %2};" : "=l"(r) : "r"(b), "r"(b));
    return r;
}
__device__ __forceinline__ ull pack2(float lo, float hi)
{
    unsigned int a = __float_as_uint(lo), b = __float_as_uint(hi);
    ull r;
    asm("mov.b64 %0, {%1, %2};" : "=l"(r) : "r"(a), "r"(b));
    return r;
}
__device__ __forceinline__ float2 unpack2(ull v)
{
    unsigned int lo, hi;
    asm("mov.b64 {%0, %1}, %2;" : "=r"(lo), "=r"(hi) : "l"(v));
    return make_float2(__uint_as_float(lo), __uint_as_float(hi));
}
#define FMA2(acc, a, b) asm("fma.rn.f32x2 %0, %1, %2, %0;" : "+l"(acc) : "l"(a), "l"(b))

__device__ __forceinline__ unsigned int smem_u32(const void* p)
{
    unsigned int a;
    asm("{ .reg .u64 t; cvta.to.shared.u64 t, %1; cvt.u32.u64 %0, t; }"
        : "=r"(a) : "l"(p));
    return a;
}

// grid point for table index 0..95: inner 0..31, outer 32..95
__device__ __forceinline__ float y_of_idx(int idx)
{
    return (idx < GI) ? (YI_MIN + (float)idx * YI_D)
                      : (YO_MIN + (float)(idx - GI) * YO_D);
}

// ---------------------------------------------------------------------------
// Setup kernel: 33 blocks x 256 threads.
//  blocks [0, 32): per-batch bases (8 threads per column)
//  block 32: mu/sigma (warp w = batch w)
// ---------------------------------------------------------------------------
__global__ __launch_bounds__(256)
void setup_kernel(const float* __restrict__ h_t,
                  const float* __restrict__ W_f1, const float* __restrict__ b_f1,
                  const float* __restrict__ W_g1, const float* __restrict__ b_g1,
                  const float* __restrict__ W_mu, const float* __restrict__ b_mu,
                  const float* __restrict__ W_sig, const float* __restrict__ b_sig,
                  float* __restrict__ out_mu, float* __restrict__ out_sigma)
{
    const int n   = blockIdx.x;
    const int tid = threadIdx.x;

    if (n < 32) {
        // ---- bases: 8 threads/column, 32 columns per block ----
        const int b    = n >> 2;               // batch
        const int part = n & 3;                // 0,1: f cols; 2,3: g cols
        const float* h = h_t + b * DMODEL;
        const int col  = ((part & 1) * 32) + (tid >> 3);   // 0..63
        const int q    = tid & 7;
        const int i0   = q * 64;
        if (part < 2) {
            float s = 0.0f;
            #pragma unroll 8
            for (int i = i0; i < i0 + 64; ++i)
                s = fmaf(h[i], W_f1[i * HIDDEN + col], s);
            s += __shfl_xor_sync(0xffffffffu, s, 1);
            s += __shfl_xor_sync(0xffffffffu, s, 2);
            s += __shfl_xor_sync(0xffffffffu, s, 4);
            if (q == 0) g_base_f1[b * HIDDEN + col] = s + b_f1[col];
        } else {
            float s = 0.0f;
            #pragma unroll 8
            for (int i = i0; i < i0 + 64; ++i)
                s = fmaf(h[i], W_g1[i * HIDDEN + col], s);
            s += __shfl_xor_sync(0xffffffffu, s, 1);
            s += __shfl_xor_sync(0xffffffffu, s, 2);
            s += __shfl_xor_sync(0xffffffffu, s, 4);
            if (q == 0) g_base_g1[b * HIDDEN + col] = s + b_g1[col];
        }
    } else {
        // ---- mu/sigma: warp w = batch w ----
        const int w    = tid >> 5;             // 0..7
        const int lane = tid & 31;
        const float* h = h_t + w * DMODEL;
        float sm = 0.0f, ss = 0.0f;
        #pragma unroll 4
        for (int i = lane; i < DMODEL; i += 32) {
            float hv = h[i];
            sm = fmaf(hv, W_mu[i], sm);
            ss = fmaf(hv, W_sig[i], ss);
        }
        #pragma unroll
        for (int off = 16; off > 0; off >>= 1) {
            sm += __shfl_xor_sync(0xffffffffu, sm, off);
            ss += __shfl_xor_sync(0xffffffffu, ss, off);
        }
        if (lane == 0) {
            out_mu[w] = sm + b_mu[0];
            float v = ss + b_sig[0];
            out_sigma[w] = fmaxf(v, 0.0f) + log1pf(expf(-fabsf(v))) + 1e-6f;
        }
    }
}

// ---------------------------------------------------------------------------
// Table build kernel: 1024 blocks (one per (b, step)) x 96 threads.
// One eval per thread (96 grid points).
// ---------------------------------------------------------------------------
__global__ __launch_bounds__(96, 4)
void build_table_kernel(const float* __restrict__ W_f1,
                        const float* __restrict__ W_f2, const float* __restrict__ b_f2,
                        const float* __restrict__ W_f3, const float* __restrict__ b_f3,
                        const float* __restrict__ W_g1,
                        const float* __restrict__ W_g2, const float* __restrict__ b_g2)
{
    __shared__ __align__(16) float sWf2[HIDDEN * HIDDEN];   // 16 KB
    __shared__ __align__(16) float sbf2[HIDDEN];
    __shared__ __align__(16) float4 sP[HIDDEN];  // {tbase_f, wy_f, tbase_g, wy_g}
    __shared__ float sWf3[HIDDEN], sWg2[HIDDEN];

    const int tid  = threadIdx.x;           // 0..95
    const int b    = blockIdx.x >> 7;       // 0..7
    const int step = blockIdx.x & 127;      // 0..127
    const float t  = (float)step;

    for (int i = tid; i < HIDDEN * HIDDEN; i += 96) sWf2[i] = W_f2[i];
    if (tid < HIDDEN) {
        sbf2[tid] = b_f2[tid];
        sWf3[tid] = W_f3[tid];
        sWg2[tid] = W_g2[tid];
        sP[tid] = make_float4(
            fmaf(t, W_f1[513 * HIDDEN + tid], g_base_f1[b * HIDDEN + tid]),
            W_f1[512 * HIDDEN + tid],
            fmaf(t, W_g1[513 * HIDDEN + tid], g_base_g1[b * HIDDEN + tid]),
            W_g1[512 * HIDDEN + tid]);
    }
    __syncthreads();

    const float bf3v = b_f3[0];
    const float bg2v = b_g2[0];
    float2* slice = g_tab + (size_t)(b * HORIZON + step) * TAB_G;

    const float y = y_of_idx(tid);

    ull acc[HIDDEN / 2];
    #pragma unroll
    for (int m = 0; m < HIDDEN / 2; ++m)
        acc[m] = pack2(sbf2[2 * m], sbf2[2 * m + 1]);
    float ga0 = bg2v, ga1 = 0.0f;

    #pragma unroll 4
    for (int i = 0; i < HIDDEN; ++i) {
        const float4 p4 = sP[i];
        const float hf = silu_f(fmaf(y, p4.y, p4.x));
        const float hg = silu_f(fmaf(y, p4.w, p4.z));
        const float gw = sWg2[i];
        if ((i & 1) == 0) ga0 = fmaf(hg, gw, ga0);
        else              ga1 = fmaf(hg, gw, ga1);

        const ull a2 = pack_dup(hf);
        const ulonglong2* wr = reinterpret_cast<const ulonglong2*>(&sWf2[i * HIDDEN]);
        #pragma unroll
        for (int q = 0; q < HIDDEN / 4; ++q) {
            ulonglong2 w = wr[q];
            FMA2(acc[2 * q],     a2, w.x);
            FMA2(acc[2 * q + 1], a2, w.y);
        }
    }

    float f0 = bf3v, f1 = 0.0f;
    #pragma unroll
    for (int m = 0; m < HIDDEN / 2; ++m) {
        float2 h2 = unpack2(acc[m]);
        f0 = fmaf(silu_f(h2.x), sWf3[2 * m],     f0);
        f1 = fmaf(silu_f(h2.y), sWf3[2 * m + 1], f1);
    }
    slice[tid] = make_float2(f0 + f1, softplus_acc(ga0 + ga1) + 1e-6f);
}

// ---------------------------------------------------------------------------
// Exact fallback for y outside [-384, 384) (never expected to execute).
// ---------------------------------------------------------------------------
__device__ __noinline__ float2 exact_fg(float y, float t, int b,
                                        const float* W_f1,
                                        const float* W_f2, const float* b_f2,
                                        const float* W_f3, const float* b_f3,
                                        const float* W_g1,
                                        const float* W_g2, const float* b_g2)
{
    float acc[HIDDEN];
    for (int j = 0; j < HIDDEN; ++j) acc[j] = b_f2[j];
    float ga = b_g2[0];
    for (int i = 0; i < HIDDEN; ++i) {
        float xf = g_base_f1[b * HIDDEN + i]
                 + y * W_f1[512 * HIDDEN + i] + t * W_f1[513 * HIDDEN + i];
        float hf = silu_f(xf);
        float xg = g_base_g1[b * HIDDEN + i]
                 + y * W_g1[512 * HIDDEN + i] + t * W_g1[513 * HIDDEN + i];
        float hg = silu_f(xg);
        ga = fmaf(hg, W_g2[i], ga);
        for (int j = 0; j < HIDDEN; ++j)
            acc[j] = fmaf(hf, W_f2[i * HIDDEN + j], acc[j]);
    }
    float f = b_f3[0];
    for (int j = 0; j < HIDDEN; ++j) f = fmaf(silu_f(acc[j]), W_f3[j], f);
    float g = softplus_acc(ga) + 1e-6f;
    return make_float2(f, g);
}

// ---------------------------------------------------------------------------
// Path kernel: 256 blocks x 128 threads, 1 path per thread. Whole batch
// table (96 KB) staged via cp.async once; inline one-step-ahead threefry
// noise; barrier-free LDS cubic step loop.
// ---------------------------------------------------------------------------
extern __shared__ __align__(16) float2 stab[];   // HORIZON * TAB_G entries

__global__ __launch_bounds__(128)
void path_kernel(const float* __restrict__ initial_price,
                 float* __restrict__ out_paths,
                 const float* __restrict__ W_f1,
                 const float* __restrict__ W_f2, const float* __restrict__ b_f2,
                 const float* __restrict__ W_f3, const float* __restrict__ b_f3,
                 const float* __restrict__ W_g1,
                 const float* __restrict__ W_g2, const float* __restrict__ b_g2)
{
    __shared__ unsigned int skeys[2 * HORIZON];

    const int tid = threadIdx.x;                  // 0..127
    const int bid = blockIdx.x;                   // 0..255
    const int row = bid * 128 + tid;
    const int b   = row >> 12;                    // uniform per block

    // split keys: key[j] = threefry((0,42), (0,j)) — one per thread
    {
        unsigned int o0, o1;
        threefry2x32(0u, 42u, 0u, (unsigned int)tid, &o0, &o1);
        skeys[2 * tid]     = o0;
        skeys[2 * tid + 1] = o1;
    }

    // stage the whole batch table (96 KB) via cp.async
    {
        const char* src = (const char*)(g_tab + (size_t)b * HORIZON * TAB_G);
        const unsigned int dst = smem_u32(stab);
        #pragma unroll
        for (int k = 0; k < TAB_SMEM / (128 * 16); ++k) {   // 48 iters
            const int off = (k * 128 + tid) * 16;
            asm volatile("cp.async.cg.shared.global [%0], [%1], 16;"
                         :: "r"(dst + off), "l"(src + off));
        }
        asm volatile("cp.async.commit_group;");
    }

    float y = logf(initial_price[b]);
    float4* outp4 = reinterpret_cast<float4*>(out_paths + (size_t)row * HORIZON);
    const unsigned int cnt = (unsigned int)row;

    asm volatile("cp.async.wait_group 0;");
    __syncthreads();   // table + keys visible

    // inline noise: z(s) from skeys — independent of y
    #define ZGEN(s, zout) do {                                                \
        unsigned int _o0, _o1;                                                \
        threefry2x32(skeys[2 * (s)], skeys[2 * (s) + 1], 0u, cnt, &_o0, &_o1);\
        const unsigned int _bits = _o0 ^ _o1;                                 \
        const float _u01 = __uint_as_float((_bits >> 9) | 0x3f800000u) - 1.0f;\
        float _u = fmaf(_u01, 2.0f, -0.99999994039535522f);                   \
        _u = fmaxf(-0.99999994039535522f, _u);                                \
        (zout) = 1.4142135381698608f * erfinv_xla(_u);                        \
    } while (0)

    float z_next;
    ZGEN(0, z_next);

    #pragma unroll 1
    for (int g = 0; g < HORIZON / 4; ++g) {
        float o[4];
        #pragma unroll
        for (int k = 0; k < 4; ++k) {
            const int s = g * 4 + k;
            const float z = z_next;
            if (s + 1 < HORIZON) ZGEN(s + 1, z_next);  // overlaps lookup below

            const float2* cur = stab + s * TAB_G;
            float f, gg;
            float p = (y - YI_MIN) * YI_INV;
            int i1 = (int)floorf(p);
            int off; bool hit = true;
            if (i1 >= 1 && i1 <= GI - 3) { off = i1; }
            else {
                p = (y - YO_MIN) * YO_INV;
                i1 = (int)floorf(p);
                if (i1 >= 1 && i1 <= GO - 3) off = GI + i1;
                else hit = false;
            }
            if (hit) {
                const float uu = p - floorf(p);
                const float2 q0 = cur[off - 1];
                const float2 q1 = cur[off];
                const float2 q2 = cur[off + 1];
                const float2 q3 = cur[off + 2];
                const float u2 = uu * uu;
                const float u3 = u2 * uu;
                const float w0 = 0.5f * (-u3 + 2.0f * u2 - uu);
                const float w1 = 0.5f * (3.0f * u3 - 5.0f * u2 + 2.0f);
                const float w2 = 0.5f * (-3.0f * u3 + 4.0f * u2 + uu);
                const float w3 = 0.5f * (u3 - u2);
                f  = w0 * q0.x + w1 * q1.x + w2 * q2.x + w3 * q3.x;
                gg = w0 * q0.y + w1 * q1.y + w2 * q2.y + w3 * q3.y;
            } else {
                float2 fg = exact_fg(y, (float)s, b, W_f1, W_f2, b_f2,
                                     W_f3, b_f3, W_g1, W_g2, b_g2);
                f = fg.x; gg = fg.y;
            }

            // Euler-Maruyama (dt = 1, sqrt_dt = 1)
            y = (y + f) + gg * z;
            o[k] = __expf(fminf(fmaxf(y, -20.0f), 20.0f));
        }
        outp4[g] = make_float4(o[0], o[1], o[2], o[3]);
    }
    #undef ZGEN
}

// ---------------------------------------------------------------------------
// Launch (graph-capturable: kernels only, no allocs/syncs) — 3 launches.
// ---------------------------------------------------------------------------
extern "C" void kernel_launch(void* const* d_in, const int* in_sizes, int n_in,
                              void* d_out, int out_size)
{
    const float* h_t    = (const float*)d_in[0];
    const float* price  = (const float*)d_in[1];
    const float* W_f1   = (const float*)d_in[2];
    const float* b_f1   = (const float*)d_in[3];
    const float* W_f2   = (const float*)d_in[4];
    const float* b_f2   = (const float*)d_in[5];
    const float* W_f3   = (const float*)d_in[6];
    const float* b_f3   = (const float*)d_in[7];
    const float* W_g1   = (const float*)d_in[8];
    const float* b_g1   = (const float*)d_in[9];
    const float* W_g2   = (const float*)d_in[10];
    const float* b_g2   = (const float*)d_in[11];
    const float* W_mu   = (const float*)d_in[12];
    const float* b_mu   = (const float*)d_in[13];
    const float* W_sig  = (const float*)d_in[14];
    const float* b_sig  = (const float*)d_in[15];

    float* out        = (float*)d_out;
    float* out_paths  = out;
    float* out_mu     = out + PATHS_ELEMS;
    float* out_sigma  = out + PATHS_ELEMS + BATCH;

    // opt-in to 96 KB dynamic smem for the path kernel (idempotent)
    cudaFuncSetAttribute(path_kernel,
                         cudaFuncAttributeMaxDynamicSharedMemorySize, TAB_SMEM);

    setup_kernel<<<33, 256>>>(h_t, W_f1, b_f1, W_g1, b_g1,
                              W_mu, b_mu, W_sig, b_sig,
                              out_mu, out_sigma);
    build_table_kernel<<<BATCH * HORIZON, 96>>>(W_f1, W_f2, b_f2, W_f3, b_f3,
                                                W_g1, W_g2, b_g2);
    path_kernel<<<256, 128, TAB_SMEM>>>(price, out_paths, W_f1, W_f2, b_f2,
                                        W_f3, b_f3, W_g1, W_g2, b_g2);
}

// round 16
// speedup vs baseline: 15.5089x; 1.1176x over previous
#include <cuda_runtime.h>
#include <cstdint>

// ---------------------------------------------------------------------------
// NeuralSDEHead: batch=8, d_model=512, hidden=64, n_paths=4096, horizon=128
// out = [paths (8*4096*128), mu (8), sigma (8)]  all fp32
// PRNG: JAX threefry2x32, jax_threefry_partitionable=True semantics.
//
// Pipeline:
//  (1) setup_kernel: per-batch bases + mu/sigma (65 blocks)
//  (2) build_table_kernel: f/g over two-tier y-grid (64 pts per (b,step))
//  (3) path_kernel: whole batch table (64 KB) staged in smem once; inline
//      one-step-ahead threefry noise; barrier-free LDS cubic step loop.
// ---------------------------------------------------------------------------

#define BATCH    8
#define DMODEL   512
#define HIDDEN   64
#define NPATHS   4096
#define HORIZON  128
#define BN       (BATCH * NPATHS)      /* 32768 */
#define PATHS_ELEMS (BN * HORIZON)     /* 4194304 */

#define GI       32                     /* inner grid points (d=2)  */
#define GO       32                     /* outer grid points (d=24) */
#define TAB_G    (GI + GO)              /* 64 per (b,step) slice */
#define SLICE_B  (TAB_G * 8)            /* 512 bytes */
#define TAB_SMEM (HORIZON * SLICE_B)    /* 65536 bytes = 64 KB */
#define YI_MIN   (-32.0f)
#define YI_D     (2.0f)
#define YI_INV   (0.5f)
#define YO_MIN   (-384.0f)
#define YO_D     (24.0f)
#define YO_INV   (1.0f / 24.0f)

typedef unsigned long long ull;

// Scratch (allocation-free rule: __device__ globals)
__device__ float        g_base_f1[BATCH * HIDDEN];
__device__ float        g_base_g1[BATCH * HIDDEN];
__device__ __align__(16) float2 g_tab[BATCH * HORIZON * TAB_G];  // 512 KB

// ---------------------------------------------------------------------------
// Threefry-2x32 (JAX-compatible, 20 rounds)
// ---------------------------------------------------------------------------
__device__ __forceinline__ void threefry2x32(unsigned int k0, unsigned int k1,
                                             unsigned int x0, unsigned int x1,
                                             unsigned int* o0, unsigned int* o1)
{
    unsigned int ks0 = k0, ks1 = k1, ks2 = k0 ^ k1 ^ 0x1BD11BDAu;
    x0 += ks0; x1 += ks1;
#define TF_ROUND(r) { x0 += x1; x1 = __funnelshift_l(x1, x1, (r)); x1 ^= x0; }
    TF_ROUND(13) TF_ROUND(15) TF_ROUND(26) TF_ROUND(6)
    x0 += ks1; x1 += ks2 + 1u;
    TF_ROUND(17) TF_ROUND(29) TF_ROUND(16) TF_ROUND(24)
    x0 += ks2; x1 += ks0 + 2u;
    TF_ROUND(13) TF_ROUND(15) TF_ROUND(26) TF_ROUND(6)
    x0 += ks0; x1 += ks1 + 3u;
    TF_ROUND(17) TF_ROUND(29) TF_ROUND(16) TF_ROUND(24)
    x0 += ks1; x1 += ks2 + 4u;
    TF_ROUND(13) TF_ROUND(15) TF_ROUND(26) TF_ROUND(6)
    x0 += ks2; x1 += ks0 + 5u;
#undef TF_ROUND
    *o0 = x0; *o1 = x1;
}

// XLA ErfInv32 (Giles polynomial)
__device__ __forceinline__ float erfinv_xla(float x)
{
    float w = -log1pf(-x * x);
    float p;
    if (w < 5.0f) {
        w = w - 2.5f;
        p = 2.81022636e-08f;
        p = fmaf(p, w, 3.43273939e-07f);
        p = fmaf(p, w, -3.5233877e-06f);
        p = fmaf(p, w, -4.39150654e-06f);
        p = fmaf(p, w, 0.00021858087f);
        p = fmaf(p, w, -0.00125372503f);
        p = fmaf(p, w, -0.00417768164f);
        p = fmaf(p, w, 0.246640727f);
        p = fmaf(p, w, 1.50140941f);
    } else {
        w = sqrtf(w) - 3.0f;
        p = -0.000200214257f;
        p = fmaf(p, w, 0.000100950558f);
        p = fmaf(p, w, 0.00134934322f);
        p = fmaf(p, w, -0.00367342844f);
        p = fmaf(p, w, 0.00573950773f);
        p = fmaf(p, w, -0.0076224613f);
        p = fmaf(p, w, 0.00943887047f);
        p = fmaf(p, w, 1.00167406f);
        p = fmaf(p, w, 2.83297682f);
    }
    return p * x;
}

__device__ __forceinline__ float silu_f(float x)
{
    return __fdividef(x, 1.0f + __expf(-x));
}

__device__ __forceinline__ float softplus_acc(float x)
{
    return fmaxf(x, 0.0f) + log1pf(__expf(-fabsf(x)));
}

// packed f32x2 helpers -------------------------------------------------------
__device__ __forceinline__ ull pack_dup(float x)
{
    unsigned int b = __float_as_uint(x);
    ull r;
    asm("mov.b64 %0, {%1, %2};" : "=l"(r) : "r"(b), "r"(b));
    return r;
}
__device__ __forceinline__ ull pack2(float lo, float hi)
{
    unsigned int a = __float_as_uint(lo), b = __float_as_uint(hi);
    ull r;
    asm("mov.b64 %0, {%1, %2};" : "=l"(r) : "r"(a), "r"(b));
    return r;
}
__device__ __forceinline__ float2 unpack2(ull v)
{
    unsigned int lo, hi;
    asm("mov.b64 {%0, %1}, %2;" : "=r"(lo), "=r"(hi) : "l"(v));
    return make_float2(__uint_as_float(lo), __uint_as_float(hi));
}
#define FMA2(acc, a, b) asm("fma.rn.f32x2 %0, %1, %2, %0;" : "+l"(acc) : "l"(a), "l"(b))

__device__ __forceinline__ unsigned int smem_u32(const void* p)
{
    unsigned int a;
    asm("{ .reg .u64 t; cvta.to.shared.u64 t, %1; cvt.u32.u64 %0, t; }"
        : "=r"(a) : "l"(p));
    return a;
}

// grid point for table index 0..63: inner 0..31, outer 32..63
__device__ __forceinline__ float y_of_idx(int idx)
{
    return (idx < GI) ? (YI_MIN + (float)idx * YI_D)
                      : (YO_MIN + (float)(idx - GI) * YO_D);
}

// ---------------------------------------------------------------------------
// Setup kernel: 65 blocks x 256 threads.
//  blocks [0, 64): per-batch bases (16 threads per column, 16 cols/block)
//  block 64: mu/sigma (warp w = batch w)
// ---------------------------------------------------------------------------
__global__ __launch_bounds__(256)
void setup_kernel(const float* __restrict__ h_t,
                  const float* __restrict__ W_f1, const float* __restrict__ b_f1,
                  const float* __restrict__ W_g1, const float* __restrict__ b_g1,
                  const float* __restrict__ W_mu, const float* __restrict__ b_mu,
                  const float* __restrict__ W_sig, const float* __restrict__ b_sig,
                  float* __restrict__ out_mu, float* __restrict__ out_sigma)
{
    const int n   = blockIdx.x;
    const int tid = threadIdx.x;

    if (n < 64) {
        // ---- bases: 16 threads/column, 16 columns per block ----
        const int b    = n >> 3;               // batch (8 blocks per batch)
        const int part = n & 7;                // 0-3: f cols; 4-7: g cols
        const float* h = h_t + b * DMODEL;
        const int col  = ((part & 3) * 16) + (tid >> 4);   // 0..63
        const int q    = tid & 15;
        const int i0   = q * 32;
        if (part < 4) {
            float s = 0.0f;
            #pragma unroll 8
            for (int i = i0; i < i0 + 32; ++i)
                s = fmaf(h[i], W_f1[i * HIDDEN + col], s);
            s += __shfl_xor_sync(0xffffffffu, s, 1);
            s += __shfl_xor_sync(0xffffffffu, s, 2);
            s += __shfl_xor_sync(0xffffffffu, s, 4);
            s += __shfl_xor_sync(0xffffffffu, s, 8);
            if (q == 0) g_base_f1[b * HIDDEN + col] = s + b_f1[col];
        } else {
            float s = 0.0f;
            #pragma unroll 8
            for (int i = i0; i < i0 + 32; ++i)
                s = fmaf(h[i], W_g1[i * HIDDEN + col], s);
            s += __shfl_xor_sync(0xffffffffu, s, 1);
            s += __shfl_xor_sync(0xffffffffu, s, 2);
            s += __shfl_xor_sync(0xffffffffu, s, 4);
            s += __shfl_xor_sync(0xffffffffu, s, 8);
            if (q == 0) g_base_g1[b * HIDDEN + col] = s + b_g1[col];
        }
    } else {
        // ---- mu/sigma: warp w = batch w ----
        const int w    = tid >> 5;             // 0..7
        const int lane = tid & 31;
        const float* h = h_t + w * DMODEL;
        float sm = 0.0f, ss = 0.0f;
        #pragma unroll 4
        for (int i = lane; i < DMODEL; i += 32) {
            float hv = h[i];
            sm = fmaf(hv, W_mu[i], sm);
            ss = fmaf(hv, W_sig[i], ss);
        }
        #pragma unroll
        for (int off = 16; off > 0; off >>= 1) {
            sm += __shfl_xor_sync(0xffffffffu, sm, off);
            ss += __shfl_xor_sync(0xffffffffu, ss, off);
        }
        if (lane == 0) {
            out_mu[w] = sm + b_mu[0];
            float v = ss + b_sig[0];
            out_sigma[w] = fmaxf(v, 0.0f) + log1pf(expf(-fabsf(v))) + 1e-6f;
        }
    }
}

// ---------------------------------------------------------------------------
// Table build kernel: 1024 blocks (one per (b, step)) x 64 threads.
// One eval per thread (64 grid points). occ 8 -> single wave chip-wide.
// ---------------------------------------------------------------------------
__global__ __launch_bounds__(64, 8)
void build_table_kernel(const float* __restrict__ W_f1,
                        const float* __restrict__ W_f2, const float* __restrict__ b_f2,
                        const float* __restrict__ W_f3, const float* __restrict__ b_f3,
                        const float* __restrict__ W_g1,
                        const float* __restrict__ W_g2, const float* __restrict__ b_g2)
{
    __shared__ __align__(16) float sWf2[HIDDEN * HIDDEN];   // 16 KB
    __shared__ __align__(16) float sbf2[HIDDEN];
    __shared__ __align__(16) float4 sP[HIDDEN];  // {tbase_f, wy_f, tbase_g, wy_g}
    __shared__ float sWf3[HIDDEN], sWg2[HIDDEN];

    const int tid  = threadIdx.x;           // 0..63
    const int b    = blockIdx.x >> 7;       // 0..7
    const int step = blockIdx.x & 127;      // 0..127
    const float t  = (float)step;

    for (int i = tid; i < HIDDEN * HIDDEN; i += 64) sWf2[i] = W_f2[i];
    {
        sbf2[tid] = b_f2[tid];
        sWf3[tid] = W_f3[tid];
        sWg2[tid] = W_g2[tid];
        sP[tid] = make_float4(
            fmaf(t, W_f1[513 * HIDDEN + tid], g_base_f1[b * HIDDEN + tid]),
            W_f1[512 * HIDDEN + tid],
            fmaf(t, W_g1[513 * HIDDEN + tid], g_base_g1[b * HIDDEN + tid]),
            W_g1[512 * HIDDEN + tid]);
    }
    __syncthreads();

    const float bf3v = b_f3[0];
    const float bg2v = b_g2[0];
    float2* slice = g_tab + (size_t)(b * HORIZON + step) * TAB_G;

    const float y = y_of_idx(tid);

    ull acc[HIDDEN / 2];
    #pragma unroll
    for (int m = 0; m < HIDDEN / 2; ++m)
        acc[m] = pack2(sbf2[2 * m], sbf2[2 * m + 1]);
    float ga0 = bg2v, ga1 = 0.0f;

    #pragma unroll 4
    for (int i = 0; i < HIDDEN; ++i) {
        const float4 p4 = sP[i];
        const float hf = silu_f(fmaf(y, p4.y, p4.x));
        const float hg = silu_f(fmaf(y, p4.w, p4.z));
        const float gw = sWg2[i];
        if ((i & 1) == 0) ga0 = fmaf(hg, gw, ga0);
        else              ga1 = fmaf(hg, gw, ga1);

        const ull a2 = pack_dup(hf);
        const ulonglong2* wr = reinterpret_cast<const ulonglong2*>(&sWf2[i * HIDDEN]);
        #pragma unroll
        for (int q = 0; q < HIDDEN / 4; ++q) {
            ulonglong2 w = wr[q];
            FMA2(acc[2 * q],     a2, w.x);
            FMA2(acc[2 * q + 1], a2, w.y);
        }
    }

    float f0 = bf3v, f1 = 0.0f;
    #pragma unroll
    for (int m = 0; m < HIDDEN / 2; ++m) {
        float2 h2 = unpack2(acc[m]);
        f0 = fmaf(silu_f(h2.x), sWf3[2 * m],     f0);
        f1 = fmaf(silu_f(h2.y), sWf3[2 * m + 1], f1);
    }
    slice[tid] = make_float2(f0 + f1, softplus_acc(ga0 + ga1) + 1e-6f);
}

// ---------------------------------------------------------------------------
// Exact fallback for y outside the outer tier (never expected to execute).
// ---------------------------------------------------------------------------
__device__ __noinline__ float2 exact_fg(float y, float t, int b,
                                        const float* W_f1,
                                        const float* W_f2, const float* b_f2,
                                        const float* W_f3, const float* b_f3,
                                        const float* W_g1,
                                        const float* W_g2, const float* b_g2)
{
    float acc[HIDDEN];
    for (int j = 0; j < HIDDEN; ++j) acc[j] = b_f2[j];
    float ga = b_g2[0];
    for (int i = 0; i < HIDDEN; ++i) {
        float xf = g_base_f1[b * HIDDEN + i]
                 + y * W_f1[512 * HIDDEN + i] + t * W_f1[513 * HIDDEN + i];
        float hf = silu_f(xf);
        float xg = g_base_g1[b * HIDDEN + i]
                 + y * W_g1[512 * HIDDEN + i] + t * W_g1[513 * HIDDEN + i];
        float hg = silu_f(xg);
        ga = fmaf(hg, W_g2[i], ga);
        for (int j = 0; j < HIDDEN; ++j)
            acc[j] = fmaf(hf, W_f2[i * HIDDEN + j], acc[j]);
    }
    float f = b_f3[0];
    for (int j = 0; j < HIDDEN; ++j) f = fmaf(silu_f(acc[j]), W_f3[j], f);
    float g = softplus_acc(ga) + 1e-6f;
    return make_float2(f, g);
}

// ---------------------------------------------------------------------------
// Path kernel: 256 blocks x 128 threads, 1 path per thread. Whole batch
// table (64 KB) staged via cp.async once -> 2+ blocks/SM, single wave.
// Inline one-step-ahead threefry noise; barrier-free LDS cubic step loop.
// ---------------------------------------------------------------------------
extern __shared__ __align__(16) float2 stab[];   // HORIZON * TAB_G entries

__global__ __launch_bounds__(128)
void path_kernel(const float* __restrict__ initial_price,
                 float* __restrict__ out_paths,
                 const float* __restrict__ W_f1,
                 const float* __restrict__ W_f2, const float* __restrict__ b_f2,
                 const float* __restrict__ W_f3, const float* __restrict__ b_f3,
                 const float* __restrict__ W_g1,
                 const float* __restrict__ W_g2, const float* __restrict__ b_g2)
{
    __shared__ unsigned int skeys[2 * HORIZON];

    const int tid = threadIdx.x;                  // 0..127
    const int bid = blockIdx.x;                   // 0..255
    const int row = bid * 128 + tid;
    const int b   = row >> 12;                    // uniform per block

    // split keys: key[j] = threefry((0,42), (0,j)) — one per thread
    {
        unsigned int o0, o1;
        threefry2x32(0u, 42u, 0u, (unsigned int)tid, &o0, &o1);
        skeys[2 * tid]     = o0;
        skeys[2 * tid + 1] = o1;
    }

    // stage the whole batch table (64 KB) via cp.async
    {
        const char* src = (const char*)(g_tab + (size_t)b * HORIZON * TAB_G);
        const unsigned int dst = smem_u32(stab);
        #pragma unroll
        for (int k = 0; k < TAB_SMEM / (128 * 16); ++k) {   // 32 iters
            const int off = (k * 128 + tid) * 16;
            asm volatile("cp.async.cg.shared.global [%0], [%1], 16;"
                         :: "r"(dst + off), "l"(src + off));
        }
        asm volatile("cp.async.commit_group;");
    }

    float y = logf(initial_price[b]);
    float4* outp4 = reinterpret_cast<float4*>(out_paths + (size_t)row * HORIZON);
    const unsigned int cnt = (unsigned int)row;

    asm volatile("cp.async.wait_group 0;");
    __syncthreads();   // table + keys visible

    // inline noise: z(s) from skeys — independent of y
    #define ZGEN(s, zout) do {                                                \
        unsigned int _o0, _o1;                                                \
        threefry2x32(skeys[2 * (s)], skeys[2 * (s) + 1], 0u, cnt, &_o0, &_o1);\
        const unsigned int _bits = _o0 ^ _o1;                                 \
        const float _u01 = __uint_as_float((_bits >> 9) | 0x3f800000u) - 1.0f;\
        float _u = fmaf(_u01, 2.0f, -0.99999994039535522f);                   \
        _u = fmaxf(-0.99999994039535522f, _u);                                \
        (zout) = 1.4142135381698608f * erfinv_xla(_u);                        \
    } while (0)

    float z_next;
    ZGEN(0, z_next);

    #pragma unroll 1
    for (int g = 0; g < HORIZON / 4; ++g) {
        float o[4];
        #pragma unroll
        for (int k = 0; k < 4; ++k) {
            const int s = g * 4 + k;
            const float z = z_next;
            if (s + 1 < HORIZON) ZGEN(s + 1, z_next);  // overlaps lookup below

            const float2* cur = stab + s * TAB_G;
            float f, gg;
            float p = (y - YI_MIN) * YI_INV;
            int i1 = (int)floorf(p);
            int off; bool hit = true;
            if (i1 >= 1 && i1 <= GI - 3) { off = i1; }
            else {
                p = (y - YO_MIN) * YO_INV;
                i1 = (int)floorf(p);
                if (i1 >= 1 && i1 <= GO - 3) off = GI + i1;
                else hit = false;
            }
            if (hit) {
                const float uu = p - floorf(p);
                const float2 q0 = cur[off - 1];
                const float2 q1 = cur[off];
                const float2 q2 = cur[off + 1];
                const float2 q3 = cur[off + 2];
                const float u2 = uu * uu;
                const float u3 = u2 * uu;
                const float w0 = 0.5f * (-u3 + 2.0f * u2 - uu);
                const float w1 = 0.5f * (3.0f * u3 - 5.0f * u2 + 2.0f);
                const float w2 = 0.5f * (-3.0f * u3 + 4.0f * u2 + uu);
                const float w3 = 0.5f * (u3 - u2);
                f  = w0 * q0.x + w1 * q1.x + w2 * q2.x + w3 * q3.x;
                gg = w0 * q0.y + w1 * q1.y + w2 * q2.y + w3 * q3.y;
            } else {
                float2 fg = exact_fg(y, (float)s, b, W_f1, W_f2, b_f2,
                                     W_f3, b_f3, W_g1, W_g2, b_g2);
                f = fg.x; gg = fg.y;
            }

            // Euler-Maruyama (dt = 1, sqrt_dt = 1)
            y = (y + f) + gg * z;
            o[k] = __expf(fminf(fmaxf(y, -20.0f), 20.0f));
        }
        outp4[g] = make_float4(o[0], o[1], o[2], o[3]);
    }
    #undef ZGEN
}

// ---------------------------------------------------------------------------
// Launch (graph-capturable: kernels only, no allocs/syncs) — 3 launches.
// ---------------------------------------------------------------------------
extern "C" void kernel_launch(void* const* d_in, const int* in_sizes, int n_in,
                              void* d_out, int out_size)
{
    const float* h_t    = (const float*)d_in[0];
    const float* price  = (const float*)d_in[1];
    const float* W_f1   = (const float*)d_in[2];
    const float* b_f1   = (const float*)d_in[3];
    const float* W_f2   = (const float*)d_in[4];
    const float* b_f2   = (const float*)d_in[5];
    const float* W_f3   = (const float*)d_in[6];
    const float* b_f3   = (const float*)d_in[7];
    const float* W_g1   = (const float*)d_in[8];
    const float* b_g1   = (const float*)d_in[9];
    const float* W_g2   = (const float*)d_in[10];
    const float* b_g2   = (const float*)d_in[11];
    const float* W_mu   = (const float*)d_in[12];
    const float* b_mu   = (const float*)d_in[13];
    const float* W_sig  = (const float*)d_in[14];
    const float* b_sig  = (const float*)d_in[15];

    float* out        = (float*)d_out;
    float* out_paths  = out;
    float* out_mu     = out + PATHS_ELEMS;
    float* out_sigma  = out + PATHS_ELEMS + BATCH;

    // opt-in to 64 KB dynamic smem for the path kernel (idempotent)
    cudaFuncSetAttribute(path_kernel,
                         cudaFuncAttributeMaxDynamicSharedMemorySize, TAB_SMEM);

    setup_kernel<<<65, 256>>>(h_t, W_f1, b_f1, W_g1, b_g1,
                              W_mu, b_mu, W_sig, b_sig,
                              out_mu, out_sigma);
    build_table_kernel<<<BATCH * HORIZON, 64>>>(W_f1, W_f2, b_f2, W_f3, b_f3,
                                                W_g1, W_g2, b_g2);
    path_kernel<<<256, 128, TAB_SMEM>>>(price, out_paths, W_f1, W_f2, b_f2,
                                        W_f3, b_f3, W_g1, W_g2, b_g2);
}